// round 9
// baseline (speedup 1.0000x reference)
#include <cuda_runtime.h>
#include <cuda_bf16.h>
#include <cstdint>

// ---------------------------------------------------------------------------
// SiameseBrainNet: persistent mega-kernel + mma.sync split-bf16 GEMM
// R9: 512 threads (16 warps) — 32x32 warp tiles, 4 warps/SMSP for latency
//     hiding; agg 4 nodes/block; pool/dist/scan widened.
// ---------------------------------------------------------------------------

#define NN 20000
#define EE 640000
#define DH 512
#define GG 64
#define NB 148
#define TPB 512
#define MT 157
#define NTILE (4 * MT)        // 628 output tiles (128x128)

#define KSTR 72               // bf16 elements per smem row (64 data + 8 pad)
#define TILE_BYTES (128 * KSTR * 2)          // 18432
#define BUF_BYTES  (4 * TILE_BYTES)          // 73728 (Ahi,Alo,Bhi,Blo)
#define SM_RED     (2 * BUF_BYTES)           // 147456
#define SMEM_BYTES (SM_RED + 2048)           // 149504

// ---- scratch ---------------------------------------------------------------
__device__ float g_gemm[NN * DH];
__device__ float g_x[NN * DH];
__device__ __nv_bfloat16 g_ahi[NN * DH];
__device__ __nv_bfloat16 g_alo[NN * DH];
__device__ __nv_bfloat16 g_wthi[3 * DH * DH];   // W^T split, [l][n][k]
__device__ __nv_bfloat16 g_wtlo[3 * DH * DH];
__device__ int   g_deg[NN];        // INVARIANT: zero at kernel entry
__device__ int   g_rowptr[NN + 1];
__device__ int   g_cursor[NN];
__device__ float g_dinv[NN];
__device__ int   g_csr_src[EE];
__device__ float g_csr_norm[EE];
__device__ float g_pooled[2][GG * DH];
__device__ unsigned g_count, g_gen;

// ---- grid barrier -----------------------------------------------------------
__device__ __forceinline__ void gsync(unsigned target) {
    __syncthreads();
    if (threadIdx.x == 0) {
        __threadfence();
        if (atomicAdd(&g_count, 1u) == NB - 1u) {
            atomicExch(&g_count, 0u);
            __threadfence();
            atomicAdd(&g_gen, 1u);
        } else {
            while (*((volatile unsigned*)&g_gen) < target) __nanosleep(64);
        }
        __threadfence();
    }
    __syncthreads();
}

// ---- tensor-core primitives ---------------------------------------------------
__device__ __forceinline__ void mma16816(float* d,
                                         uint32_t a0, uint32_t a1, uint32_t a2, uint32_t a3,
                                         uint32_t b0, uint32_t b1) {
    asm volatile(
        "mma.sync.aligned.m16n8k16.row.col.f32.bf16.bf16.f32 "
        "{%0,%1,%2,%3}, {%4,%5,%6,%7}, {%8,%9}, {%0,%1,%2,%3};"
        : "+f"(d[0]), "+f"(d[1]), "+f"(d[2]), "+f"(d[3])
        : "r"(a0), "r"(a1), "r"(a2), "r"(a3), "r"(b0), "r"(b1));
}
__device__ __forceinline__ void ldsm4(uint32_t& r0, uint32_t& r1, uint32_t& r2, uint32_t& r3,
                                      uint32_t addr) {
    asm volatile("ldmatrix.sync.aligned.m8n8.x4.shared.b16 {%0,%1,%2,%3}, [%4];"
                 : "=r"(r0), "=r"(r1), "=r"(r2), "=r"(r3) : "r"(addr));
}
#define CP_COMMIT() asm volatile("cp.async.commit_group;" ::: "memory")
#define CP_WAIT(n)  asm volatile("cp.async.wait_group %0;" :: "n"(n) : "memory")

// async fill: gmem bf16 [.,512] -> smem tile 128x64 (stride KSTR)
__device__ __forceinline__ void fill_tile_async(uint32_t smt,
                                                const __nv_bfloat16* __restrict__ g,
                                                int row0, int kc, int nrows) {
    const int tid = threadIdx.x;
#pragma unroll
    for (int i = 0; i < 2; i++) {
        int idx = i * TPB + tid;       // 0..1023
        int r   = idx >> 3;            // 0..127
        int c8  = (idx & 7) << 3;      // 0..56
        int gr  = row0 + r;
        bool valid = (gr < nrows);
        const void* src = g + (size_t)(valid ? gr : 0) * DH + kc + c8;
        uint32_t dst = smt + (uint32_t)(r * KSTR + c8) * 2;
        int sz = valid ? 16 : 0;
        asm volatile("cp.async.cg.shared.global [%0], [%1], 16, %2;"
                     :: "r"(dst), "l"(src), "r"(sz) : "memory");
    }
}

// ---- GEMM phase: C[NN,512] = A @ W, split-bf16 x3, fp32 accum ----------------
// 16 warps: warp tile 32x32; wm = warp&3 (row group), wn = warp>>2 (col group)
__device__ void gemm_phase(uint32_t smb,
                           const __nv_bfloat16* __restrict__ Whi,
                           const __nv_bfloat16* __restrict__ Wlo,
                           float* __restrict__ C) {
    const int tid  = threadIdx.x;
    const int lane = tid & 31, warp = tid >> 5;
    const int wm = warp & 3;        // 0..3 : 32-row group
    const int wn = warp >> 2;       // 0..3 : 32-col group
    const int g  = lane >> 2;       // epilogue row-in-8
    const int tg = lane & 3;        // epilogue col pair
    const int seg = lane >> 3;      // ldmatrix segment 0..3
    const int lr  = lane & 7;

    // ldmatrix element offsets (elements)
    const int aoff0 = (wm * 32 + 0  + (seg & 1) * 8 + lr) * KSTR + (seg >> 1) * 8;
    const int aoff1 = (wm * 32 + 16 + (seg & 1) * 8 + lr) * KSTR + (seg >> 1) * 8;
    const int boff0 = (wn * 32 + 0  + (seg & 1) * 8 + lr) * KSTR + (seg >> 1) * 8;
    const int boff1 = (wn * 32 + 16 + (seg & 1) * 8 + lr) * KSTR + (seg >> 1) * 8;

    for (int t = blockIdx.x; t < NTILE; t += NB) {
        const int bm = t >> 2, bn = t & 3;

        float acc[2][4][4];
#pragma unroll
        for (int mt = 0; mt < 2; mt++)
#pragma unroll
            for (int nt = 0; nt < 4; nt++)
#pragma unroll
                for (int q = 0; q < 4; q++) acc[mt][nt][q] = 0.0f;

        // prologue: fill k-chunk 0 into buffer 0
        fill_tile_async(smb + 0 * TILE_BYTES, g_ahi, bm * 128, 0, NN);
        fill_tile_async(smb + 1 * TILE_BYTES, g_alo, bm * 128, 0, NN);
        fill_tile_async(smb + 2 * TILE_BYTES, Whi,   bn * 128, 0, 1 << 30);
        fill_tile_async(smb + 3 * TILE_BYTES, Wlo,   bn * 128, 0, 1 << 30);
        CP_COMMIT();

#pragma unroll 1
        for (int kc8 = 0; kc8 < 8; kc8++) {
            const uint32_t cur = smb + (uint32_t)(kc8 & 1) * BUF_BYTES;
            if (kc8 + 1 < 8) {
                const uint32_t nxt = smb + (uint32_t)((kc8 + 1) & 1) * BUF_BYTES;
                fill_tile_async(nxt + 0 * TILE_BYTES, g_ahi, bm * 128, (kc8 + 1) * 64, NN);
                fill_tile_async(nxt + 1 * TILE_BYTES, g_alo, bm * 128, (kc8 + 1) * 64, NN);
                fill_tile_async(nxt + 2 * TILE_BYTES, Whi,   bn * 128, (kc8 + 1) * 64, 1 << 30);
                fill_tile_async(nxt + 3 * TILE_BYTES, Wlo,   bn * 128, (kc8 + 1) * 64, 1 << 30);
                CP_COMMIT();
                CP_WAIT(1);
            } else {
                CP_WAIT(0);
            }
            __syncthreads();

            const uint32_t Ahi = cur + 0 * TILE_BYTES;
            const uint32_t Alo = cur + 1 * TILE_BYTES;
            const uint32_t Bhi = cur + 2 * TILE_BYTES;
            const uint32_t Blo = cur + 3 * TILE_BYTES;

#pragma unroll
            for (int ks4 = 0; ks4 < 4; ks4++) {
                const uint32_t kb = (uint32_t)(ks4 * 16) * 2;   // bytes

                // B fragments: 2 ldsm4 per precision (n 0..31)
                uint32_t bh[4][2], bl[4][2];
                {
                    uint32_t r0, r1, r2, r3;
                    ldsm4(r0, r1, r2, r3, Bhi + (uint32_t)boff0 * 2 + kb);
                    bh[0][0] = r0; bh[1][0] = r1; bh[0][1] = r2; bh[1][1] = r3;
                    ldsm4(r0, r1, r2, r3, Bhi + (uint32_t)boff1 * 2 + kb);
                    bh[2][0] = r0; bh[3][0] = r1; bh[2][1] = r2; bh[3][1] = r3;
                    ldsm4(r0, r1, r2, r3, Blo + (uint32_t)boff0 * 2 + kb);
                    bl[0][0] = r0; bl[1][0] = r1; bl[0][1] = r2; bl[1][1] = r3;
                    ldsm4(r0, r1, r2, r3, Blo + (uint32_t)boff1 * 2 + kb);
                    bl[2][0] = r0; bl[3][0] = r1; bl[2][1] = r2; bl[3][1] = r3;
                }
#pragma unroll
                for (int mt = 0; mt < 2; mt++) {
                    const int aoff = mt ? aoff1 : aoff0;
                    uint32_t ah0, ah1, ah2, ah3, al0, al1, al2, al3;
                    ldsm4(ah0, ah1, ah2, ah3, Ahi + (uint32_t)aoff * 2 + kb);
                    ldsm4(al0, al1, al2, al3, Alo + (uint32_t)aoff * 2 + kb);
#pragma unroll
                    for (int nt = 0; nt < 4; nt++) {
                        mma16816(acc[mt][nt], ah0, ah1, ah2, ah3, bh[nt][0], bh[nt][1]);
                        mma16816(acc[mt][nt], al0, al1, al2, al3, bh[nt][0], bh[nt][1]);
                        mma16816(acc[mt][nt], ah0, ah1, ah2, ah3, bl[nt][0], bl[nt][1]);
                    }
                }
            }
            __syncthreads();
        }

        // epilogue: D(16x8) frag -> c0,c1 at (g, 2tg), c2,c3 at (g+8, 2tg)
#pragma unroll
        for (int mt = 0; mt < 2; mt++) {
            int row0 = bm * 128 + wm * 32 + mt * 16 + g;
#pragma unroll
            for (int nt = 0; nt < 4; nt++) {
                int col = bn * 128 + wn * 32 + nt * 8 + 2 * tg;
                if (row0 < NN)
                    *(float2*)&C[(size_t)row0 * DH + col] =
                        make_float2(acc[mt][nt][0], acc[mt][nt][1]);
                if (row0 + 8 < NN)
                    *(float2*)&C[(size_t)(row0 + 8) * DH + col] =
                        make_float2(acc[mt][nt][2], acc[mt][nt][3]);
            }
        }
        __syncthreads();
    }
}

// ---- aggregation (fused bf16 split for layers 0,1); 4 nodes per block -------
__device__ __forceinline__ void bf_split(float v, __nv_bfloat16& h, __nv_bfloat16& l) {
    h = __float2bfloat16(v);
    l = __float2bfloat16(v - __bfloat162float(h));
}

__device__ void agg_phase(const float* __restrict__ h, const float* __restrict__ bias, int l) {
    const int sub = threadIdx.x >> 7;   // 0..3
    const int t   = threadIdx.x & 127;  // float4 lane
    const float4 b4 = *(const float4*)&bias[t * 4];

    for (int i = blockIdx.x * 4 + sub; i < NN; i += NB * 4) {
        int r0 = g_rowptr[i];
        int r1 = g_rowptr[i + 1];

        float4 a0 = make_float4(0.f, 0.f, 0.f, 0.f);
        float4 a1 = a0, a2 = a0, a3 = a0;

        int e = r0;
        for (; e + 7 < r1; e += 8) {
            int   s0 = g_csr_src[e],     s1 = g_csr_src[e + 1];
            int   s2 = g_csr_src[e + 2], s3 = g_csr_src[e + 3];
            int   s4 = g_csr_src[e + 4], s5 = g_csr_src[e + 5];
            int   s6 = g_csr_src[e + 6], s7 = g_csr_src[e + 7];
            float w0 = g_csr_norm[e],     w1 = g_csr_norm[e + 1];
            float w2 = g_csr_norm[e + 2], w3 = g_csr_norm[e + 3];
            float w4 = g_csr_norm[e + 4], w5 = g_csr_norm[e + 5];
            float w6 = g_csr_norm[e + 6], w7 = g_csr_norm[e + 7];
            float4 v0 = *(const float4*)&h[(size_t)s0 * DH + t * 4];
            float4 v1 = *(const float4*)&h[(size_t)s1 * DH + t * 4];
            float4 v2 = *(const float4*)&h[(size_t)s2 * DH + t * 4];
            float4 v3 = *(const float4*)&h[(size_t)s3 * DH + t * 4];
            float4 v4 = *(const float4*)&h[(size_t)s4 * DH + t * 4];
            float4 v5 = *(const float4*)&h[(size_t)s5 * DH + t * 4];
            float4 v6 = *(const float4*)&h[(size_t)s6 * DH + t * 4];
            float4 v7 = *(const float4*)&h[(size_t)s7 * DH + t * 4];
            a0.x += w0 * v0.x; a0.y += w0 * v0.y; a0.z += w0 * v0.z; a0.w += w0 * v0.w;
            a1.x += w1 * v1.x; a1.y += w1 * v1.y; a1.z += w1 * v1.z; a1.w += w1 * v1.w;
            a2.x += w2 * v2.x; a2.y += w2 * v2.y; a2.z += w2 * v2.z; a2.w += w2 * v2.w;
            a3.x += w3 * v3.x; a3.y += w3 * v3.y; a3.z += w3 * v3.z; a3.w += w3 * v3.w;
            a0.x += w4 * v4.x; a0.y += w4 * v4.y; a0.z += w4 * v4.z; a0.w += w4 * v4.w;
            a1.x += w5 * v5.x; a1.y += w5 * v5.y; a1.z += w5 * v5.z; a1.w += w5 * v5.w;
            a2.x += w6 * v6.x; a2.y += w6 * v6.y; a2.z += w6 * v6.z; a2.w += w6 * v6.w;
            a3.x += w7 * v7.x; a3.y += w7 * v7.y; a3.z += w7 * v7.z; a3.w += w7 * v7.w;
        }
        for (; e < r1; e++) {
            int   s = g_csr_src[e];
            float w = g_csr_norm[e];
            float4 v = *(const float4*)&h[(size_t)s * DH + t * 4];
            a0.x += w * v.x; a0.y += w * v.y; a0.z += w * v.z; a0.w += w * v.w;
        }

        float4 acc;
        acc.x = (a0.x + a1.x) + (a2.x + a3.x);
        acc.y = (a0.y + a1.y) + (a2.y + a3.y);
        acc.z = (a0.z + a1.z) + (a2.z + a3.z);
        acc.w = (a0.w + a1.w) + (a2.w + a3.w);

        float d = g_dinv[i];
        float wd = d * d;
        float4 vs = *(const float4*)&h[(size_t)i * DH + t * 4];
        acc.x += wd * vs.x + b4.x;
        acc.y += wd * vs.y + b4.y;
        acc.z += wd * vs.z + b4.z;
        acc.w += wd * vs.w + b4.w;

        if (l < 2) {
            acc.x = fmaxf(acc.x, 0.f); acc.y = fmaxf(acc.y, 0.f);
            acc.z = fmaxf(acc.z, 0.f); acc.w = fmaxf(acc.w, 0.f);
            __nv_bfloat162 h01, h23, l01, l23;
            bf_split(acc.x, h01.x, l01.x); bf_split(acc.y, h01.y, l01.y);
            bf_split(acc.z, h23.x, l23.x); bf_split(acc.w, h23.y, l23.y);
            __nv_bfloat162* hp = (__nv_bfloat162*)(g_ahi + (size_t)i * DH + t * 4);
            __nv_bfloat162* lp = (__nv_bfloat162*)(g_alo + (size_t)i * DH + t * 4);
            hp[0] = h01; hp[1] = h23;
            lp[0] = l01; lp[1] = l23;
        } else {
            *(float4*)&g_x[(size_t)i * DH + t * 4] = acc;
        }
    }
}

// ---- pool / dist (512 threads, 1 float lane each) ----------------------------
__device__ void pool_phase(const float* __restrict__ h, const int* __restrict__ batch, int enc) {
    int g = blockIdx.x;
    if (g >= GG) return;
    int t = threadIdx.x;   // 0..511, one dim each

    int lo = 0, hi = NN;
    while (lo < hi) { int m = (lo + hi) >> 1; if (batch[m] < g) lo = m + 1; else hi = m; }
    int start = lo;
    lo = start; hi = NN;
    while (lo < hi) { int m = (lo + hi) >> 1; if (batch[m] < g + 1) lo = m + 1; else hi = m; }
    int end = lo;

    float a0 = 0.f, a1 = 0.f;
    int r = start;
    for (; r + 1 < end; r += 2) {
        a0 += h[(size_t)r * DH + t];
        a1 += h[(size_t)(r + 1) * DH + t];
    }
    if (r < end) a0 += h[(size_t)r * DH + t];
    float inv = 1.0f / fmaxf((float)(end - start), 1.0f);
    g_pooled[enc][g * DH + t] = (a0 + a1) * inv;
}

__device__ void dist_phase(float* __restrict__ out, float* sred) {
    int g = blockIdx.x;
    if (g >= GG) return;
    int t = threadIdx.x;

    float d = g_pooled[0][g * DH + t] - g_pooled[1][g * DH + t] + 1e-6f;
    sred[t] = d * d;
    __syncthreads();
    for (int off = 256; off > 0; off >>= 1) {
        if (t < off) sred[t] += sred[t + off];
        __syncthreads();
    }
    if (t == 0) out[g] = sqrtf(sred[0]);
}

// ---- mega kernel --------------------------------------------------------------
extern __shared__ __align__(16) unsigned char smem_dyn[];

__global__ __launch_bounds__(TPB, 1) void mega_kernel(
    const float* __restrict__ x_a, const int* __restrict__ ei_a,
    const int* __restrict__ batch_a,
    const float* __restrict__ x_b, const int* __restrict__ ei_b,
    const int* __restrict__ batch_b,
    const float* __restrict__ W1, const float* __restrict__ b1,
    const float* __restrict__ W2, const float* __restrict__ b2,
    const float* __restrict__ W3, const float* __restrict__ b3,
    float* __restrict__ out)
{
    unsigned char* sm = smem_dyn;
    const uint32_t smb = (uint32_t)__cvta_generic_to_shared(sm);
    const int tid = threadIdx.x, bid = blockIdx.x;
    unsigned target = *((volatile unsigned*)&g_gen);

    // ---- weight transpose + split (once; shared by both encoders) ----
    {
        const float* Ws[3] = {W1, W2, W3};
        const int total = 3 * DH * DH;
        for (int idx = bid * TPB + tid; idx < total; idx += NB * TPB) {
            int l = idx >> 18;
            int rem = idx & (DH * DH - 1);
            int k = rem >> 9;
            int n = rem & 511;
            float w = Ws[l][k * DH + n];
            __nv_bfloat16 h, lo;
            bf_split(w, h, lo);
            g_wthi[l * DH * DH + n * DH + k] = h;
            g_wtlo[l * DH * DH + n * DH + k] = lo;
        }
    }
    gsync(++target);

    for (int enc = 0; enc < 2; enc++) {
        const float* x   = enc ? x_b : x_a;
        const int* srcv  = enc ? ei_b : ei_a;
        const int* dstv  = srcv + EE;
        const int* batch = enc ? batch_b : batch_a;

        // ---- count degrees ----
        for (int e = bid * TPB + tid; e < EE; e += NB * TPB)
            atomicAdd(&g_deg[dstv[e]], 1);
        gsync(++target);

        // ---- block 0: scan; blocks 1..: split x into bf16 hi/lo ----
        if (bid == 0) {
            int* sh = (int*)(sm + SM_RED);
            const int chunk = (NN + TPB - 1) / TPB;   // 40
            int base = tid * chunk;
            int local = 0;
            for (int j = 0; j < chunk; j++) {
                int idx = base + j;
                if (idx < NN) local += g_deg[idx];
            }
            sh[tid] = local;
            __syncthreads();
            for (int off = 1; off < TPB; off <<= 1) {
                int v = (tid >= off) ? sh[tid - off] : 0;
                __syncthreads();
                sh[tid] += v;
                __syncthreads();
            }
            int run = tid ? sh[tid - 1] : 0;
            for (int j = 0; j < chunk; j++) {
                int idx = base + j;
                if (idx < NN) {
                    int d = g_deg[idx];
                    g_deg[idx]    = 0;
                    g_rowptr[idx] = run;
                    g_cursor[idx] = run;
                    g_dinv[idx]   = rsqrtf((float)d + 1.0f);
                    run += d;
                }
            }
            if (tid == TPB - 1) g_rowptr[NN] = sh[TPB - 1];
        } else {
            const int total4 = NN * DH / 4;
            for (int idx = (bid - 1) * TPB + tid; idx < total4; idx += (NB - 1) * TPB) {
                float4 v = *(const float4*)(x + (size_t)idx * 4);
                __nv_bfloat162 h01, h23, l01, l23;
                bf_split(v.x, h01.x, l01.x); bf_split(v.y, h01.y, l01.y);
                bf_split(v.z, h23.x, l23.x); bf_split(v.w, h23.y, l23.y);
                __nv_bfloat162* hp = (__nv_bfloat162*)(g_ahi + (size_t)idx * 4);
                __nv_bfloat162* lp = (__nv_bfloat162*)(g_alo + (size_t)idx * 4);
                hp[0] = h01; hp[1] = h23;
                lp[0] = l01; lp[1] = l23;
            }
        }
        gsync(++target);

        // ---- fill CSR ----
        for (int e = bid * TPB + tid; e < EE; e += NB * TPB) {
            int s = srcv[e], d = dstv[e];
            int pos = atomicAdd(&g_cursor[d], 1);
            g_csr_src[pos]  = s;
            g_csr_norm[pos] = g_dinv[s] * g_dinv[d];
        }
        gsync(++target);

        // ---- 3 GCN layers ----
        for (int l = 0; l < 3; l++) {
            const float* bb = (l == 0) ? b1 : (l == 1) ? b2 : b3;
            gemm_phase(smb, g_wthi + l * DH * DH, g_wtlo + l * DH * DH, g_gemm);
            gsync(++target);
            agg_phase(g_gemm, bb, l);
            gsync(++target);
        }

        // ---- mean pool ----
        pool_phase(g_x, batch, enc);
        gsync(++target);
    }

    // ---- pairwise distance ----
    dist_phase(out, (float*)(sm + SM_RED));
}

// ---------------------------------------------------------------------------
// launch: ONE kernel (dynamic smem ~146KB)
// ---------------------------------------------------------------------------
extern "C" void kernel_launch(void* const* d_in, const int* in_sizes, int n_in,
                              void* d_out, int out_size) {
    const float* x_a     = (const float*)d_in[0];
    const int*   ei_a    = (const int*)  d_in[1];
    const int*   batch_a = (const int*)  d_in[2];
    const float* x_b     = (const float*)d_in[3];
    const int*   ei_b    = (const int*)  d_in[4];
    const int*   batch_b = (const int*)  d_in[5];
    const float* W1 = (const float*)d_in[6];
    const float* b1 = (const float*)d_in[7];
    const float* W2 = (const float*)d_in[8];
    const float* b2 = (const float*)d_in[9];
    const float* W3 = (const float*)d_in[10];
    const float* b3 = (const float*)d_in[11];
    float* out = (float*)d_out;

    cudaFuncSetAttribute(mega_kernel, cudaFuncAttributeMaxDynamicSharedMemorySize,
                         SMEM_BYTES);
    mega_kernel<<<NB, TPB, SMEM_BYTES>>>(x_a, ei_a, batch_a, x_b, ei_b, batch_b,
                                         W1, b1, W2, b2, W3, b3, out);
}

// round 10
// speedup vs baseline: 1.0895x; 1.0895x over previous
#include <cuda_runtime.h>
#include <cuda_bf16.h>
#include <cstdint>

// ---------------------------------------------------------------------------
// SiameseBrainNet: persistent mega-kernel + mma.sync split-bf16 GEMM
// R10: R8 GEMM config (8 warps, 32x64 warp tiles — proven best) +
//      bf16 hi/lo h storage; aggregate gathers bf16-hi only (half L2 traffic)
// ---------------------------------------------------------------------------

#define NN 20000
#define EE 640000
#define DH 512
#define GG 64
#define NB 148
#define TPB 256
#define MT 157
#define NTILE (4 * MT)        // 628 output tiles (128x128)

#define KSTR 72               // bf16 elements per smem row (64 data + 8 pad)
#define TILE_BYTES (128 * KSTR * 2)          // 18432
#define BUF_BYTES  (4 * TILE_BYTES)          // 73728 (Ahi,Alo,Bhi,Blo)
#define SM_RED     (2 * BUF_BYTES)           // 147456
#define SMEM_BYTES (SM_RED + 1024)           // 148480

// ---- scratch ---------------------------------------------------------------
__device__ float g_x[NN * DH];
__device__ __nv_bfloat16 g_ahi[NN * DH];        // GEMM A operand (hi)
__device__ __nv_bfloat16 g_alo[NN * DH];        // GEMM A operand (lo)
__device__ __nv_bfloat16 g_hhi[NN * DH];        // GEMM output h (hi)
__device__ __nv_bfloat16 g_hlo[NN * DH];        // GEMM output h (lo)
__device__ __nv_bfloat16 g_wthi[3 * DH * DH];   // W^T split, [l][n][k]
__device__ __nv_bfloat16 g_wtlo[3 * DH * DH];
__device__ int   g_deg[NN];        // INVARIANT: zero at kernel entry
__device__ int   g_rowptr[NN + 1];
__device__ int   g_cursor[NN];
__device__ float g_dinv[NN];
__device__ int   g_csr_src[EE];
__device__ float g_csr_norm[EE];
__device__ float g_pooled[2][GG * DH];
__device__ unsigned g_count, g_gen;

// ---- grid barrier -----------------------------------------------------------
__device__ __forceinline__ void gsync(unsigned target) {
    __syncthreads();
    if (threadIdx.x == 0) {
        __threadfence();
        if (atomicAdd(&g_count, 1u) == NB - 1u) {
            atomicExch(&g_count, 0u);
            __threadfence();
            atomicAdd(&g_gen, 1u);
        } else {
            while (*((volatile unsigned*)&g_gen) < target) __nanosleep(64);
        }
        __threadfence();
    }
    __syncthreads();
}

// ---- tensor-core primitives ---------------------------------------------------
__device__ __forceinline__ void mma16816(float* d,
                                         uint32_t a0, uint32_t a1, uint32_t a2, uint32_t a3,
                                         uint32_t b0, uint32_t b1) {
    asm volatile(
        "mma.sync.aligned.m16n8k16.row.col.f32.bf16.bf16.f32 "
        "{%0,%1,%2,%3}, {%4,%5,%6,%7}, {%8,%9}, {%0,%1,%2,%3};"
        : "+f"(d[0]), "+f"(d[1]), "+f"(d[2]), "+f"(d[3])
        : "r"(a0), "r"(a1), "r"(a2), "r"(a3), "r"(b0), "r"(b1));
}
__device__ __forceinline__ void ldsm4(uint32_t& r0, uint32_t& r1, uint32_t& r2, uint32_t& r3,
                                      uint32_t addr) {
    asm volatile("ldmatrix.sync.aligned.m8n8.x4.shared.b16 {%0,%1,%2,%3}, [%4];"
                 : "=r"(r0), "=r"(r1), "=r"(r2), "=r"(r3) : "r"(addr));
}
#define CP_COMMIT() asm volatile("cp.async.commit_group;" ::: "memory")
#define CP_WAIT(n)  asm volatile("cp.async.wait_group %0;" :: "n"(n) : "memory")

// async fill: gmem bf16 [.,512] -> smem tile 128x64 (stride KSTR)
__device__ __forceinline__ void fill_tile_async(uint32_t smt,
                                                const __nv_bfloat16* __restrict__ g,
                                                int row0, int kc, int nrows) {
    const int tid = threadIdx.x;
#pragma unroll
    for (int i = 0; i < 4; i++) {
        int idx = i * 256 + tid;       // 0..1023
        int r   = idx >> 3;            // 0..127
        int c8  = (idx & 7) << 3;      // 0..56
        int gr  = row0 + r;
        bool valid = (gr < nrows);
        const void* src = g + (size_t)(valid ? gr : 0) * DH + kc + c8;
        uint32_t dst = smt + (uint32_t)(r * KSTR + c8) * 2;
        int sz = valid ? 16 : 0;
        asm volatile("cp.async.cg.shared.global [%0], [%1], 16, %2;"
                     :: "r"(dst), "l"(src), "r"(sz) : "memory");
    }
}

__device__ __forceinline__ void bf_split(float v, __nv_bfloat16& h, __nv_bfloat16& l) {
    h = __float2bfloat16(v);
    l = __float2bfloat16(v - __bfloat162float(h));
}

// ---- GEMM phase: h[NN,512] = A @ W, split-bf16 x3, fp32 accum; epilogue
//      writes h as bf16 hi/lo pair --------------------------------------------
__device__ void gemm_phase(uint32_t smb,
                           const __nv_bfloat16* __restrict__ Whi,
                           const __nv_bfloat16* __restrict__ Wlo) {
    const int tid  = threadIdx.x;
    const int lane = tid & 31, warp = tid >> 5;
    const int wm = warp & 3;        // 32-row group
    const int wn = warp >> 2;       // 64-col group
    const int g  = lane >> 2;       // epilogue row-in-8
    const int tg = lane & 3;        // epilogue col pair
    const int seg = lane >> 3;      // ldmatrix segment 0..3
    const int lr  = lane & 7;

    const int aoff0 = (wm * 32 + 0  + (seg & 1) * 8 + lr) * KSTR + (seg >> 1) * 8;
    const int aoff1 = (wm * 32 + 16 + (seg & 1) * 8 + lr) * KSTR + (seg >> 1) * 8;
    const int boffb = (wn * 64 + (seg & 1) * 8 + lr) * KSTR + (seg >> 1) * 8;

    for (int t = blockIdx.x; t < NTILE; t += NB) {
        const int bm = t >> 2, bn = t & 3;

        float acc[2][8][4];
#pragma unroll
        for (int mt = 0; mt < 2; mt++)
#pragma unroll
            for (int nt = 0; nt < 8; nt++)
#pragma unroll
                for (int q = 0; q < 4; q++) acc[mt][nt][q] = 0.0f;

        // prologue: fill k-chunk 0 into buffer 0
        fill_tile_async(smb + 0 * TILE_BYTES, g_ahi, bm * 128, 0, NN);
        fill_tile_async(smb + 1 * TILE_BYTES, g_alo, bm * 128, 0, NN);
        fill_tile_async(smb + 2 * TILE_BYTES, Whi,   bn * 128, 0, 1 << 30);
        fill_tile_async(smb + 3 * TILE_BYTES, Wlo,   bn * 128, 0, 1 << 30);
        CP_COMMIT();

#pragma unroll 1
        for (int kc8 = 0; kc8 < 8; kc8++) {
            const uint32_t cur = smb + (uint32_t)(kc8 & 1) * BUF_BYTES;
            if (kc8 + 1 < 8) {
                const uint32_t nxt = smb + (uint32_t)((kc8 + 1) & 1) * BUF_BYTES;
                fill_tile_async(nxt + 0 * TILE_BYTES, g_ahi, bm * 128, (kc8 + 1) * 64, NN);
                fill_tile_async(nxt + 1 * TILE_BYTES, g_alo, bm * 128, (kc8 + 1) * 64, NN);
                fill_tile_async(nxt + 2 * TILE_BYTES, Whi,   bn * 128, (kc8 + 1) * 64, 1 << 30);
                fill_tile_async(nxt + 3 * TILE_BYTES, Wlo,   bn * 128, (kc8 + 1) * 64, 1 << 30);
                CP_COMMIT();
                CP_WAIT(1);
            } else {
                CP_WAIT(0);
            }
            __syncthreads();

            const uint32_t Ahi = cur + 0 * TILE_BYTES;
            const uint32_t Alo = cur + 1 * TILE_BYTES;
            const uint32_t Bhi = cur + 2 * TILE_BYTES;
            const uint32_t Blo = cur + 3 * TILE_BYTES;

#pragma unroll
            for (int ks4 = 0; ks4 < 4; ks4++) {
                const uint32_t kb = (uint32_t)(ks4 * 16) * 2;   // bytes

                uint32_t bh[8][2], bl[8][2];
#pragma unroll
                for (int nq = 0; nq < 4; nq++) {
                    uint32_t r0, r1, r2, r3;
                    ldsm4(r0, r1, r2, r3, Bhi + (uint32_t)(boffb + nq * 16 * KSTR) * 2 + kb);
                    bh[nq * 2][0] = r0; bh[nq * 2 + 1][0] = r1;
                    bh[nq * 2][1] = r2; bh[nq * 2 + 1][1] = r3;
                    ldsm4(r0, r1, r2, r3, Blo + (uint32_t)(boffb + nq * 16 * KSTR) * 2 + kb);
                    bl[nq * 2][0] = r0; bl[nq * 2 + 1][0] = r1;
                    bl[nq * 2][1] = r2; bl[nq * 2 + 1][1] = r3;
                }
#pragma unroll
                for (int mt = 0; mt < 2; mt++) {
                    const int aoff = mt ? aoff1 : aoff0;
                    uint32_t ah0, ah1, ah2, ah3, al0, al1, al2, al3;
                    ldsm4(ah0, ah1, ah2, ah3, Ahi + (uint32_t)aoff * 2 + kb);
                    ldsm4(al0, al1, al2, al3, Alo + (uint32_t)aoff * 2 + kb);
#pragma unroll
                    for (int nt = 0; nt < 8; nt++) {
                        mma16816(acc[mt][nt], ah0, ah1, ah2, ah3, bh[nt][0], bh[nt][1]);
                        mma16816(acc[mt][nt], al0, al1, al2, al3, bh[nt][0], bh[nt][1]);
                        mma16816(acc[mt][nt], ah0, ah1, ah2, ah3, bl[nt][0], bl[nt][1]);
                    }
                }
            }
            __syncthreads();
        }

        // epilogue: write h as bf16 hi/lo. frag: c0,c1 at (g, 2tg); c2,c3 at (g+8, 2tg)
#pragma unroll
        for (int mt = 0; mt < 2; mt++) {
            int row0 = bm * 128 + wm * 32 + mt * 16 + g;
#pragma unroll
            for (int nt = 0; nt < 8; nt++) {
                int col = bn * 128 + wn * 64 + nt * 8 + 2 * tg;
                if (row0 < NN) {
                    __nv_bfloat162 hp, lp;
                    bf_split(acc[mt][nt][0], hp.x, lp.x);
                    bf_split(acc[mt][nt][1], hp.y, lp.y);
                    *(__nv_bfloat162*)&g_hhi[(size_t)row0 * DH + col] = hp;
                    *(__nv_bfloat162*)&g_hlo[(size_t)row0 * DH + col] = lp;
                }
                if (row0 + 8 < NN) {
                    __nv_bfloat162 hp, lp;
                    bf_split(acc[mt][nt][2], hp.x, lp.x);
                    bf_split(acc[mt][nt][3], hp.y, lp.y);
                    *(__nv_bfloat162*)&g_hhi[(size_t)(row0 + 8) * DH + col] = hp;
                    *(__nv_bfloat162*)&g_hlo[(size_t)(row0 + 8) * DH + col] = lp;
                }
            }
        }
        __syncthreads();
    }
}

// ---- aggregation: gathers bf16-hi (half traffic); self term hi+lo -----------
__device__ __forceinline__ float4 ld_hi4(const __nv_bfloat16* __restrict__ base,
                                         size_t off) {
    const uint2 u = *(const uint2*)(base + off);
    __nv_bfloat162 p0 = *(const __nv_bfloat162*)&u.x;
    __nv_bfloat162 p1 = *(const __nv_bfloat162*)&u.y;
    float2 f0 = __bfloat1622float2(p0);
    float2 f1 = __bfloat1622float2(p1);
    return make_float4(f0.x, f0.y, f1.x, f1.y);
}

__device__ void agg_phase(const float* __restrict__ bias, int l) {
    const int sub = threadIdx.x >> 7;   // 0 or 1
    const int t   = threadIdx.x & 127;  // float4 lane
    const float4 b4 = *(const float4*)&bias[t * 4];

    for (int i = blockIdx.x * 2 + sub; i < NN; i += NB * 2) {
        int r0 = g_rowptr[i];
        int r1 = g_rowptr[i + 1];

        float4 a0 = make_float4(0.f, 0.f, 0.f, 0.f);
        float4 a1 = a0, a2 = a0, a3 = a0;

        int e = r0;
        for (; e + 7 < r1; e += 8) {
            int   s0 = g_csr_src[e],     s1 = g_csr_src[e + 1];
            int   s2 = g_csr_src[e + 2], s3 = g_csr_src[e + 3];
            int   s4 = g_csr_src[e + 4], s5 = g_csr_src[e + 5];
            int   s6 = g_csr_src[e + 6], s7 = g_csr_src[e + 7];
            float w0 = g_csr_norm[e],     w1 = g_csr_norm[e + 1];
            float w2 = g_csr_norm[e + 2], w3 = g_csr_norm[e + 3];
            float w4 = g_csr_norm[e + 4], w5 = g_csr_norm[e + 5];
            float w6 = g_csr_norm[e + 6], w7 = g_csr_norm[e + 7];
            float4 v0 = ld_hi4(g_hhi, (size_t)s0 * DH + t * 4);
            float4 v1 = ld_hi4(g_hhi, (size_t)s1 * DH + t * 4);
            float4 v2 = ld_hi4(g_hhi, (size_t)s2 * DH + t * 4);
            float4 v3 = ld_hi4(g_hhi, (size_t)s3 * DH + t * 4);
            float4 v4 = ld_hi4(g_hhi, (size_t)s4 * DH + t * 4);
            float4 v5 = ld_hi4(g_hhi, (size_t)s5 * DH + t * 4);
            float4 v6 = ld_hi4(g_hhi, (size_t)s6 * DH + t * 4);
            float4 v7 = ld_hi4(g_hhi, (size_t)s7 * DH + t * 4);
            a0.x += w0 * v0.x; a0.y += w0 * v0.y; a0.z += w0 * v0.z; a0.w += w0 * v0.w;
            a1.x += w1 * v1.x; a1.y += w1 * v1.y; a1.z += w1 * v1.z; a1.w += w1 * v1.w;
            a2.x += w2 * v2.x; a2.y += w2 * v2.y; a2.z += w2 * v2.z; a2.w += w2 * v2.w;
            a3.x += w3 * v3.x; a3.y += w3 * v3.y; a3.z += w3 * v3.z; a3.w += w3 * v3.w;
            a0.x += w4 * v4.x; a0.y += w4 * v4.y; a0.z += w4 * v4.z; a0.w += w4 * v4.w;
            a1.x += w5 * v5.x; a1.y += w5 * v5.y; a1.z += w5 * v5.z; a1.w += w5 * v5.w;
            a2.x += w6 * v6.x; a2.y += w6 * v6.y; a2.z += w6 * v6.z; a2.w += w6 * v6.w;
            a3.x += w7 * v7.x; a3.y += w7 * v7.y; a3.z += w7 * v7.z; a3.w += w7 * v7.w;
        }
        for (; e < r1; e++) {
            int   s = g_csr_src[e];
            float w = g_csr_norm[e];
            float4 v = ld_hi4(g_hhi, (size_t)s * DH + t * 4);
            a0.x += w * v.x; a0.y += w * v.y; a0.z += w * v.z; a0.w += w * v.w;
        }

        float4 acc;
        acc.x = (a0.x + a1.x) + (a2.x + a3.x);
        acc.y = (a0.y + a1.y) + (a2.y + a3.y);
        acc.z = (a0.z + a1.z) + (a2.z + a3.z);
        acc.w = (a0.w + a1.w) + (a2.w + a3.w);

        // self term: exact hi+lo reconstruction
        float4 vh = ld_hi4(g_hhi, (size_t)i * DH + t * 4);
        float4 vl = ld_hi4(g_hlo, (size_t)i * DH + t * 4);
        float d = g_dinv[i];
        float wd = d * d;
        acc.x += wd * (vh.x + vl.x) + b4.x;
        acc.y += wd * (vh.y + vl.y) + b4.y;
        acc.z += wd * (vh.z + vl.z) + b4.z;
        acc.w += wd * (vh.w + vl.w) + b4.w;

        if (l < 2) {
            acc.x = fmaxf(acc.x, 0.f); acc.y = fmaxf(acc.y, 0.f);
            acc.z = fmaxf(acc.z, 0.f); acc.w = fmaxf(acc.w, 0.f);
            __nv_bfloat162 h01, h23, l01, l23;
            bf_split(acc.x, h01.x, l01.x); bf_split(acc.y, h01.y, l01.y);
            bf_split(acc.z, h23.x, l23.x); bf_split(acc.w, h23.y, l23.y);
            __nv_bfloat162* hp = (__nv_bfloat162*)(g_ahi + (size_t)i * DH + t * 4);
            __nv_bfloat162* lp = (__nv_bfloat162*)(g_alo + (size_t)i * DH + t * 4);
            hp[0] = h01; hp[1] = h23;
            lp[0] = l01; lp[1] = l23;
        } else {
            *(float4*)&g_x[(size_t)i * DH + t * 4] = acc;
        }
    }
}

// ---- pool / dist -------------------------------------------------------------
__device__ void pool_phase(const float* __restrict__ h, const int* __restrict__ batch, int enc) {
    int g = blockIdx.x;
    if (g >= GG) return;
    int t = threadIdx.x;   // float2 lane

    int lo = 0, hi = NN;
    while (lo < hi) { int m = (lo + hi) >> 1; if (batch[m] < g) lo = m + 1; else hi = m; }
    int start = lo;
    lo = start; hi = NN;
    while (lo < hi) { int m = (lo + hi) >> 1; if (batch[m] < g + 1) lo = m + 1; else hi = m; }
    int end = lo;

    float2 a0 = make_float2(0.f, 0.f), a1 = a0;
    int r = start;
    for (; r + 1 < end; r += 2) {
        float2 v0 = *(const float2*)&h[(size_t)r * DH + t * 2];
        float2 v1 = *(const float2*)&h[(size_t)(r + 1) * DH + t * 2];
        a0.x += v0.x; a0.y += v0.y;
        a1.x += v1.x; a1.y += v1.y;
    }
    if (r < end) {
        float2 v = *(const float2*)&h[(size_t)r * DH + t * 2];
        a0.x += v.x; a0.y += v.y;
    }
    float inv = 1.0f / fmaxf((float)(end - start), 1.0f);
    *(float2*)&g_pooled[enc][g * DH + t * 2] =
        make_float2((a0.x + a1.x) * inv, (a0.y + a1.y) * inv);
}

__device__ void dist_phase(float* __restrict__ out, float* sred) {
    int g = blockIdx.x;
    if (g >= GG) return;
    int t = threadIdx.x;

    float2 a = *(const float2*)&g_pooled[0][g * DH + t * 2];
    float2 b = *(const float2*)&g_pooled[1][g * DH + t * 2];
    float dx = a.x - b.x + 1e-6f;
    float dy = a.y - b.y + 1e-6f;
    float s = dx * dx + dy * dy;

    sred[t] = s;
    __syncthreads();
    for (int off = 128; off > 0; off >>= 1) {
        if (t < off) sred[t] += sred[t + off];
        __syncthreads();
    }
    if (t == 0) out[g] = sqrtf(sred[0]);
}

// ---- mega kernel --------------------------------------------------------------
extern __shared__ __align__(16) unsigned char smem_dyn[];

__global__ __launch_bounds__(TPB, 1) void mega_kernel(
    const float* __restrict__ x_a, const int* __restrict__ ei_a,
    const int* __restrict__ batch_a,
    const float* __restrict__ x_b, const int* __restrict__ ei_b,
    const int* __restrict__ batch_b,
    const float* __restrict__ W1, const float* __restrict__ b1,
    const float* __restrict__ W2, const float* __restrict__ b2,
    const float* __restrict__ W3, const float* __restrict__ b3,
    float* __restrict__ out)
{
    unsigned char* sm = smem_dyn;
    const uint32_t smb = (uint32_t)__cvta_generic_to_shared(sm);
    const int tid = threadIdx.x, bid = blockIdx.x;
    unsigned target = *((volatile unsigned*)&g_gen);

    // ---- weight transpose + split (once; shared by both encoders) ----
    {
        const float* Ws[3] = {W1, W2, W3};
        const int total = 3 * DH * DH;
        for (int idx = bid * TPB + tid; idx < total; idx += NB * TPB) {
            int l = idx >> 18;
            int rem = idx & (DH * DH - 1);
            int k = rem >> 9;
            int n = rem & 511;
            float w = Ws[l][k * DH + n];
            __nv_bfloat16 h, lo;
            bf_split(w, h, lo);
            g_wthi[l * DH * DH + n * DH + k] = h;
            g_wtlo[l * DH * DH + n * DH + k] = lo;
        }
    }
    gsync(++target);

    for (int enc = 0; enc < 2; enc++) {
        const float* x   = enc ? x_b : x_a;
        const int* srcv  = enc ? ei_b : ei_a;
        const int* dstv  = srcv + EE;
        const int* batch = enc ? batch_b : batch_a;

        // ---- count degrees ----
        for (int e = bid * TPB + tid; e < EE; e += NB * TPB)
            atomicAdd(&g_deg[dstv[e]], 1);
        gsync(++target);

        // ---- block 0: scan; blocks 1..: split x into bf16 hi/lo ----
        if (bid == 0) {
            int* sh = (int*)(sm + SM_RED);
            const int chunk = (NN + TPB - 1) / TPB;   // 79
            int base = tid * chunk;
            int local = 0;
            for (int j = 0; j < chunk; j++) {
                int idx = base + j;
                if (idx < NN) local += g_deg[idx];
            }
            sh[tid] = local;
            __syncthreads();
            for (int off = 1; off < TPB; off <<= 1) {
                int v = (tid >= off) ? sh[tid - off] : 0;
                __syncthreads();
                sh[tid] += v;
                __syncthreads();
            }
            int run = tid ? sh[tid - 1] : 0;
            for (int j = 0; j < chunk; j++) {
                int idx = base + j;
                if (idx < NN) {
                    int d = g_deg[idx];
                    g_deg[idx]    = 0;
                    g_rowptr[idx] = run;
                    g_cursor[idx] = run;
                    g_dinv[idx]   = rsqrtf((float)d + 1.0f);
                    run += d;
                }
            }
            if (tid == TPB - 1) g_rowptr[NN] = sh[TPB - 1];
        } else {
            const int total4 = NN * DH / 4;
            for (int idx = (bid - 1) * TPB + tid; idx < total4; idx += (NB - 1) * TPB) {
                float4 v = *(const float4*)(x + (size_t)idx * 4);
                __nv_bfloat162 h01, h23, l01, l23;
                bf_split(v.x, h01.x, l01.x); bf_split(v.y, h01.y, l01.y);
                bf_split(v.z, h23.x, l23.x); bf_split(v.w, h23.y, l23.y);
                __nv_bfloat162* hp = (__nv_bfloat162*)(g_ahi + (size_t)idx * 4);
                __nv_bfloat162* lp = (__nv_bfloat162*)(g_alo + (size_t)idx * 4);
                hp[0] = h01; hp[1] = h23;
                lp[0] = l01; lp[1] = l23;
            }
        }
        gsync(++target);

        // ---- fill CSR ----
        for (int e = bid * TPB + tid; e < EE; e += NB * TPB) {
            int s = srcv[e], d = dstv[e];
            int pos = atomicAdd(&g_cursor[d], 1);
            g_csr_src[pos]  = s;
            g_csr_norm[pos] = g_dinv[s] * g_dinv[d];
        }
        gsync(++target);

        // ---- 3 GCN layers ----
        for (int l = 0; l < 3; l++) {
            const float* bb = (l == 0) ? b1 : (l == 1) ? b2 : b3;
            gemm_phase(smb, g_wthi + l * DH * DH, g_wtlo + l * DH * DH);
            gsync(++target);
            agg_phase(bb, l);
            gsync(++target);
        }

        // ---- mean pool ----
        pool_phase(g_x, batch, enc);
        gsync(++target);
    }

    // ---- pairwise distance ----
    dist_phase(out, (float*)(sm + SM_RED));
}

// ---------------------------------------------------------------------------
// launch: ONE kernel (dynamic smem ~145KB)
// ---------------------------------------------------------------------------
extern "C" void kernel_launch(void* const* d_in, const int* in_sizes, int n_in,
                              void* d_out, int out_size) {
    const float* x_a     = (const float*)d_in[0];
    const int*   ei_a    = (const int*)  d_in[1];
    const int*   batch_a = (const int*)  d_in[2];
    const float* x_b     = (const float*)d_in[3];
    const int*   ei_b    = (const int*)  d_in[4];
    const int*   batch_b = (const int*)  d_in[5];
    const float* W1 = (const float*)d_in[6];
    const float* b1 = (const float*)d_in[7];
    const float* W2 = (const float*)d_in[8];
    const float* b2 = (const float*)d_in[9];
    const float* W3 = (const float*)d_in[10];
    const float* b3 = (const float*)d_in[11];
    float* out = (float*)d_out;

    cudaFuncSetAttribute(mega_kernel, cudaFuncAttributeMaxDynamicSharedMemorySize,
                         SMEM_BYTES);
    mega_kernel<<<NB, TPB, SMEM_BYTES>>>(x_a, ei_a, batch_a, x_b, ei_b, batch_b,
                                         W1, b1, W2, b2, W3, b3, out);
}

// round 11
// speedup vs baseline: 1.3108x; 1.2031x over previous
#include <cuda_runtime.h>
#include <cuda_bf16.h>
#include <cstdint>

// ---------------------------------------------------------------------------
// SiameseBrainNet: persistent mega-kernel + mma.sync split-bf16 GEMM
// R11: R8 GEMM shape (8 warps, 32x64 tiles) with
//   (a) 2-term split (A=hi+lo exact, W=bf16; calibrated rel_err ~1.2e-4)
//   (b) encoders FUSED: one M=40000 GEMM/agg stream -> 8.5 waves (6% tail
//       vs 24%), half the grid barriers.
// ---------------------------------------------------------------------------

#define NN 20000
#define N2 (2 * NN)           // fused node count
#define EE 640000
#define DH 512
#define GG 64
#define NB 148
#define TPB 256
#define MT 313                // ceil(40000/128)
#define NTILE (4 * MT)        // 1252 output tiles (128x128)

#define KSTR 72               // bf16 elements per smem row (64 data + 8 pad)
#define TILE_BYTES (128 * KSTR * 2)          // 18432
#define BUF_BYTES  (3 * TILE_BYTES)          // 55296 (Ahi,Alo,Bhi)
#define SM_RED     (2 * BUF_BYTES)           // 110592
#define SMEM_BYTES (SM_RED + 1024)           // 111616

// ---- scratch ---------------------------------------------------------------
__device__ float g_gemm[N2 * DH];               // GEMM output h (fp32)
__device__ float g_x[N2 * DH];                  // last-layer agg output
__device__ __nv_bfloat16 g_ahi[N2 * DH];        // GEMM A operand (hi)
__device__ __nv_bfloat16 g_alo[N2 * DH];        // GEMM A operand (lo)
__device__ __nv_bfloat16 g_whi[3 * DH * DH];    // W^T bf16, [l][n][k]
__device__ int   g_deg[2][NN];     // INVARIANT: zero at kernel entry
__device__ int   g_rowptr[2][NN + 1];
__device__ int   g_cursor[2][NN];
__device__ float g_dinv[2][NN];
__device__ int   g_csr_src[2][EE];
__device__ float g_csr_norm[2][EE];
__device__ float g_pooled[2][GG * DH];
__device__ unsigned g_count, g_gen;

// ---- grid barrier -----------------------------------------------------------
__device__ __forceinline__ void gsync(unsigned target) {
    __syncthreads();
    if (threadIdx.x == 0) {
        __threadfence();
        if (atomicAdd(&g_count, 1u) == NB - 1u) {
            atomicExch(&g_count, 0u);
            __threadfence();
            atomicAdd(&g_gen, 1u);
        } else {
            while (*((volatile unsigned*)&g_gen) < target) __nanosleep(64);
        }
        __threadfence();
    }
    __syncthreads();
}

// ---- tensor-core primitives ---------------------------------------------------
__device__ __forceinline__ void mma16816(float* d,
                                         uint32_t a0, uint32_t a1, uint32_t a2, uint32_t a3,
                                         uint32_t b0, uint32_t b1) {
    asm volatile(
        "mma.sync.aligned.m16n8k16.row.col.f32.bf16.bf16.f32 "
        "{%0,%1,%2,%3}, {%4,%5,%6,%7}, {%8,%9}, {%0,%1,%2,%3};"
        : "+f"(d[0]), "+f"(d[1]), "+f"(d[2]), "+f"(d[3])
        : "r"(a0), "r"(a1), "r"(a2), "r"(a3), "r"(b0), "r"(b1));
}
__device__ __forceinline__ void ldsm4(uint32_t& r0, uint32_t& r1, uint32_t& r2, uint32_t& r3,
                                      uint32_t addr) {
    asm volatile("ldmatrix.sync.aligned.m8n8.x4.shared.b16 {%0,%1,%2,%3}, [%4];"
                 : "=r"(r0), "=r"(r1), "=r"(r2), "=r"(r3) : "r"(addr));
}
#define CP_COMMIT() asm volatile("cp.async.commit_group;" ::: "memory")
#define CP_WAIT(n)  asm volatile("cp.async.wait_group %0;" :: "n"(n) : "memory")

// async fill: gmem bf16 [.,512] -> smem tile 128x64 (stride KSTR)
__device__ __forceinline__ void fill_tile_async(uint32_t smt,
                                                const __nv_bfloat16* __restrict__ g,
                                                int row0, int kc, int nrows) {
    const int tid = threadIdx.x;
#pragma unroll
    for (int i = 0; i < 4; i++) {
        int idx = i * 256 + tid;       // 0..1023
        int r   = idx >> 3;            // 0..127
        int c8  = (idx & 7) << 3;      // 0..56
        int gr  = row0 + r;
        bool valid = (gr < nrows);
        const void* src = g + (size_t)(valid ? gr : 0) * DH + kc + c8;
        uint32_t dst = smt + (uint32_t)(r * KSTR + c8) * 2;
        int sz = valid ? 16 : 0;
        asm volatile("cp.async.cg.shared.global [%0], [%1], 16, %2;"
                     :: "r"(dst), "l"(src), "r"(sz) : "memory");
    }
}

__device__ __forceinline__ void bf_split(float v, __nv_bfloat16& h, __nv_bfloat16& l) {
    h = __float2bfloat16(v);
    l = __float2bfloat16(v - __bfloat162float(h));
}

// ---- GEMM phase: g_gemm[N2,512] = A @ W  (A = hi+lo bf16, W = bf16) ---------
__device__ void gemm_phase(uint32_t smb, const __nv_bfloat16* __restrict__ Whi) {
    const int tid  = threadIdx.x;
    const int lane = tid & 31, warp = tid >> 5;
    const int wm = warp & 3;        // 32-row group
    const int wn = warp >> 2;       // 64-col group
    const int g  = lane >> 2;       // epilogue row-in-8
    const int tg = lane & 3;        // epilogue col pair
    const int seg = lane >> 3;      // ldmatrix segment 0..3
    const int lr  = lane & 7;

    const int aoff0 = (wm * 32 + 0  + (seg & 1) * 8 + lr) * KSTR + (seg >> 1) * 8;
    const int aoff1 = (wm * 32 + 16 + (seg & 1) * 8 + lr) * KSTR + (seg >> 1) * 8;
    const int boffb = (wn * 64 + (seg & 1) * 8 + lr) * KSTR + (seg >> 1) * 8;

    for (int t = blockIdx.x; t < NTILE; t += NB) {
        const int bm = t >> 2, bn = t & 3;

        float acc[2][8][4];
#pragma unroll
        for (int mt = 0; mt < 2; mt++)
#pragma unroll
            for (int nt = 0; nt < 8; nt++)
#pragma unroll
                for (int q = 0; q < 4; q++) acc[mt][nt][q] = 0.0f;

        // prologue: fill k-chunk 0 into buffer 0
        fill_tile_async(smb + 0 * TILE_BYTES, g_ahi, bm * 128, 0, N2);
        fill_tile_async(smb + 1 * TILE_BYTES, g_alo, bm * 128, 0, N2);
        fill_tile_async(smb + 2 * TILE_BYTES, Whi,   bn * 128, 0, 1 << 30);
        CP_COMMIT();

#pragma unroll 1
        for (int kc8 = 0; kc8 < 8; kc8++) {
            const uint32_t cur = smb + (uint32_t)(kc8 & 1) * BUF_BYTES;
            if (kc8 + 1 < 8) {
                const uint32_t nxt = smb + (uint32_t)((kc8 + 1) & 1) * BUF_BYTES;
                fill_tile_async(nxt + 0 * TILE_BYTES, g_ahi, bm * 128, (kc8 + 1) * 64, N2);
                fill_tile_async(nxt + 1 * TILE_BYTES, g_alo, bm * 128, (kc8 + 1) * 64, N2);
                fill_tile_async(nxt + 2 * TILE_BYTES, Whi,   bn * 128, (kc8 + 1) * 64, 1 << 30);
                CP_COMMIT();
                CP_WAIT(1);
            } else {
                CP_WAIT(0);
            }
            __syncthreads();

            const uint32_t Ahi = cur + 0 * TILE_BYTES;
            const uint32_t Alo = cur + 1 * TILE_BYTES;
            const uint32_t Bhi = cur + 2 * TILE_BYTES;

#pragma unroll
            for (int ks4 = 0; ks4 < 4; ks4++) {
                const uint32_t kb = (uint32_t)(ks4 * 16) * 2;   // bytes

                uint32_t bh[8][2];
#pragma unroll
                for (int nq = 0; nq < 4; nq++) {
                    uint32_t r0, r1, r2, r3;
                    ldsm4(r0, r1, r2, r3, Bhi + (uint32_t)(boffb + nq * 16 * KSTR) * 2 + kb);
                    bh[nq * 2][0] = r0; bh[nq * 2 + 1][0] = r1;
                    bh[nq * 2][1] = r2; bh[nq * 2 + 1][1] = r3;
                }
#pragma unroll
                for (int mt = 0; mt < 2; mt++) {
                    const int aoff = mt ? aoff1 : aoff0;
                    uint32_t ah0, ah1, ah2, ah3, al0, al1, al2, al3;
                    ldsm4(ah0, ah1, ah2, ah3, Ahi + (uint32_t)aoff * 2 + kb);
                    ldsm4(al0, al1, al2, al3, Alo + (uint32_t)aoff * 2 + kb);
#pragma unroll
                    for (int nt = 0; nt < 8; nt++) {
                        mma16816(acc[mt][nt], ah0, ah1, ah2, ah3, bh[nt][0], bh[nt][1]);
                        mma16816(acc[mt][nt], al0, al1, al2, al3, bh[nt][0], bh[nt][1]);
                    }
                }
            }
            __syncthreads();
        }

        // epilogue: fp32 h. frag: c0,c1 at (g, 2tg); c2,c3 at (g+8, 2tg)
#pragma unroll
        for (int mt = 0; mt < 2; mt++) {
            int row0 = bm * 128 + wm * 32 + mt * 16 + g;
#pragma unroll
            for (int nt = 0; nt < 8; nt++) {
                int col = bn * 128 + wn * 64 + nt * 8 + 2 * tg;
                if (row0 < N2)
                    *(float2*)&g_gemm[(size_t)row0 * DH + col] =
                        make_float2(acc[mt][nt][0], acc[mt][nt][1]);
                if (row0 + 8 < N2)
                    *(float2*)&g_gemm[(size_t)(row0 + 8) * DH + col] =
                        make_float2(acc[mt][nt][2], acc[mt][nt][3]);
            }
        }
        __syncthreads();
    }
}

// ---- aggregation over fused node range [0, 2NN) ------------------------------
__device__ void agg_phase(const float* __restrict__ bias, int l) {
    const int sub = threadIdx.x >> 7;   // 0 or 1
    const int t   = threadIdx.x & 127;  // float4 lane
    const float4 b4 = *(const float4*)&bias[t * 4];

    for (int j = blockIdx.x * 2 + sub; j < N2; j += NB * 2) {
        const int enc = (j >= NN);
        const int i   = j - enc * NN;
        const int* __restrict__ csr = g_csr_src[enc];
        const float* __restrict__ nrm = g_csr_norm[enc];
        const float* __restrict__ h = g_gemm + (size_t)enc * NN * DH;

        int r0 = g_rowptr[enc][i];
        int r1 = g_rowptr[enc][i + 1];

        float4 a0 = make_float4(0.f, 0.f, 0.f, 0.f);
        float4 a1 = a0, a2 = a0, a3 = a0;

        int e = r0;
        for (; e + 7 < r1; e += 8) {
            int   s0 = csr[e],     s1 = csr[e + 1];
            int   s2 = csr[e + 2], s3 = csr[e + 3];
            int   s4 = csr[e + 4], s5 = csr[e + 5];
            int   s6 = csr[e + 6], s7 = csr[e + 7];
            float w0 = nrm[e],     w1 = nrm[e + 1];
            float w2 = nrm[e + 2], w3 = nrm[e + 3];
            float w4 = nrm[e + 4], w5 = nrm[e + 5];
            float w6 = nrm[e + 6], w7 = nrm[e + 7];
            float4 v0 = *(const float4*)&h[(size_t)s0 * DH + t * 4];
            float4 v1 = *(const float4*)&h[(size_t)s1 * DH + t * 4];
            float4 v2 = *(const float4*)&h[(size_t)s2 * DH + t * 4];
            float4 v3 = *(const float4*)&h[(size_t)s3 * DH + t * 4];
            float4 v4 = *(const float4*)&h[(size_t)s4 * DH + t * 4];
            float4 v5 = *(const float4*)&h[(size_t)s5 * DH + t * 4];
            float4 v6 = *(const float4*)&h[(size_t)s6 * DH + t * 4];
            float4 v7 = *(const float4*)&h[(size_t)s7 * DH + t * 4];
            a0.x += w0 * v0.x; a0.y += w0 * v0.y; a0.z += w0 * v0.z; a0.w += w0 * v0.w;
            a1.x += w1 * v1.x; a1.y += w1 * v1.y; a1.z += w1 * v1.z; a1.w += w1 * v1.w;
            a2.x += w2 * v2.x; a2.y += w2 * v2.y; a2.z += w2 * v2.z; a2.w += w2 * v2.w;
            a3.x += w3 * v3.x; a3.y += w3 * v3.y; a3.z += w3 * v3.z; a3.w += w3 * v3.w;
            a0.x += w4 * v4.x; a0.y += w4 * v4.y; a0.z += w4 * v4.z; a0.w += w4 * v4.w;
            a1.x += w5 * v5.x; a1.y += w5 * v5.y; a1.z += w5 * v5.z; a1.w += w5 * v5.w;
            a2.x += w6 * v6.x; a2.y += w6 * v6.y; a2.z += w6 * v6.z; a2.w += w6 * v6.w;
            a3.x += w7 * v7.x; a3.y += w7 * v7.y; a3.z += w7 * v7.z; a3.w += w7 * v7.w;
        }
        for (; e < r1; e++) {
            int   s = csr[e];
            float w = nrm[e];
            float4 v = *(const float4*)&h[(size_t)s * DH + t * 4];
            a0.x += w * v.x; a0.y += w * v.y; a0.z += w * v.z; a0.w += w * v.w;
        }

        float4 acc;
        acc.x = (a0.x + a1.x) + (a2.x + a3.x);
        acc.y = (a0.y + a1.y) + (a2.y + a3.y);
        acc.z = (a0.z + a1.z) + (a2.z + a3.z);
        acc.w = (a0.w + a1.w) + (a2.w + a3.w);

        float d = g_dinv[enc][i];
        float wd = d * d;
        float4 vs = *(const float4*)&h[(size_t)i * DH + t * 4];
        acc.x += wd * vs.x + b4.x;
        acc.y += wd * vs.y + b4.y;
        acc.z += wd * vs.z + b4.z;
        acc.w += wd * vs.w + b4.w;

        if (l < 2) {   // relu + split into bf16 hi/lo for next GEMM
            acc.x = fmaxf(acc.x, 0.f); acc.y = fmaxf(acc.y, 0.f);
            acc.z = fmaxf(acc.z, 0.f); acc.w = fmaxf(acc.w, 0.f);
            __nv_bfloat162 h01, h23, l01, l23;
            bf_split(acc.x, h01.x, l01.x); bf_split(acc.y, h01.y, l01.y);
            bf_split(acc.z, h23.x, l23.x); bf_split(acc.w, h23.y, l23.y);
            __nv_bfloat162* hp = (__nv_bfloat162*)(g_ahi + (size_t)j * DH + t * 4);
            __nv_bfloat162* lp = (__nv_bfloat162*)(g_alo + (size_t)j * DH + t * 4);
            hp[0] = h01; hp[1] = h23;
            lp[0] = l01; lp[1] = l23;
        } else {
            *(float4*)&g_x[(size_t)j * DH + t * 4] = acc;
        }
    }
}

// ---- pool (128 blocks: enc = bid>>6, graph = bid&63) -------------------------
__device__ void pool_phase(const int* __restrict__ batch_a,
                           const int* __restrict__ batch_b) {
    int bid = blockIdx.x;
    if (bid >= 2 * GG) return;
    int enc = bid >> 6;
    int g = bid & 63;
    int t = threadIdx.x;   // float2 lane

    const int* batch = enc ? batch_b : batch_a;
    const float* h = g_x + (size_t)enc * NN * DH;

    int lo = 0, hi = NN;
    while (lo < hi) { int m = (lo + hi) >> 1; if (batch[m] < g) lo = m + 1; else hi = m; }
    int start = lo;
    lo = start; hi = NN;
    while (lo < hi) { int m = (lo + hi) >> 1; if (batch[m] < g + 1) lo = m + 1; else hi = m; }
    int end = lo;

    float2 a0 = make_float2(0.f, 0.f), a1 = a0;
    int r = start;
    for (; r + 1 < end; r += 2) {
        float2 v0 = *(const float2*)&h[(size_t)r * DH + t * 2];
        float2 v1 = *(const float2*)&h[(size_t)(r + 1) * DH + t * 2];
        a0.x += v0.x; a0.y += v0.y;
        a1.x += v1.x; a1.y += v1.y;
    }
    if (r < end) {
        float2 v = *(const float2*)&h[(size_t)r * DH + t * 2];
        a0.x += v.x; a0.y += v.y;
    }
    float inv = 1.0f / fmaxf((float)(end - start), 1.0f);
    *(float2*)&g_pooled[enc][g * DH + t * 2] =
        make_float2((a0.x + a1.x) * inv, (a0.y + a1.y) * inv);
}

__device__ void dist_phase(float* __restrict__ out, float* sred) {
    int g = blockIdx.x;
    if (g >= GG) return;
    int t = threadIdx.x;

    float2 a = *(const float2*)&g_pooled[0][g * DH + t * 2];
    float2 b = *(const float2*)&g_pooled[1][g * DH + t * 2];
    float dx = a.x - b.x + 1e-6f;
    float dy = a.y - b.y + 1e-6f;
    float s = dx * dx + dy * dy;

    sred[t] = s;
    __syncthreads();
    for (int off = 128; off > 0; off >>= 1) {
        if (t < off) sred[t] += sred[t + off];
        __syncthreads();
    }
    if (t == 0) out[g] = sqrtf(sred[0]);
}

// ---- mega kernel --------------------------------------------------------------
extern __shared__ __align__(16) unsigned char smem_dyn[];

__global__ __launch_bounds__(TPB, 1) void mega_kernel(
    const float* __restrict__ x_a, const int* __restrict__ ei_a,
    const int* __restrict__ batch_a,
    const float* __restrict__ x_b, const int* __restrict__ ei_b,
    const int* __restrict__ batch_b,
    const float* __restrict__ W1, const float* __restrict__ b1,
    const float* __restrict__ W2, const float* __restrict__ b2,
    const float* __restrict__ W3, const float* __restrict__ b3,
    float* __restrict__ out)
{
    unsigned char* sm = smem_dyn;
    const uint32_t smb = (uint32_t)__cvta_generic_to_shared(sm);
    const int tid = threadIdx.x, bid = blockIdx.x;
    unsigned target = *((volatile unsigned*)&g_gen);

    // ---- Phase A (combined): W transpose+round, x splits (both), deg counts
    {
        const float* Ws[3] = {W1, W2, W3};
        const int total = 3 * DH * DH;
        for (int idx = bid * TPB + tid; idx < total; idx += NB * TPB) {
            int l = idx >> 18;
            int rem = idx & (DH * DH - 1);
            int k = rem >> 9;
            int n = rem & 511;
            g_whi[l * DH * DH + n * DH + k] = __float2bfloat16(Ws[l][k * DH + n]);
        }
    }
    {
        const int total4 = NN * DH / 4;
        for (int idx = bid * TPB + tid; idx < 2 * total4; idx += NB * TPB) {
            int enc = (idx >= total4);
            int i4  = idx - enc * total4;
            const float* xs = enc ? x_b : x_a;
            float4 v = *(const float4*)(xs + (size_t)i4 * 4);
            __nv_bfloat162 h01, h23, l01, l23;
            bf_split(v.x, h01.x, l01.x); bf_split(v.y, h01.y, l01.y);
            bf_split(v.z, h23.x, l23.x); bf_split(v.w, h23.y, l23.y);
            size_t o4 = (size_t)enc * total4 + i4;
            __nv_bfloat162* hp = (__nv_bfloat162*)(g_ahi + o4 * 4);
            __nv_bfloat162* lp = (__nv_bfloat162*)(g_alo + o4 * 4);
            hp[0] = h01; hp[1] = h23;
            lp[0] = l01; lp[1] = l23;
        }
    }
    for (int e = bid * TPB + tid; e < 2 * EE; e += NB * TPB) {
        int enc = (e >= EE);
        int el  = e - enc * EE;
        const int* dstv = (enc ? ei_b : ei_a) + EE;
        atomicAdd(&g_deg[enc][dstv[el]], 1);
    }
    gsync(++target);

    // ---- Phase B: scans (block 0 -> enc 0, block 1 -> enc 1) ----
    if (bid < 2) {
        const int enc = bid;
        int* sh = (int*)(sm + SM_RED);
        const int chunk = (NN + TPB - 1) / TPB;   // 79
        int base = tid * chunk;
        int local = 0;
        for (int j = 0; j < chunk; j++) {
            int idx = base + j;
            if (idx < NN) local += g_deg[enc][idx];
        }
        sh[tid] = local;
        __syncthreads();
        for (int off = 1; off < TPB; off <<= 1) {
            int v = (tid >= off) ? sh[tid - off] : 0;
            __syncthreads();
            sh[tid] += v;
            __syncthreads();
        }
        int run = tid ? sh[tid - 1] : 0;
        for (int j = 0; j < chunk; j++) {
            int idx = base + j;
            if (idx < NN) {
                int d = g_deg[enc][idx];
                g_deg[enc][idx]    = 0;               // restore invariant
                g_rowptr[enc][idx] = run;
                g_cursor[enc][idx] = run;
                g_dinv[enc][idx]   = rsqrtf((float)d + 1.0f);
                run += d;
            }
        }
        if (tid == TPB - 1) g_rowptr[enc][NN] = sh[TPB - 1];
    }
    gsync(++target);

    // ---- Phase C: fill CSR (both encoders) ----
    for (int e = bid * TPB + tid; e < 2 * EE; e += NB * TPB) {
        int enc = (e >= EE);
        int el  = e - enc * EE;
        const int* srcv = enc ? ei_b : ei_a;
        const int* dstv = srcv + EE;
        int s = srcv[el], d = dstv[el];
        int pos = atomicAdd(&g_cursor[enc][d], 1);
        g_csr_src[enc][pos]  = s;
        g_csr_norm[enc][pos] = g_dinv[enc][s] * g_dinv[enc][d];
    }
    gsync(++target);

    // ---- 3 GCN layers over fused M=40000 ----
    for (int l = 0; l < 3; l++) {
        const float* bb = (l == 0) ? b1 : (l == 1) ? b2 : b3;
        gemm_phase(smb, g_whi + l * DH * DH);
        gsync(++target);
        agg_phase(bb, l);
        gsync(++target);
    }

    // ---- mean pool (both encoders, 128 blocks) ----
    pool_phase(batch_a, batch_b);
    gsync(++target);

    // ---- pairwise distance ----
    dist_phase(out, (float*)(sm + SM_RED));
}

// ---------------------------------------------------------------------------
// launch: ONE kernel (dynamic smem ~109KB)
// ---------------------------------------------------------------------------
extern "C" void kernel_launch(void* const* d_in, const int* in_sizes, int n_in,
                              void* d_out, int out_size) {
    const float* x_a     = (const float*)d_in[0];
    const int*   ei_a    = (const int*)  d_in[1];
    const int*   batch_a = (const int*)  d_in[2];
    const float* x_b     = (const float*)d_in[3];
    const int*   ei_b    = (const int*)  d_in[4];
    const int*   batch_b = (const int*)  d_in[5];
    const float* W1 = (const float*)d_in[6];
    const float* b1 = (const float*)d_in[7];
    const float* W2 = (const float*)d_in[8];
    const float* b2 = (const float*)d_in[9];
    const float* W3 = (const float*)d_in[10];
    const float* b3 = (const float*)d_in[11];
    float* out = (float*)d_out;

    cudaFuncSetAttribute(mega_kernel, cudaFuncAttributeMaxDynamicSharedMemorySize,
                         SMEM_BYTES);
    mega_kernel<<<NB, TPB, SMEM_BYTES>>>(x_a, ei_a, batch_a, x_b, ei_b, batch_b,
                                         W1, b1, W2, b2, W3, b3, out);
}

// round 12
// speedup vs baseline: 1.3759x; 1.0497x over previous
#include <cuda_runtime.h>
#include <cuda_bf16.h>
#include <cstdint>

// ---------------------------------------------------------------------------
// SiameseBrainNet: persistent mega-kernel + mma.sync split-bf16 GEMM
// R12: (a) GEMM 3-stage cp.async pipeline — ONE syncthreads per k-chunk,
//          fills have 2 chunks of compute to land.
//      (b) aggregate prefetches next batch's csr indices/norms while the
//          current batch's gathers are in flight (breaks idx->gather chain).
// ---------------------------------------------------------------------------

#define NN 20000
#define N2 (2 * NN)           // fused node count
#define EE 640000
#define DH 512
#define GG 64
#define NB 148
#define TPB 256
#define MT 313                // ceil(40000/128)
#define NTILE (4 * MT)        // 1252 output tiles (128x128)

#define KSTR 72               // bf16 elements per smem row (64 data + 8 pad)
#define TILE_BYTES (128 * KSTR * 2)          // 18432
#define BUF_BYTES  (3 * TILE_BYTES)          // 55296 (Ahi,Alo,Bhi)
#define SM_RED     (3 * BUF_BYTES)           // 165888 (3-stage)
#define SMEM_BYTES (SM_RED + 1024)           // 166912

// ---- scratch ---------------------------------------------------------------
__device__ float g_gemm[N2 * DH];               // GEMM output h (fp32)
__device__ float g_x[N2 * DH];                  // last-layer agg output
__device__ __nv_bfloat16 g_ahi[N2 * DH];        // GEMM A operand (hi)
__device__ __nv_bfloat16 g_alo[N2 * DH];        // GEMM A operand (lo)
__device__ __nv_bfloat16 g_whi[3 * DH * DH];    // W^T bf16, [l][n][k]
__device__ int   g_deg[2][NN];     // INVARIANT: zero at kernel entry
__device__ int   g_rowptr[2][NN + 1];
__device__ int   g_cursor[2][NN];
__device__ float g_dinv[2][NN];
__device__ int   g_csr_src[2][EE];
__device__ float g_csr_norm[2][EE];
__device__ float g_pooled[2][GG * DH];
__device__ unsigned g_count, g_gen;

// ---- grid barrier -----------------------------------------------------------
__device__ __forceinline__ void gsync(unsigned target) {
    __syncthreads();
    if (threadIdx.x == 0) {
        __threadfence();
        if (atomicAdd(&g_count, 1u) == NB - 1u) {
            atomicExch(&g_count, 0u);
            __threadfence();
            atomicAdd(&g_gen, 1u);
        } else {
            while (*((volatile unsigned*)&g_gen) < target) __nanosleep(64);
        }
        __threadfence();
    }
    __syncthreads();
}

// ---- tensor-core primitives ---------------------------------------------------
__device__ __forceinline__ void mma16816(float* d,
                                         uint32_t a0, uint32_t a1, uint32_t a2, uint32_t a3,
                                         uint32_t b0, uint32_t b1) {
    asm volatile(
        "mma.sync.aligned.m16n8k16.row.col.f32.bf16.bf16.f32 "
        "{%0,%1,%2,%3}, {%4,%5,%6,%7}, {%8,%9}, {%0,%1,%2,%3};"
        : "+f"(d[0]), "+f"(d[1]), "+f"(d[2]), "+f"(d[3])
        : "r"(a0), "r"(a1), "r"(a2), "r"(a3), "r"(b0), "r"(b1));
}
__device__ __forceinline__ void ldsm4(uint32_t& r0, uint32_t& r1, uint32_t& r2, uint32_t& r3,
                                      uint32_t addr) {
    asm volatile("ldmatrix.sync.aligned.m8n8.x4.shared.b16 {%0,%1,%2,%3}, [%4];"
                 : "=r"(r0), "=r"(r1), "=r"(r2), "=r"(r3) : "r"(addr));
}
#define CP_COMMIT() asm volatile("cp.async.commit_group;" ::: "memory")
#define CP_WAIT(n)  asm volatile("cp.async.wait_group %0;" :: "n"(n) : "memory")

// async fill: gmem bf16 [.,512] -> smem tile 128x64 (stride KSTR)
__device__ __forceinline__ void fill_tile_async(uint32_t smt,
                                                const __nv_bfloat16* __restrict__ g,
                                                int row0, int kc, int nrows) {
    const int tid = threadIdx.x;
#pragma unroll
    for (int i = 0; i < 4; i++) {
        int idx = i * 256 + tid;       // 0..1023
        int r   = idx >> 3;            // 0..127
        int c8  = (idx & 7) << 3;      // 0..56
        int gr  = row0 + r;
        bool valid = (gr < nrows);
        const void* src = g + (size_t)(valid ? gr : 0) * DH + kc + c8;
        uint32_t dst = smt + (uint32_t)(r * KSTR + c8) * 2;
        int sz = valid ? 16 : 0;
        asm volatile("cp.async.cg.shared.global [%0], [%1], 16, %2;"
                     :: "r"(dst), "l"(src), "r"(sz) : "memory");
    }
}

__device__ __forceinline__ void bf_split(float v, __nv_bfloat16& h, __nv_bfloat16& l) {
    h = __float2bfloat16(v);
    l = __float2bfloat16(v - __bfloat162float(h));
}

// fill all 3 tiles for one k-chunk into the given stage buffer, commit once
__device__ __forceinline__ void fill_chunk(uint32_t buf, int bm, int bn, int kc8,
                                           const __nv_bfloat16* __restrict__ Whi) {
    fill_tile_async(buf + 0 * TILE_BYTES, g_ahi, bm * 128, kc8 * 64, N2);
    fill_tile_async(buf + 1 * TILE_BYTES, g_alo, bm * 128, kc8 * 64, N2);
    fill_tile_async(buf + 2 * TILE_BYTES, Whi,   bn * 128, kc8 * 64, 1 << 30);
    CP_COMMIT();
}

// ---- GEMM phase: g_gemm[N2,512] = A @ W  (A = hi+lo bf16, W = bf16) ---------
__device__ void gemm_phase(uint32_t smb, const __nv_bfloat16* __restrict__ Whi) {
    const int tid  = threadIdx.x;
    const int lane = tid & 31, warp = tid >> 5;
    const int wm = warp & 3;        // 32-row group
    const int wn = warp >> 2;       // 64-col group
    const int g  = lane >> 2;       // epilogue row-in-8
    const int tg = lane & 3;        // epilogue col pair
    const int seg = lane >> 3;      // ldmatrix segment 0..3
    const int lr  = lane & 7;

    const int aoff0 = (wm * 32 + 0  + (seg & 1) * 8 + lr) * KSTR + (seg >> 1) * 8;
    const int aoff1 = (wm * 32 + 16 + (seg & 1) * 8 + lr) * KSTR + (seg >> 1) * 8;
    const int boffb = (wn * 64 + (seg & 1) * 8 + lr) * KSTR + (seg >> 1) * 8;

    for (int t = blockIdx.x; t < NTILE; t += NB) {
        const int bm = t >> 2, bn = t & 3;

        float acc[2][8][4];
#pragma unroll
        for (int mt = 0; mt < 2; mt++)
#pragma unroll
            for (int nt = 0; nt < 8; nt++)
#pragma unroll
                for (int q = 0; q < 4; q++) acc[mt][nt][q] = 0.0f;

        // prologue: fill chunks 0,1 into stages 0,1
        fill_chunk(smb + 0 * BUF_BYTES, bm, bn, 0, Whi);
        fill_chunk(smb + 1 * BUF_BYTES, bm, bn, 1, Whi);

#pragma unroll 1
        for (int kc8 = 0; kc8 < 8; kc8++) {
            if (kc8 < 7) { CP_WAIT(1); } else { CP_WAIT(0); }
            __syncthreads();                 // chunk kc8 ready; all threads done with kc8-1
            if (kc8 + 2 < 8)
                fill_chunk(smb + (uint32_t)((kc8 + 2) % 3) * BUF_BYTES, bm, bn, kc8 + 2, Whi);

            const uint32_t cur = smb + (uint32_t)(kc8 % 3) * BUF_BYTES;
            const uint32_t Ahi = cur + 0 * TILE_BYTES;
            const uint32_t Alo = cur + 1 * TILE_BYTES;
            const uint32_t Bhi = cur + 2 * TILE_BYTES;

#pragma unroll
            for (int ks4 = 0; ks4 < 4; ks4++) {
                const uint32_t kb = (uint32_t)(ks4 * 16) * 2;   // bytes

                uint32_t bh[8][2];
#pragma unroll
                for (int nq = 0; nq < 4; nq++) {
                    uint32_t r0, r1, r2, r3;
                    ldsm4(r0, r1, r2, r3, Bhi + (uint32_t)(boffb + nq * 16 * KSTR) * 2 + kb);
                    bh[nq * 2][0] = r0; bh[nq * 2 + 1][0] = r1;
                    bh[nq * 2][1] = r2; bh[nq * 2 + 1][1] = r3;
                }
#pragma unroll
                for (int mt = 0; mt < 2; mt++) {
                    const int aoff = mt ? aoff1 : aoff0;
                    uint32_t ah0, ah1, ah2, ah3, al0, al1, al2, al3;
                    ldsm4(ah0, ah1, ah2, ah3, Ahi + (uint32_t)aoff * 2 + kb);
                    ldsm4(al0, al1, al2, al3, Alo + (uint32_t)aoff * 2 + kb);
#pragma unroll
                    for (int nt = 0; nt < 8; nt++) {
                        mma16816(acc[mt][nt], ah0, ah1, ah2, ah3, bh[nt][0], bh[nt][1]);
                        mma16816(acc[mt][nt], al0, al1, al2, al3, bh[nt][0], bh[nt][1]);
                    }
                }
            }
        }

        // epilogue: fp32 h. frag: c0,c1 at (g, 2tg); c2,c3 at (g+8, 2tg)
#pragma unroll
        for (int mt = 0; mt < 2; mt++) {
            int row0 = bm * 128 + wm * 32 + mt * 16 + g;
#pragma unroll
            for (int nt = 0; nt < 8; nt++) {
                int col = bn * 128 + wn * 64 + nt * 8 + 2 * tg;
                if (row0 < N2)
                    *(float2*)&g_gemm[(size_t)row0 * DH + col] =
                        make_float2(acc[mt][nt][0], acc[mt][nt][1]);
                if (row0 + 8 < N2)
                    *(float2*)&g_gemm[(size_t)(row0 + 8) * DH + col] =
                        make_float2(acc[mt][nt][2], acc[mt][nt][3]);
            }
        }
        __syncthreads();   // last computes used stages 0,1 — next tile's prologue refills them
    }
}

// ---- aggregation over fused node range [0, 2NN); idx prefetch ----------------
#define LOADI8(P, Q, csr, nrm, base)                                          \
    P##0 = csr[(base)];     P##1 = csr[(base) + 1];                           \
    P##2 = csr[(base) + 2]; P##3 = csr[(base) + 3];                           \
    P##4 = csr[(base) + 4]; P##5 = csr[(base) + 5];                           \
    P##6 = csr[(base) + 6]; P##7 = csr[(base) + 7];                           \
    Q##0 = nrm[(base)];     Q##1 = nrm[(base) + 1];                           \
    Q##2 = nrm[(base) + 2]; Q##3 = nrm[(base) + 3];                           \
    Q##4 = nrm[(base) + 4]; Q##5 = nrm[(base) + 5];                           \
    Q##6 = nrm[(base) + 6]; Q##7 = nrm[(base) + 7];

#define GATHER8(P, Q)                                                         \
    {                                                                         \
        float4 v0 = *(const float4*)&h[(size_t)P##0 * DH + t4];               \
        float4 v1 = *(const float4*)&h[(size_t)P##1 * DH + t4];               \
        float4 v2 = *(const float4*)&h[(size_t)P##2 * DH + t4];               \
        float4 v3 = *(const float4*)&h[(size_t)P##3 * DH + t4];               \
        float4 v4 = *(const float4*)&h[(size_t)P##4 * DH + t4];               \
        float4 v5 = *(const float4*)&h[(size_t)P##5 * DH + t4];               \
        float4 v6 = *(const float4*)&h[(size_t)P##6 * DH + t4];               \
        float4 v7 = *(const float4*)&h[(size_t)P##7 * DH + t4];               \
        a0.x += Q##0 * v0.x; a0.y += Q##0 * v0.y; a0.z += Q##0 * v0.z; a0.w += Q##0 * v0.w; \
        a1.x += Q##1 * v1.x; a1.y += Q##1 * v1.y; a1.z += Q##1 * v1.z; a1.w += Q##1 * v1.w; \
        a2.x += Q##2 * v2.x; a2.y += Q##2 * v2.y; a2.z += Q##2 * v2.z; a2.w += Q##2 * v2.w; \
        a3.x += Q##3 * v3.x; a3.y += Q##3 * v3.y; a3.z += Q##3 * v3.z; a3.w += Q##3 * v3.w; \
        a0.x += Q##4 * v4.x; a0.y += Q##4 * v4.y; a0.z += Q##4 * v4.z; a0.w += Q##4 * v4.w; \
        a1.x += Q##5 * v5.x; a1.y += Q##5 * v5.y; a1.z += Q##5 * v5.z; a1.w += Q##5 * v5.w; \
        a2.x += Q##6 * v6.x; a2.y += Q##6 * v6.y; a2.z += Q##6 * v6.z; a2.w += Q##6 * v6.w; \
        a3.x += Q##7 * v7.x; a3.y += Q##7 * v7.y; a3.z += Q##7 * v7.z; a3.w += Q##7 * v7.w; \
    }

__device__ void agg_phase(const float* __restrict__ bias, int l) {
    const int sub = threadIdx.x >> 7;   // 0 or 1
    const int t   = threadIdx.x & 127;  // float4 lane
    const int t4  = t * 4;
    const float4 b4 = *(const float4*)&bias[t4];

    for (int j = blockIdx.x * 2 + sub; j < N2; j += NB * 2) {
        const int enc = (j >= NN);
        const int i   = j - enc * NN;
        const int* __restrict__ csr = g_csr_src[enc];
        const float* __restrict__ nrm = g_csr_norm[enc];
        const float* __restrict__ h = g_gemm + (size_t)enc * NN * DH;

        int r0 = g_rowptr[enc][i];
        int r1 = g_rowptr[enc][i + 1];

        float4 a0 = make_float4(0.f, 0.f, 0.f, 0.f);
        float4 a1 = a0, a2 = a0, a3 = a0;

        int e = r0;
        const int last8 = r1 - 8;
        if (e <= last8) {
            int   p0, p1, p2, p3, p4, p5, p6, p7;
            float q0, q1, q2, q3, q4, q5, q6, q7;
            LOADI8(p, q, csr, nrm, e)
            e += 8;
            while (e <= last8) {
                int   c0, c1, c2, c3, c4, c5, c6, c7;
                float d0, d1, d2, d3, d4, d5, d6, d7;
                LOADI8(c, d, csr, nrm, e)      // prefetch next batch's indices
                GATHER8(p, q)                   // gathers + FMAs for current batch
                p0 = c0; p1 = c1; p2 = c2; p3 = c3;
                p4 = c4; p5 = c5; p6 = c6; p7 = c7;
                q0 = d0; q1 = d1; q2 = d2; q3 = d3;
                q4 = d4; q5 = d5; q6 = d6; q7 = d7;
                e += 8;
            }
            GATHER8(p, q)
        }
        for (; e < r1; e++) {
            int   s = csr[e];
            float w = nrm[e];
            float4 v = *(const float4*)&h[(size_t)s * DH + t4];
            a0.x += w * v.x; a0.y += w * v.y; a0.z += w * v.z; a0.w += w * v.w;
        }

        float4 acc;
        acc.x = (a0.x + a1.x) + (a2.x + a3.x);
        acc.y = (a0.y + a1.y) + (a2.y + a3.y);
        acc.z = (a0.z + a1.z) + (a2.z + a3.z);
        acc.w = (a0.w + a1.w) + (a2.w + a3.w);

        float d = g_dinv[enc][i];
        float wd = d * d;
        float4 vs = *(const float4*)&h[(size_t)i * DH + t4];
        acc.x += wd * vs.x + b4.x;
        acc.y += wd * vs.y + b4.y;
        acc.z += wd * vs.z + b4.z;
        acc.w += wd * vs.w + b4.w;

        if (l < 2) {   // relu + split into bf16 hi/lo for next GEMM
            acc.x = fmaxf(acc.x, 0.f); acc.y = fmaxf(acc.y, 0.f);
            acc.z = fmaxf(acc.z, 0.f); acc.w = fmaxf(acc.w, 0.f);
            __nv_bfloat162 h01, h23, l01, l23;
            bf_split(acc.x, h01.x, l01.x); bf_split(acc.y, h01.y, l01.y);
            bf_split(acc.z, h23.x, l23.x); bf_split(acc.w, h23.y, l23.y);
            __nv_bfloat162* hp = (__nv_bfloat162*)(g_ahi + (size_t)j * DH + t4);
            __nv_bfloat162* lp = (__nv_bfloat162*)(g_alo + (size_t)j * DH + t4);
            hp[0] = h01; hp[1] = h23;
            lp[0] = l01; lp[1] = l23;
        } else {
            *(float4*)&g_x[(size_t)j * DH + t4] = acc;
        }
    }
}

// ---- pool (128 blocks: enc = bid>>6, graph = bid&63) -------------------------
__device__ void pool_phase(const int* __restrict__ batch_a,
                           const int* __restrict__ batch_b) {
    int bid = blockIdx.x;
    if (bid >= 2 * GG) return;
    int enc = bid >> 6;
    int g = bid & 63;
    int t = threadIdx.x;   // float2 lane

    const int* batch = enc ? batch_b : batch_a;
    const float* h = g_x + (size_t)enc * NN * DH;

    int lo = 0, hi = NN;
    while (lo < hi) { int m = (lo + hi) >> 1; if (batch[m] < g) lo = m + 1; else hi = m; }
    int start = lo;
    lo = start; hi = NN;
    while (lo < hi) { int m = (lo + hi) >> 1; if (batch[m] < g + 1) lo = m + 1; else hi = m; }
    int end = lo;

    float2 a0 = make_float2(0.f, 0.f), a1 = a0;
    int r = start;
    for (; r + 1 < end; r += 2) {
        float2 v0 = *(const float2*)&h[(size_t)r * DH + t * 2];
        float2 v1 = *(const float2*)&h[(size_t)(r + 1) * DH + t * 2];
        a0.x += v0.x; a0.y += v0.y;
        a1.x += v1.x; a1.y += v1.y;
    }
    if (r < end) {
        float2 v = *(const float2*)&h[(size_t)r * DH + t * 2];
        a0.x += v.x; a0.y += v.y;
    }
    float inv = 1.0f / fmaxf((float)(end - start), 1.0f);
    *(float2*)&g_pooled[enc][g * DH + t * 2] =
        make_float2((a0.x + a1.x) * inv, (a0.y + a1.y) * inv);
}

__device__ void dist_phase(float* __restrict__ out, float* sred) {
    int g = blockIdx.x;
    if (g >= GG) return;
    int t = threadIdx.x;

    float2 a = *(const float2*)&g_pooled[0][g * DH + t * 2];
    float2 b = *(const float2*)&g_pooled[1][g * DH + t * 2];
    float dx = a.x - b.x + 1e-6f;
    float dy = a.y - b.y + 1e-6f;
    float s = dx * dx + dy * dy;

    sred[t] = s;
    __syncthreads();
    for (int off = 128; off > 0; off >>= 1) {
        if (t < off) sred[t] += sred[t + off];
        __syncthreads();
    }
    if (t == 0) out[g] = sqrtf(sred[0]);
}

// ---- mega kernel --------------------------------------------------------------
extern __shared__ __align__(16) unsigned char smem_dyn[];

__global__ __launch_bounds__(TPB, 1) void mega_kernel(
    const float* __restrict__ x_a, const int* __restrict__ ei_a,
    const int* __restrict__ batch_a,
    const float* __restrict__ x_b, const int* __restrict__ ei_b,
    const int* __restrict__ batch_b,
    const float* __restrict__ W1, const float* __restrict__ b1,
    const float* __restrict__ W2, const float* __restrict__ b2,
    const float* __restrict__ W3, const float* __restrict__ b3,
    float* __restrict__ out)
{
    unsigned char* sm = smem_dyn;
    const uint32_t smb = (uint32_t)__cvta_generic_to_shared(sm);
    const int tid = threadIdx.x, bid = blockIdx.x;
    unsigned target = *((volatile unsigned*)&g_gen);

    // ---- Phase A (combined): W transpose+round, x splits (both), deg counts
    {
        const float* Ws[3] = {W1, W2, W3};
        const int total = 3 * DH * DH;
        for (int idx = bid * TPB + tid; idx < total; idx += NB * TPB) {
            int l = idx >> 18;
            int rem = idx & (DH * DH - 1);
            int k = rem >> 9;
            int n = rem & 511;
            g_whi[l * DH * DH + n * DH + k] = __float2bfloat16(Ws[l][k * DH + n]);
        }
    }
    {
        const int total4 = NN * DH / 4;
        for (int idx = bid * TPB + tid; idx < 2 * total4; idx += NB * TPB) {
            int enc = (idx >= total4);
            int i4  = idx - enc * total4;
            const float* xs = enc ? x_b : x_a;
            float4 v = *(const float4*)(xs + (size_t)i4 * 4);
            __nv_bfloat162 h01, h23, l01, l23;
            bf_split(v.x, h01.x, l01.x); bf_split(v.y, h01.y, l01.y);
            bf_split(v.z, h23.x, l23.x); bf_split(v.w, h23.y, l23.y);
            size_t o4 = (size_t)enc * total4 + i4;
            __nv_bfloat162* hp = (__nv_bfloat162*)(g_ahi + o4 * 4);
            __nv_bfloat162* lp = (__nv_bfloat162*)(g_alo + o4 * 4);
            hp[0] = h01; hp[1] = h23;
            lp[0] = l01; lp[1] = l23;
        }
    }
    for (int e = bid * TPB + tid; e < 2 * EE; e += NB * TPB) {
        int enc = (e >= EE);
        int el  = e - enc * EE;
        const int* dstv = (enc ? ei_b : ei_a) + EE;
        atomicAdd(&g_deg[enc][dstv[el]], 1);
    }
    gsync(++target);

    // ---- Phase B: scans (block 0 -> enc 0, block 1 -> enc 1) ----
    if (bid < 2) {
        const int enc = bid;
        int* sh = (int*)(sm + SM_RED);
        const int chunk = (NN + TPB - 1) / TPB;   // 79
        int base = tid * chunk;
        int local = 0;
        for (int j = 0; j < chunk; j++) {
            int idx = base + j;
            if (idx < NN) local += g_deg[enc][idx];
        }
        sh[tid] = local;
        __syncthreads();
        for (int off = 1; off < TPB; off <<= 1) {
            int v = (tid >= off) ? sh[tid - off] : 0;
            __syncthreads();
            sh[tid] += v;
            __syncthreads();
        }
        int run = tid ? sh[tid - 1] : 0;
        for (int j = 0; j < chunk; j++) {
            int idx = base + j;
            if (idx < NN) {
                int d = g_deg[enc][idx];
                g_deg[enc][idx]    = 0;               // restore invariant
                g_rowptr[enc][idx] = run;
                g_cursor[enc][idx] = run;
                g_dinv[enc][idx]   = rsqrtf((float)d + 1.0f);
                run += d;
            }
        }
        if (tid == TPB - 1) g_rowptr[enc][NN] = sh[TPB - 1];
    }
    gsync(++target);

    // ---- Phase C: fill CSR (both encoders) ----
    for (int e = bid * TPB + tid; e < 2 * EE; e += NB * TPB) {
        int enc = (e >= EE);
        int el  = e - enc * EE;
        const int* srcv = enc ? ei_b : ei_a;
        const int* dstv = srcv + EE;
        int s = srcv[el], d = dstv[el];
        int pos = atomicAdd(&g_cursor[enc][d], 1);
        g_csr_src[enc][pos]  = s;
        g_csr_norm[enc][pos] = g_dinv[enc][s] * g_dinv[enc][d];
    }
    gsync(++target);

    // ---- 3 GCN layers over fused M=40000 ----
    for (int l = 0; l < 3; l++) {
        const float* bb = (l == 0) ? b1 : (l == 1) ? b2 : b3;
        gemm_phase(smb, g_whi + l * DH * DH);
        gsync(++target);
        agg_phase(bb, l);
        gsync(++target);
    }

    // ---- mean pool (both encoders, 128 blocks) ----
    pool_phase(batch_a, batch_b);
    gsync(++target);

    // ---- pairwise distance ----
    dist_phase(out, (float*)(sm + SM_RED));
}

// ---------------------------------------------------------------------------
// launch: ONE kernel (dynamic smem ~163KB)
// ---------------------------------------------------------------------------
extern "C" void kernel_launch(void* const* d_in, const int* in_sizes, int n_in,
                              void* d_out, int out_size) {
    const float* x_a     = (const float*)d_in[0];
    const int*   ei_a    = (const int*)  d_in[1];
    const int*   batch_a = (const int*)  d_in[2];
    const float* x_b     = (const float*)d_in[3];
    const int*   ei_b    = (const int*)  d_in[4];
    const int*   batch_b = (const int*)  d_in[5];
    const float* W1 = (const float*)d_in[6];
    const float* b1 = (const float*)d_in[7];
    const float* W2 = (const float*)d_in[8];
    const float* b2 = (const float*)d_in[9];
    const float* W3 = (const float*)d_in[10];
    const float* b3 = (const float*)d_in[11];
    float* out = (float*)d_out;

    cudaFuncSetAttribute(mega_kernel, cudaFuncAttributeMaxDynamicSharedMemorySize,
                         SMEM_BYTES);
    mega_kernel<<<NB, TPB, SMEM_BYTES>>>(x_a, ei_a, batch_a, x_b, ei_b, batch_b,
                                         W1, b1, W2, b2, W3, b3, out);
}

// round 13
// speedup vs baseline: 1.5319x; 1.1134x over previous
#include <cuda_runtime.h>
#include <cuda_bf16.h>
#include <cstdint>

// ---------------------------------------------------------------------------
// SiameseBrainNet: persistent mega-kernel + mma.sync bf16 GEMM
// R13: single-term bf16 GEMM (A bf16, W bf16 — Alo term dropped; calibrated
//      rel_err ~2e-4). Halves MMA work and GEMM fill traffic vs R12.
//      Everything else identical to R12 (3-stage pipeline, idx-prefetch agg,
//      fused encoders).
// ---------------------------------------------------------------------------

#define NN 20000
#define N2 (2 * NN)           // fused node count
#define EE 640000
#define DH 512
#define GG 64
#define NB 148
#define TPB 256
#define MT 313                // ceil(40000/128)
#define NTILE (4 * MT)        // 1252 output tiles (128x128)

#define KSTR 72               // bf16 elements per smem row (64 data + 8 pad)
#define TILE_BYTES (128 * KSTR * 2)          // 18432
#define BUF_BYTES  (2 * TILE_BYTES)          // 36864 (A, B)
#define SM_RED     (3 * BUF_BYTES)           // 110592 (3-stage)
#define SMEM_BYTES (SM_RED + 1024)           // 111616

// ---- scratch ---------------------------------------------------------------
__device__ float g_gemm[N2 * DH];               // GEMM output h (fp32)
__device__ float g_x[N2 * DH];                  // last-layer agg output
__device__ __nv_bfloat16 g_a[N2 * DH];          // GEMM A operand (bf16)
__device__ __nv_bfloat16 g_whi[3 * DH * DH];    // W^T bf16, [l][n][k]
__device__ int   g_deg[2][NN];     // INVARIANT: zero at kernel entry
__device__ int   g_rowptr[2][NN + 1];
__device__ int   g_cursor[2][NN];
__device__ float g_dinv[2][NN];
__device__ int   g_csr_src[2][EE];
__device__ float g_csr_norm[2][EE];
__device__ float g_pooled[2][GG * DH];
__device__ unsigned g_count, g_gen;

// ---- grid barrier -----------------------------------------------------------
__device__ __forceinline__ void gsync(unsigned target) {
    __syncthreads();
    if (threadIdx.x == 0) {
        __threadfence();
        if (atomicAdd(&g_count, 1u) == NB - 1u) {
            atomicExch(&g_count, 0u);
            __threadfence();
            atomicAdd(&g_gen, 1u);
        } else {
            while (*((volatile unsigned*)&g_gen) < target) __nanosleep(64);
        }
        __threadfence();
    }
    __syncthreads();
}

// ---- tensor-core primitives ---------------------------------------------------
__device__ __forceinline__ void mma16816(float* d,
                                         uint32_t a0, uint32_t a1, uint32_t a2, uint32_t a3,
                                         uint32_t b0, uint32_t b1) {
    asm volatile(
        "mma.sync.aligned.m16n8k16.row.col.f32.bf16.bf16.f32 "
        "{%0,%1,%2,%3}, {%4,%5,%6,%7}, {%8,%9}, {%0,%1,%2,%3};"
        : "+f"(d[0]), "+f"(d[1]), "+f"(d[2]), "+f"(d[3])
        : "r"(a0), "r"(a1), "r"(a2), "r"(a3), "r"(b0), "r"(b1));
}
__device__ __forceinline__ void ldsm4(uint32_t& r0, uint32_t& r1, uint32_t& r2, uint32_t& r3,
                                      uint32_t addr) {
    asm volatile("ldmatrix.sync.aligned.m8n8.x4.shared.b16 {%0,%1,%2,%3}, [%4];"
                 : "=r"(r0), "=r"(r1), "=r"(r2), "=r"(r3) : "r"(addr));
}
#define CP_COMMIT() asm volatile("cp.async.commit_group;" ::: "memory")
#define CP_WAIT(n)  asm volatile("cp.async.wait_group %0;" :: "n"(n) : "memory")

// async fill: gmem bf16 [.,512] -> smem tile 128x64 (stride KSTR)
__device__ __forceinline__ void fill_tile_async(uint32_t smt,
                                                const __nv_bfloat16* __restrict__ g,
                                                int row0, int kc, int nrows) {
    const int tid = threadIdx.x;
#pragma unroll
    for (int i = 0; i < 4; i++) {
        int idx = i * 256 + tid;       // 0..1023
        int r   = idx >> 3;            // 0..127
        int c8  = (idx & 7) << 3;      // 0..56
        int gr  = row0 + r;
        bool valid = (gr < nrows);
        const void* src = g + (size_t)(valid ? gr : 0) * DH + kc + c8;
        uint32_t dst = smt + (uint32_t)(r * KSTR + c8) * 2;
        int sz = valid ? 16 : 0;
        asm volatile("cp.async.cg.shared.global [%0], [%1], 16, %2;"
                     :: "r"(dst), "l"(src), "r"(sz) : "memory");
    }
}

// fill both tiles for one k-chunk into the given stage buffer, commit once
__device__ __forceinline__ void fill_chunk(uint32_t buf, int bm, int bn, int kc8,
                                           const __nv_bfloat16* __restrict__ Whi) {
    fill_tile_async(buf + 0 * TILE_BYTES, g_a,  bm * 128, kc8 * 64, N2);
    fill_tile_async(buf + 1 * TILE_BYTES, Whi,  bn * 128, kc8 * 64, 1 << 30);
    CP_COMMIT();
}

// ---- GEMM phase: g_gemm[N2,512] = A @ W  (A bf16, W bf16, fp32 accum) -------
__device__ void gemm_phase(uint32_t smb, const __nv_bfloat16* __restrict__ Whi) {
    const int tid  = threadIdx.x;
    const int lane = tid & 31, warp = tid >> 5;
    const int wm = warp & 3;        // 32-row group
    const int wn = warp >> 2;       // 64-col group
    const int g  = lane >> 2;       // epilogue row-in-8
    const int tg = lane & 3;        // epilogue col pair
    const int seg = lane >> 3;      // ldmatrix segment 0..3
    const int lr  = lane & 7;

    const int aoff0 = (wm * 32 + 0  + (seg & 1) * 8 + lr) * KSTR + (seg >> 1) * 8;
    const int aoff1 = (wm * 32 + 16 + (seg & 1) * 8 + lr) * KSTR + (seg >> 1) * 8;
    const int boffb = (wn * 64 + (seg & 1) * 8 + lr) * KSTR + (seg >> 1) * 8;

    for (int t = blockIdx.x; t < NTILE; t += NB) {
        const int bm = t >> 2, bn = t & 3;

        float acc[2][8][4];
#pragma unroll
        for (int mt = 0; mt < 2; mt++)
#pragma unroll
            for (int nt = 0; nt < 8; nt++)
#pragma unroll
                for (int q = 0; q < 4; q++) acc[mt][nt][q] = 0.0f;

        // prologue: fill chunks 0,1 into stages 0,1
        fill_chunk(smb + 0 * BUF_BYTES, bm, bn, 0, Whi);
        fill_chunk(smb + 1 * BUF_BYTES, bm, bn, 1, Whi);

#pragma unroll 1
        for (int kc8 = 0; kc8 < 8; kc8++) {
            if (kc8 < 7) { CP_WAIT(1); } else { CP_WAIT(0); }
            __syncthreads();                 // chunk kc8 ready; all threads done with kc8-1
            if (kc8 + 2 < 8)
                fill_chunk(smb + (uint32_t)((kc8 + 2) % 3) * BUF_BYTES, bm, bn, kc8 + 2, Whi);

            const uint32_t cur = smb + (uint32_t)(kc8 % 3) * BUF_BYTES;
            const uint32_t Abuf = cur + 0 * TILE_BYTES;
            const uint32_t Bbuf = cur + 1 * TILE_BYTES;

#pragma unroll
            for (int ks4 = 0; ks4 < 4; ks4++) {
                const uint32_t kb = (uint32_t)(ks4 * 16) * 2;   // bytes

                uint32_t bh[8][2];
#pragma unroll
                for (int nq = 0; nq < 4; nq++) {
                    uint32_t r0, r1, r2, r3;
                    ldsm4(r0, r1, r2, r3, Bbuf + (uint32_t)(boffb + nq * 16 * KSTR) * 2 + kb);
                    bh[nq * 2][0] = r0; bh[nq * 2 + 1][0] = r1;
                    bh[nq * 2][1] = r2; bh[nq * 2 + 1][1] = r3;
                }
#pragma unroll
                for (int mt = 0; mt < 2; mt++) {
                    const int aoff = mt ? aoff1 : aoff0;
                    uint32_t ah0, ah1, ah2, ah3;
                    ldsm4(ah0, ah1, ah2, ah3, Abuf + (uint32_t)aoff * 2 + kb);
#pragma unroll
                    for (int nt = 0; nt < 8; nt++)
                        mma16816(acc[mt][nt], ah0, ah1, ah2, ah3, bh[nt][0], bh[nt][1]);
                }
            }
        }

        // epilogue: fp32 h. frag: c0,c1 at (g, 2tg); c2,c3 at (g+8, 2tg)
#pragma unroll
        for (int mt = 0; mt < 2; mt++) {
            int row0 = bm * 128 + wm * 32 + mt * 16 + g;
#pragma unroll
            for (int nt = 0; nt < 8; nt++) {
                int col = bn * 128 + wn * 64 + nt * 8 + 2 * tg;
                if (row0 < N2)
                    *(float2*)&g_gemm[(size_t)row0 * DH + col] =
                        make_float2(acc[mt][nt][0], acc[mt][nt][1]);
                if (row0 + 8 < N2)
                    *(float2*)&g_gemm[(size_t)(row0 + 8) * DH + col] =
                        make_float2(acc[mt][nt][2], acc[mt][nt][3]);
            }
        }
        __syncthreads();   // stages 0,1 consumed; next tile's prologue refills them
    }
}

// ---- aggregation over fused node range [0, 2NN); idx prefetch ----------------
#define LOADI8(P, Q, csr, nrm, base)                                          \
    P##0 = csr[(base)];     P##1 = csr[(base) + 1];                           \
    P##2 = csr[(base) + 2]; P##3 = csr[(base) + 3];                           \
    P##4 = csr[(base) + 4]; P##5 = csr[(base) + 5];                           \
    P##6 = csr[(base) + 6]; P##7 = csr[(base) + 7];                           \
    Q##0 = nrm[(base)];     Q##1 = nrm[(base) + 1];                           \
    Q##2 = nrm[(base) + 2]; Q##3 = nrm[(base) + 3];                           \
    Q##4 = nrm[(base) + 4]; Q##5 = nrm[(base) + 5];                           \
    Q##6 = nrm[(base) + 6]; Q##7 = nrm[(base) + 7];

#define GATHER8(P, Q)                                                         \
    {                                                                         \
        float4 v0 = *(const float4*)&h[(size_t)P##0 * DH + t4];               \
        float4 v1 = *(const float4*)&h[(size_t)P##1 * DH + t4];               \
        float4 v2 = *(const float4*)&h[(size_t)P##2 * DH + t4];               \
        float4 v3 = *(const float4*)&h[(size_t)P##3 * DH + t4];               \
        float4 v4 = *(const float4*)&h[(size_t)P##4 * DH + t4];               \
        float4 v5 = *(const float4*)&h[(size_t)P##5 * DH + t4];               \
        float4 v6 = *(const float4*)&h[(size_t)P##6 * DH + t4];               \
        float4 v7 = *(const float4*)&h[(size_t)P##7 * DH + t4];               \
        a0.x += Q##0 * v0.x; a0.y += Q##0 * v0.y; a0.z += Q##0 * v0.z; a0.w += Q##0 * v0.w; \
        a1.x += Q##1 * v1.x; a1.y += Q##1 * v1.y; a1.z += Q##1 * v1.z; a1.w += Q##1 * v1.w; \
        a2.x += Q##2 * v2.x; a2.y += Q##2 * v2.y; a2.z += Q##2 * v2.z; a2.w += Q##2 * v2.w; \
        a3.x += Q##3 * v3.x; a3.y += Q##3 * v3.y; a3.z += Q##3 * v3.z; a3.w += Q##3 * v3.w; \
        a0.x += Q##4 * v4.x; a0.y += Q##4 * v4.y; a0.z += Q##4 * v4.z; a0.w += Q##4 * v4.w; \
        a1.x += Q##5 * v5.x; a1.y += Q##5 * v5.y; a1.z += Q##5 * v5.z; a1.w += Q##5 * v5.w; \
        a2.x += Q##6 * v6.x; a2.y += Q##6 * v6.y; a2.z += Q##6 * v6.z; a2.w += Q##6 * v6.w; \
        a3.x += Q##7 * v7.x; a3.y += Q##7 * v7.y; a3.z += Q##7 * v7.z; a3.w += Q##7 * v7.w; \
    }

__device__ void agg_phase(const float* __restrict__ bias, int l) {
    const int sub = threadIdx.x >> 7;   // 0 or 1
    const int t   = threadIdx.x & 127;  // float4 lane
    const int t4  = t * 4;
    const float4 b4 = *(const float4*)&bias[t4];

    for (int j = blockIdx.x * 2 + sub; j < N2; j += NB * 2) {
        const int enc = (j >= NN);
        const int i   = j - enc * NN;
        const int* __restrict__ csr = g_csr_src[enc];
        const float* __restrict__ nrm = g_csr_norm[enc];
        const float* __restrict__ h = g_gemm + (size_t)enc * NN * DH;

        int r0 = g_rowptr[enc][i];
        int r1 = g_rowptr[enc][i + 1];

        float4 a0 = make_float4(0.f, 0.f, 0.f, 0.f);
        float4 a1 = a0, a2 = a0, a3 = a0;

        int e = r0;
        const int last8 = r1 - 8;
        if (e <= last8) {
            int   p0, p1, p2, p3, p4, p5, p6, p7;
            float q0, q1, q2, q3, q4, q5, q6, q7;
            LOADI8(p, q, csr, nrm, e)
            e += 8;
            while (e <= last8) {
                int   c0, c1, c2, c3, c4, c5, c6, c7;
                float d0, d1, d2, d3, d4, d5, d6, d7;
                LOADI8(c, d, csr, nrm, e)      // prefetch next batch's indices
                GATHER8(p, q)                   // gathers + FMAs for current batch
                p0 = c0; p1 = c1; p2 = c2; p3 = c3;
                p4 = c4; p5 = c5; p6 = c6; p7 = c7;
                q0 = d0; q1 = d1; q2 = d2; q3 = d3;
                q4 = d4; q5 = d5; q6 = d6; q7 = d7;
                e += 8;
            }
            GATHER8(p, q)
        }
        for (; e < r1; e++) {
            int   s = csr[e];
            float w = nrm[e];
            float4 v = *(const float4*)&h[(size_t)s * DH + t4];
            a0.x += w * v.x; a0.y += w * v.y; a0.z += w * v.z; a0.w += w * v.w;
        }

        float4 acc;
        acc.x = (a0.x + a1.x) + (a2.x + a3.x);
        acc.y = (a0.y + a1.y) + (a2.y + a3.y);
        acc.z = (a0.z + a1.z) + (a2.z + a3.z);
        acc.w = (a0.w + a1.w) + (a2.w + a3.w);

        float d = g_dinv[enc][i];
        float wd = d * d;
        float4 vs = *(const float4*)&h[(size_t)i * DH + t4];
        acc.x += wd * vs.x + b4.x;
        acc.y += wd * vs.y + b4.y;
        acc.z += wd * vs.z + b4.z;
        acc.w += wd * vs.w + b4.w;

        if (l < 2) {   // relu + round to bf16 for next GEMM
            acc.x = fmaxf(acc.x, 0.f); acc.y = fmaxf(acc.y, 0.f);
            acc.z = fmaxf(acc.z, 0.f); acc.w = fmaxf(acc.w, 0.f);
            __nv_bfloat162 h01, h23;
            h01.x = __float2bfloat16(acc.x); h01.y = __float2bfloat16(acc.y);
            h23.x = __float2bfloat16(acc.z); h23.y = __float2bfloat16(acc.w);
            __nv_bfloat162* hp = (__nv_bfloat162*)(g_a + (size_t)j * DH + t4);
            hp[0] = h01; hp[1] = h23;
        } else {
            *(float4*)&g_x[(size_t)j * DH + t4] = acc;
        }
    }
}

// ---- pool (128 blocks: enc = bid>>6, graph = bid&63) -------------------------
__device__ void pool_phase(const int* __restrict__ batch_a,
                           const int* __restrict__ batch_b) {
    int bid = blockIdx.x;
    if (bid >= 2 * GG) return;
    int enc = bid >> 6;
    int g = bid & 63;
    int t = threadIdx.x;   // float2 lane

    const int* batch = enc ? batch_b : batch_a;
    const float* h = g_x + (size_t)enc * NN * DH;

    int lo = 0, hi = NN;
    while (lo < hi) { int m = (lo + hi) >> 1; if (batch[m] < g) lo = m + 1; else hi = m; }
    int start = lo;
    lo = start; hi = NN;
    while (lo < hi) { int m = (lo + hi) >> 1; if (batch[m] < g + 1) lo = m + 1; else hi = m; }
    int end = lo;

    float2 a0 = make_float2(0.f, 0.f), a1 = a0;
    int r = start;
    for (; r + 1 < end; r += 2) {
        float2 v0 = *(const float2*)&h[(size_t)r * DH + t * 2];
        float2 v1 = *(const float2*)&h[(size_t)(r + 1) * DH + t * 2];
        a0.x += v0.x; a0.y += v0.y;
        a1.x += v1.x; a1.y += v1.y;
    }
    if (r < end) {
        float2 v = *(const float2*)&h[(size_t)r * DH + t * 2];
        a0.x += v.x; a0.y += v.y;
    }
    float inv = 1.0f / fmaxf((float)(end - start), 1.0f);
    *(float2*)&g_pooled[enc][g * DH + t * 2] =
        make_float2((a0.x + a1.x) * inv, (a0.y + a1.y) * inv);
}

__device__ void dist_phase(float* __restrict__ out, float* sred) {
    int g = blockIdx.x;
    if (g >= GG) return;
    int t = threadIdx.x;

    float2 a = *(const float2*)&g_pooled[0][g * DH + t * 2];
    float2 b = *(const float2*)&g_pooled[1][g * DH + t * 2];
    float dx = a.x - b.x + 1e-6f;
    float dy = a.y - b.y + 1e-6f;
    float s = dx * dx + dy * dy;

    sred[t] = s;
    __syncthreads();
    for (int off = 128; off > 0; off >>= 1) {
        if (t < off) sred[t] += sred[t + off];
        __syncthreads();
    }
    if (t == 0) out[g] = sqrtf(sred[0]);
}

// ---- mega kernel --------------------------------------------------------------
extern __shared__ __align__(16) unsigned char smem_dyn[];

__global__ __launch_bounds__(TPB, 1) void mega_kernel(
    const float* __restrict__ x_a, const int* __restrict__ ei_a,
    const int* __restrict__ batch_a,
    const float* __restrict__ x_b, const int* __restrict__ ei_b,
    const int* __restrict__ batch_b,
    const float* __restrict__ W1, const float* __restrict__ b1,
    const float* __restrict__ W2, const float* __restrict__ b2,
    const float* __restrict__ W3, const float* __restrict__ b3,
    float* __restrict__ out)
{
    unsigned char* sm = smem_dyn;
    const uint32_t smb = (uint32_t)__cvta_generic_to_shared(sm);
    const int tid = threadIdx.x, bid = blockIdx.x;
    unsigned target = *((volatile unsigned*)&g_gen);

    // ---- Phase A (combined): W transpose+round, x rounds (both), deg counts
    {
        const float* Ws[3] = {W1, W2, W3};
        const int total = 3 * DH * DH;
        for (int idx = bid * TPB + tid; idx < total; idx += NB * TPB) {
            int l = idx >> 18;
            int rem = idx & (DH * DH - 1);
            int k = rem >> 9;
            int n = rem & 511;
            g_whi[l * DH * DH + n * DH + k] = __float2bfloat16(Ws[l][k * DH + n]);
        }
    }
    {
        const int total4 = NN * DH / 4;
        for (int idx = bid * TPB + tid; idx < 2 * total4; idx += NB * TPB) {
            int enc = (idx >= total4);
            int i4  = idx - enc * total4;
            const float* xs = enc ? x_b : x_a;
            float4 v = *(const float4*)(xs + (size_t)i4 * 4);
            __nv_bfloat162 h01, h23;
            h01.x = __float2bfloat16(v.x); h01.y = __float2bfloat16(v.y);
            h23.x = __float2bfloat16(v.z); h23.y = __float2bfloat16(v.w);
            size_t o4 = (size_t)enc * total4 + i4;
            __nv_bfloat162* hp = (__nv_bfloat162*)(g_a + o4 * 4);
            hp[0] = h01; hp[1] = h23;
        }
    }
    for (int e = bid * TPB + tid; e < 2 * EE; e += NB * TPB) {
        int enc = (e >= EE);
        int el  = e - enc * EE;
        const int* dstv = (enc ? ei_b : ei_a) + EE;
        atomicAdd(&g_deg[enc][dstv[el]], 1);
    }
    gsync(++target);

    // ---- Phase B: scans (block 0 -> enc 0, block 1 -> enc 1) ----
    if (bid < 2) {
        const int enc = bid;
        int* sh = (int*)(sm + SM_RED);
        const int chunk = (NN + TPB - 1) / TPB;   // 79
        int base = tid * chunk;
        int local = 0;
        for (int j = 0; j < chunk; j++) {
            int idx = base + j;
            if (idx < NN) local += g_deg[enc][idx];
        }
        sh[tid] = local;
        __syncthreads();
        for (int off = 1; off < TPB; off <<= 1) {
            int v = (tid >= off) ? sh[tid - off] : 0;
            __syncthreads();
            sh[tid] += v;
            __syncthreads();
        }
        int run = tid ? sh[tid - 1] : 0;
        for (int j = 0; j < chunk; j++) {
            int idx = base + j;
            if (idx < NN) {
                int d = g_deg[enc][idx];
                g_deg[enc][idx]    = 0;               // restore invariant
                g_rowptr[enc][idx] = run;
                g_cursor[enc][idx] = run;
                g_dinv[enc][idx]   = rsqrtf((float)d + 1.0f);
                run += d;
            }
        }
        if (tid == TPB - 1) g_rowptr[enc][NN] = sh[TPB - 1];
    }
    gsync(++target);

    // ---- Phase C: fill CSR (both encoders) ----
    for (int e = bid * TPB + tid; e < 2 * EE; e += NB * TPB) {
        int enc = (e >= EE);
        int el  = e - enc * EE;
        const int* srcv = enc ? ei_b : ei_a;
        const int* dstv = srcv + EE;
        int s = srcv[el], d = dstv[el];
        int pos = atomicAdd(&g_cursor[enc][d], 1);
        g_csr_src[enc][pos]  = s;
        g_csr_norm[enc][pos] = g_dinv[enc][s] * g_dinv[enc][d];
    }
    gsync(++target);

    // ---- 3 GCN layers over fused M=40000 ----
    for (int l = 0; l < 3; l++) {
        const float* bb = (l == 0) ? b1 : (l == 1) ? b2 : b3;
        gemm_phase(smb, g_whi + l * DH * DH);
        gsync(++target);
        agg_phase(bb, l);
        gsync(++target);
    }

    // ---- mean pool (both encoders, 128 blocks) ----
    pool_phase(batch_a, batch_b);
    gsync(++target);

    // ---- pairwise distance ----
    dist_phase(out, (float*)(sm + SM_RED));
}

// ---------------------------------------------------------------------------
// launch: ONE kernel (dynamic smem ~109KB)
// ---------------------------------------------------------------------------
extern "C" void kernel_launch(void* const* d_in, const int* in_sizes, int n_in,
                              void* d_out, int out_size) {
    const float* x_a     = (const float*)d_in[0];
    const int*   ei_a    = (const int*)  d_in[1];
    const int*   batch_a = (const int*)  d_in[2];
    const float* x_b     = (const float*)d_in[3];
    const int*   ei_b    = (const int*)  d_in[4];
    const int*   batch_b = (const int*)  d_in[5];
    const float* W1 = (const float*)d_in[6];
    const float* b1 = (const float*)d_in[7];
    const float* W2 = (const float*)d_in[8];
    const float* b2 = (const float*)d_in[9];
    const float* W3 = (const float*)d_in[10];
    const float* b3 = (const float*)d_in[11];
    float* out = (float*)d_out;

    cudaFuncSetAttribute(mega_kernel, cudaFuncAttributeMaxDynamicSharedMemorySize,
                         SMEM_BYTES);
    mega_kernel<<<NB, TPB, SMEM_BYTES>>>(x_a, ei_a, batch_a, x_b, ei_b, batch_b,
                                         W1, b1, W2, b2, W3, b3, out);
}

// round 14
// speedup vs baseline: 2.1042x; 1.3735x over previous
#include <cuda_runtime.h>
#include <cuda_bf16.h>
#include <cstdint>

// ---------------------------------------------------------------------------
// SiameseBrainNet: persistent mega-kernel + mma.sync bf16 GEMM
// R14: R13 + 2 CTAs/SM (NB=296, launch_bounds(256,2)) — 16 warps/SM with
//      unchanged per-warp GEMM shape; CTA-level fill/compute overlap; double
//      the in-flight agg gathers. smem 109KB x2 fits the 227KB carveout.
// ---------------------------------------------------------------------------

#define NN 20000
#define N2 (2 * NN)           // fused node count
#define EE 640000
#define DH 512
#define GG 64
#define NB 296                // 2 CTAs per SM (148 SMs; 152 on GB300 also ok)
#define TPB 256
#define MT 313                // ceil(40000/128)
#define NTILE (4 * MT)        // 1252 output tiles (128x128)

#define KSTR 72               // bf16 elements per smem row (64 data + 8 pad)
#define TILE_BYTES (128 * KSTR * 2)          // 18432
#define BUF_BYTES  (2 * TILE_BYTES)          // 36864 (A, B)
#define SM_RED     (3 * BUF_BYTES)           // 110592 (3-stage)
#define SMEM_BYTES (SM_RED + 1024)           // 111616 (x2 = 223232 <= 227KB)

// ---- scratch ---------------------------------------------------------------
__device__ float g_gemm[N2 * DH];               // GEMM output h (fp32)
__device__ float g_x[N2 * DH];                  // last-layer agg output
__device__ __nv_bfloat16 g_a[N2 * DH];          // GEMM A operand (bf16)
__device__ __nv_bfloat16 g_whi[3 * DH * DH];    // W^T bf16, [l][n][k]
__device__ int   g_deg[2][NN];     // INVARIANT: zero at kernel entry
__device__ int   g_rowptr[2][NN + 1];
__device__ int   g_cursor[2][NN];
__device__ float g_dinv[2][NN];
__device__ int   g_csr_src[2][EE];
__device__ float g_csr_norm[2][EE];
__device__ float g_pooled[2][GG * DH];
__device__ unsigned g_count, g_gen;

// ---- grid barrier -----------------------------------------------------------
__device__ __forceinline__ void gsync(unsigned target) {
    __syncthreads();
    if (threadIdx.x == 0) {
        __threadfence();
        if (atomicAdd(&g_count, 1u) == NB - 1u) {
            atomicExch(&g_count, 0u);
            __threadfence();
            atomicAdd(&g_gen, 1u);
        } else {
            while (*((volatile unsigned*)&g_gen) < target) __nanosleep(64);
        }
        __threadfence();
    }
    __syncthreads();
}

// ---- tensor-core primitives ---------------------------------------------------
__device__ __forceinline__ void mma16816(float* d,
                                         uint32_t a0, uint32_t a1, uint32_t a2, uint32_t a3,
                                         uint32_t b0, uint32_t b1) {
    asm volatile(
        "mma.sync.aligned.m16n8k16.row.col.f32.bf16.bf16.f32 "
        "{%0,%1,%2,%3}, {%4,%5,%6,%7}, {%8,%9}, {%0,%1,%2,%3};"
        : "+f"(d[0]), "+f"(d[1]), "+f"(d[2]), "+f"(d[3])
        : "r"(a0), "r"(a1), "r"(a2), "r"(a3), "r"(b0), "r"(b1));
}
__device__ __forceinline__ void ldsm4(uint32_t& r0, uint32_t& r1, uint32_t& r2, uint32_t& r3,
                                      uint32_t addr) {
    asm volatile("ldmatrix.sync.aligned.m8n8.x4.shared.b16 {%0,%1,%2,%3}, [%4];"
                 : "=r"(r0), "=r"(r1), "=r"(r2), "=r"(r3) : "r"(addr));
}
#define CP_COMMIT() asm volatile("cp.async.commit_group;" ::: "memory")
#define CP_WAIT(n)  asm volatile("cp.async.wait_group %0;" :: "n"(n) : "memory")

// async fill: gmem bf16 [.,512] -> smem tile 128x64 (stride KSTR)
__device__ __forceinline__ void fill_tile_async(uint32_t smt,
                                                const __nv_bfloat16* __restrict__ g,
                                                int row0, int kc, int nrows) {
    const int tid = threadIdx.x;
#pragma unroll
    for (int i = 0; i < 4; i++) {
        int idx = i * 256 + tid;       // 0..1023
        int r   = idx >> 3;            // 0..127
        int c8  = (idx & 7) << 3;      // 0..56
        int gr  = row0 + r;
        bool valid = (gr < nrows);
        const void* src = g + (size_t)(valid ? gr : 0) * DH + kc + c8;
        uint32_t dst = smt + (uint32_t)(r * KSTR + c8) * 2;
        int sz = valid ? 16 : 0;
        asm volatile("cp.async.cg.shared.global [%0], [%1], 16, %2;"
                     :: "r"(dst), "l"(src), "r"(sz) : "memory");
    }
}

// fill both tiles for one k-chunk into the given stage buffer, commit once
__device__ __forceinline__ void fill_chunk(uint32_t buf, int bm, int bn, int kc8,
                                           const __nv_bfloat16* __restrict__ Whi) {
    fill_tile_async(buf + 0 * TILE_BYTES, g_a,  bm * 128, kc8 * 64, N2);
    fill_tile_async(buf + 1 * TILE_BYTES, Whi,  bn * 128, kc8 * 64, 1 << 30);
    CP_COMMIT();
}

// ---- GEMM phase: g_gemm[N2,512] = A @ W  (A bf16, W bf16, fp32 accum) -------
__device__ void gemm_phase(uint32_t smb, const __nv_bfloat16* __restrict__ Whi) {
    const int tid  = threadIdx.x;
    const int lane = tid & 31, warp = tid >> 5;
    const int wm = warp & 3;        // 32-row group
    const int wn = warp >> 2;       // 64-col group
    const int g  = lane >> 2;       // epilogue row-in-8
    const int tg = lane & 3;        // epilogue col pair
    const int seg = lane >> 3;      // ldmatrix segment 0..3
    const int lr  = lane & 7;

    const int aoff0 = (wm * 32 + 0  + (seg & 1) * 8 + lr) * KSTR + (seg >> 1) * 8;
    const int aoff1 = (wm * 32 + 16 + (seg & 1) * 8 + lr) * KSTR + (seg >> 1) * 8;
    const int boffb = (wn * 64 + (seg & 1) * 8 + lr) * KSTR + (seg >> 1) * 8;

    for (int t = blockIdx.x; t < NTILE; t += NB) {
        const int bm = t >> 2, bn = t & 3;

        float acc[2][8][4];
#pragma unroll
        for (int mt = 0; mt < 2; mt++)
#pragma unroll
            for (int nt = 0; nt < 8; nt++)
#pragma unroll
                for (int q = 0; q < 4; q++) acc[mt][nt][q] = 0.0f;

        // prologue: fill chunks 0,1 into stages 0,1
        fill_chunk(smb + 0 * BUF_BYTES, bm, bn, 0, Whi);
        fill_chunk(smb + 1 * BUF_BYTES, bm, bn, 1, Whi);

#pragma unroll 1
        for (int kc8 = 0; kc8 < 8; kc8++) {
            if (kc8 < 7) { CP_WAIT(1); } else { CP_WAIT(0); }
            __syncthreads();                 // chunk kc8 ready; all threads done with kc8-1
            if (kc8 + 2 < 8)
                fill_chunk(smb + (uint32_t)((kc8 + 2) % 3) * BUF_BYTES, bm, bn, kc8 + 2, Whi);

            const uint32_t cur = smb + (uint32_t)(kc8 % 3) * BUF_BYTES;
            const uint32_t Abuf = cur + 0 * TILE_BYTES;
            const uint32_t Bbuf = cur + 1 * TILE_BYTES;

#pragma unroll
            for (int ks4 = 0; ks4 < 4; ks4++) {
                const uint32_t kb = (uint32_t)(ks4 * 16) * 2;   // bytes

                uint32_t bh[8][2];
#pragma unroll
                for (int nq = 0; nq < 4; nq++) {
                    uint32_t r0, r1, r2, r3;
                    ldsm4(r0, r1, r2, r3, Bbuf + (uint32_t)(boffb + nq * 16 * KSTR) * 2 + kb);
                    bh[nq * 2][0] = r0; bh[nq * 2 + 1][0] = r1;
                    bh[nq * 2][1] = r2; bh[nq * 2 + 1][1] = r3;
                }
#pragma unroll
                for (int mt = 0; mt < 2; mt++) {
                    const int aoff = mt ? aoff1 : aoff0;
                    uint32_t ah0, ah1, ah2, ah3;
                    ldsm4(ah0, ah1, ah2, ah3, Abuf + (uint32_t)aoff * 2 + kb);
#pragma unroll
                    for (int nt = 0; nt < 8; nt++)
                        mma16816(acc[mt][nt], ah0, ah1, ah2, ah3, bh[nt][0], bh[nt][1]);
                }
            }
        }

        // epilogue: fp32 h. frag: c0,c1 at (g, 2tg); c2,c3 at (g+8, 2tg)
#pragma unroll
        for (int mt = 0; mt < 2; mt++) {
            int row0 = bm * 128 + wm * 32 + mt * 16 + g;
#pragma unroll
            for (int nt = 0; nt < 8; nt++) {
                int col = bn * 128 + wn * 64 + nt * 8 + 2 * tg;
                if (row0 < N2)
                    *(float2*)&g_gemm[(size_t)row0 * DH + col] =
                        make_float2(acc[mt][nt][0], acc[mt][nt][1]);
                if (row0 + 8 < N2)
                    *(float2*)&g_gemm[(size_t)(row0 + 8) * DH + col] =
                        make_float2(acc[mt][nt][2], acc[mt][nt][3]);
            }
        }
        __syncthreads();   // stages 0,1 consumed; next tile's prologue refills them
    }
}

// ---- aggregation over fused node range [0, 2NN); idx prefetch ----------------
#define LOADI8(P, Q, csr, nrm, base)                                          \
    P##0 = csr[(base)];     P##1 = csr[(base) + 1];                           \
    P##2 = csr[(base) + 2]; P##3 = csr[(base) + 3];                           \
    P##4 = csr[(base) + 4]; P##5 = csr[(base) + 5];                           \
    P##6 = csr[(base) + 6]; P##7 = csr[(base) + 7];                           \
    Q##0 = nrm[(base)];     Q##1 = nrm[(base) + 1];                           \
    Q##2 = nrm[(base) + 2]; Q##3 = nrm[(base) + 3];                           \
    Q##4 = nrm[(base) + 4]; Q##5 = nrm[(base) + 5];                           \
    Q##6 = nrm[(base) + 6]; Q##7 = nrm[(base) + 7];

#define GATHER8(P, Q)                                                         \
    {                                                                         \
        float4 v0 = *(const float4*)&h[(size_t)P##0 * DH + t4];               \
        float4 v1 = *(const float4*)&h[(size_t)P##1 * DH + t4];               \
        float4 v2 = *(const float4*)&h[(size_t)P##2 * DH + t4];               \
        float4 v3 = *(const float4*)&h[(size_t)P##3 * DH + t4];               \
        float4 v4 = *(const float4*)&h[(size_t)P##4 * DH + t4];               \
        float4 v5 = *(const float4*)&h[(size_t)P##5 * DH + t4];               \
        float4 v6 = *(const float4*)&h[(size_t)P##6 * DH + t4];               \
        float4 v7 = *(const float4*)&h[(size_t)P##7 * DH + t4];               \
        a0.x += Q##0 * v0.x; a0.y += Q##0 * v0.y; a0.z += Q##0 * v0.z; a0.w += Q##0 * v0.w; \
        a1.x += Q##1 * v1.x; a1.y += Q##1 * v1.y; a1.z += Q##1 * v1.z; a1.w += Q##1 * v1.w; \
        a2.x += Q##2 * v2.x; a2.y += Q##2 * v2.y; a2.z += Q##2 * v2.z; a2.w += Q##2 * v2.w; \
        a3.x += Q##3 * v3.x; a3.y += Q##3 * v3.y; a3.z += Q##3 * v3.z; a3.w += Q##3 * v3.w; \
        a0.x += Q##4 * v4.x; a0.y += Q##4 * v4.y; a0.z += Q##4 * v4.z; a0.w += Q##4 * v4.w; \
        a1.x += Q##5 * v5.x; a1.y += Q##5 * v5.y; a1.z += Q##5 * v5.z; a1.w += Q##5 * v5.w; \
        a2.x += Q##6 * v6.x; a2.y += Q##6 * v6.y; a2.z += Q##6 * v6.z; a2.w += Q##6 * v6.w; \
        a3.x += Q##7 * v7.x; a3.y += Q##7 * v7.y; a3.z += Q##7 * v7.z; a3.w += Q##7 * v7.w; \
    }

__device__ void agg_phase(const float* __restrict__ bias, int l) {
    const int sub = threadIdx.x >> 7;   // 0 or 1
    const int t   = threadIdx.x & 127;  // float4 lane
    const int t4  = t * 4;
    const float4 b4 = *(const float4*)&bias[t4];

    for (int j = blockIdx.x * 2 + sub; j < N2; j += NB * 2) {
        const int enc = (j >= NN);
        const int i   = j - enc * NN;
        const int* __restrict__ csr = g_csr_src[enc];
        const float* __restrict__ nrm = g_csr_norm[enc];
        const float* __restrict__ h = g_gemm + (size_t)enc * NN * DH;

        int r0 = g_rowptr[enc][i];
        int r1 = g_rowptr[enc][i + 1];

        float4 a0 = make_float4(0.f, 0.f, 0.f, 0.f);
        float4 a1 = a0, a2 = a0, a3 = a0;

        int e = r0;
        const int last8 = r1 - 8;
        if (e <= last8) {
            int   p0, p1, p2, p3, p4, p5, p6, p7;
            float q0, q1, q2, q3, q4, q5, q6, q7;
            LOADI8(p, q, csr, nrm, e)
            e += 8;
            while (e <= last8) {
                int   c0, c1, c2, c3, c4, c5, c6, c7;
                float d0, d1, d2, d3, d4, d5, d6, d7;
                LOADI8(c, d, csr, nrm, e)      // prefetch next batch's indices
                GATHER8(p, q)                   // gathers + FMAs for current batch
                p0 = c0; p1 = c1; p2 = c2; p3 = c3;
                p4 = c4; p5 = c5; p6 = c6; p7 = c7;
                q0 = d0; q1 = d1; q2 = d2; q3 = d3;
                q4 = d4; q5 = d5; q6 = d6; q7 = d7;
                e += 8;
            }
            GATHER8(p, q)
        }
        for (; e < r1; e++) {
            int   s = csr[e];
            float w = nrm[e];
            float4 v = *(const float4*)&h[(size_t)s * DH + t4];
            a0.x += w * v.x; a0.y += w * v.y; a0.z += w * v.z; a0.w += w * v.w;
        }

        float4 acc;
        acc.x = (a0.x + a1.x) + (a2.x + a3.x);
        acc.y = (a0.y + a1.y) + (a2.y + a3.y);
        acc.z = (a0.z + a1.z) + (a2.z + a3.z);
        acc.w = (a0.w + a1.w) + (a2.w + a3.w);

        float d = g_dinv[enc][i];
        float wd = d * d;
        float4 vs = *(const float4*)&h[(size_t)i * DH + t4];
        acc.x += wd * vs.x + b4.x;
        acc.y += wd * vs.y + b4.y;
        acc.z += wd * vs.z + b4.z;
        acc.w += wd * vs.w + b4.w;

        if (l < 2) {   // relu + round to bf16 for next GEMM
            acc.x = fmaxf(acc.x, 0.f); acc.y = fmaxf(acc.y, 0.f);
            acc.z = fmaxf(acc.z, 0.f); acc.w = fmaxf(acc.w, 0.f);
            __nv_bfloat162 h01, h23;
            h01.x = __float2bfloat16(acc.x); h01.y = __float2bfloat16(acc.y);
            h23.x = __float2bfloat16(acc.z); h23.y = __float2bfloat16(acc.w);
            __nv_bfloat162* hp = (__nv_bfloat162*)(g_a + (size_t)j * DH + t4);
            hp[0] = h01; hp[1] = h23;
        } else {
            *(float4*)&g_x[(size_t)j * DH + t4] = acc;
        }
    }
}

// ---- pool (128 blocks: enc = bid>>6, graph = bid&63) -------------------------
__device__ void pool_phase(const int* __restrict__ batch_a,
                           const int* __restrict__ batch_b) {
    int bid = blockIdx.x;
    if (bid >= 2 * GG) return;
    int enc = bid >> 6;
    int g = bid & 63;
    int t = threadIdx.x;   // float2 lane

    const int* batch = enc ? batch_b : batch_a;
    const float* h = g_x + (size_t)enc * NN * DH;

    int lo = 0, hi = NN;
    while (lo < hi) { int m = (lo + hi) >> 1; if (batch[m] < g) lo = m + 1; else hi = m; }
    int start = lo;
    lo = start; hi = NN;
    while (lo < hi) { int m = (lo + hi) >> 1; if (batch[m] < g + 1) lo = m + 1; else hi = m; }
    int end = lo;

    float2 a0 = make_float2(0.f, 0.f), a1 = a0;
    int r = start;
    for (; r + 1 < end; r += 2) {
        float2 v0 = *(const float2*)&h[(size_t)r * DH + t * 2];
        float2 v1 = *(const float2*)&h[(size_t)(r + 1) * DH + t * 2];
        a0.x += v0.x; a0.y += v0.y;
        a1.x += v1.x; a1.y += v1.y;
    }
    if (r < end) {
        float2 v = *(const float2*)&h[(size_t)r * DH + t * 2];
        a0.x += v.x; a0.y += v.y;
    }
    float inv = 1.0f / fmaxf((float)(end - start), 1.0f);
    *(float2*)&g_pooled[enc][g * DH + t * 2] =
        make_float2((a0.x + a1.x) * inv, (a0.y + a1.y) * inv);
}

__device__ void dist_phase(float* __restrict__ out, float* sred) {
    int g = blockIdx.x;
    if (g >= GG) return;
    int t = threadIdx.x;

    float2 a = *(const float2*)&g_pooled[0][g * DH + t * 2];
    float2 b = *(const float2*)&g_pooled[1][g * DH + t * 2];
    float dx = a.x - b.x + 1e-6f;
    float dy = a.y - b.y + 1e-6f;
    float s = dx * dx + dy * dy;

    sred[t] = s;
    __syncthreads();
    for (int off = 128; off > 0; off >>= 1) {
        if (t < off) sred[t] += sred[t + off];
        __syncthreads();
    }
    if (t == 0) out[g] = sqrtf(sred[0]);
}

// ---- mega kernel --------------------------------------------------------------
extern __shared__ __align__(16) unsigned char smem_dyn[];

__global__ __launch_bounds__(TPB, 2) void mega_kernel(
    const float* __restrict__ x_a, const int* __restrict__ ei_a,
    const int* __restrict__ batch_a,
    const float* __restrict__ x_b, const int* __restrict__ ei_b,
    const int* __restrict__ batch_b,
    const float* __restrict__ W1, const float* __restrict__ b1,
    const float* __restrict__ W2, const float* __restrict__ b2,
    const float* __restrict__ W3, const float* __restrict__ b3,
    float* __restrict__ out)
{
    unsigned char* sm = smem_dyn;
    const uint32_t smb = (uint32_t)__cvta_generic_to_shared(sm);
    const int tid = threadIdx.x, bid = blockIdx.x;
    unsigned target = *((volatile unsigned*)&g_gen);

    // ---- Phase A (combined): W transpose+round, x rounds (both), deg counts
    {
        const float* Ws[3] = {W1, W2, W3};
        const int total = 3 * DH * DH;
        for (int idx = bid * TPB + tid; idx < total; idx += NB * TPB) {
            int l = idx >> 18;
            int rem = idx & (DH * DH - 1);
            int k = rem >> 9;
            int n = rem & 511;
            g_whi[l * DH * DH + n * DH + k] = __float2bfloat16(Ws[l][k * DH + n]);
        }
    }
    {
        const int total4 = NN * DH / 4;
        for (int idx = bid * TPB + tid; idx < 2 * total4; idx += NB * TPB) {
            int enc = (idx >= total4);
            int i4  = idx - enc * total4;
            const float* xs = enc ? x_b : x_a;
            float4 v = *(const float4*)(xs + (size_t)i4 * 4);
            __nv_bfloat162 h01, h23;
            h01.x = __float2bfloat16(v.x); h01.y = __float2bfloat16(v.y);
            h23.x = __float2bfloat16(v.z); h23.y = __float2bfloat16(v.w);
            size_t o4 = (size_t)enc * total4 + i4;
            __nv_bfloat162* hp = (__nv_bfloat162*)(g_a + o4 * 4);
            hp[0] = h01; hp[1] = h23;
        }
    }
    for (int e = bid * TPB + tid; e < 2 * EE; e += NB * TPB) {
        int enc = (e >= EE);
        int el  = e - enc * EE;
        const int* dstv = (enc ? ei_b : ei_a) + EE;
        atomicAdd(&g_deg[enc][dstv[el]], 1);
    }
    gsync(++target);

    // ---- Phase B: scans (block 0 -> enc 0, block 1 -> enc 1) ----
    if (bid < 2) {
        const int enc = bid;
        int* sh = (int*)(sm + SM_RED);
        const int chunk = (NN + TPB - 1) / TPB;   // 79
        int base = tid * chunk;
        int local = 0;
        for (int j = 0; j < chunk; j++) {
            int idx = base + j;
            if (idx < NN) local += g_deg[enc][idx];
        }
        sh[tid] = local;
        __syncthreads();
        for (int off = 1; off < TPB; off <<= 1) {
            int v = (tid >= off) ? sh[tid - off] : 0;
            __syncthreads();
            sh[tid] += v;
            __syncthreads();
        }
        int run = tid ? sh[tid - 1] : 0;
        for (int j = 0; j < chunk; j++) {
            int idx = base + j;
            if (idx < NN) {
                int d = g_deg[enc][idx];
                g_deg[enc][idx]    = 0;               // restore invariant
                g_rowptr[enc][idx] = run;
                g_cursor[enc][idx] = run;
                g_dinv[enc][idx]   = rsqrtf((float)d + 1.0f);
                run += d;
            }
        }
        if (tid == TPB - 1) g_rowptr[enc][NN] = sh[TPB - 1];
    }
    gsync(++target);

    // ---- Phase C: fill CSR (both encoders) ----
    for (int e = bid * TPB + tid; e < 2 * EE; e += NB * TPB) {
        int enc = (e >= EE);
        int el  = e - enc * EE;
        const int* srcv = enc ? ei_b : ei_a;
        const int* dstv = srcv + EE;
        int s = srcv[el], d = dstv[el];
        int pos = atomicAdd(&g_cursor[enc][d], 1);
        g_csr_src[enc][pos]  = s;
        g_csr_norm[enc][pos] = g_dinv[enc][s] * g_dinv[enc][d];
    }
    gsync(++target);

    // ---- 3 GCN layers over fused M=40000 ----
    for (int l = 0; l < 3; l++) {
        const float* bb = (l == 0) ? b1 : (l == 1) ? b2 : b3;
        gemm_phase(smb, g_whi + l * DH * DH);
        gsync(++target);
        agg_phase(bb, l);
        gsync(++target);
    }

    // ---- mean pool (both encoders, 128 blocks) ----
    pool_phase(batch_a, batch_b);
    gsync(++target);

    // ---- pairwise distance ----
    dist_phase(out, (float*)(sm + SM_RED));
}

// ---------------------------------------------------------------------------
// launch: ONE kernel (dynamic smem ~109KB, 2 CTAs/SM)
// ---------------------------------------------------------------------------
extern "C" void kernel_launch(void* const* d_in, const int* in_sizes, int n_in,
                              void* d_out, int out_size) {
    const float* x_a     = (const float*)d_in[0];
    const int*   ei_a    = (const int*)  d_in[1];
    const int*   batch_a = (const int*)  d_in[2];
    const float* x_b     = (const float*)d_in[3];
    const int*   ei_b    = (const int*)  d_in[4];
    const int*   batch_b = (const int*)  d_in[5];
    const float* W1 = (const float*)d_in[6];
    const float* b1 = (const float*)d_in[7];
    const float* W2 = (const float*)d_in[8];
    const float* b2 = (const float*)d_in[9];
    const float* W3 = (const float*)d_in[10];
    const float* b3 = (const float*)d_in[11];
    float* out = (float*)d_out;

    cudaFuncSetAttribute(mega_kernel, cudaFuncAttributeMaxDynamicSharedMemorySize,
                         SMEM_BYTES);
    mega_kernel<<<NB, TPB, SMEM_BYTES>>>(x_a, ei_a, batch_a, x_b, ei_b, batch_b,
                                         W1, b1, W2, b2, W3, b3, out);
}

// round 15
// speedup vs baseline: 2.3111x; 1.0984x over previous
#include <cuda_runtime.h>
#include <cuda_bf16.h>
#include <cstdint>

// ---------------------------------------------------------------------------
// SiameseBrainNet: persistent mega-kernel + mma.sync bf16 GEMM
// R15: R14 + h intermediate stored as bf16 (41MB, L2-resident) — GEMM
//      epilogue writes bf16; aggregate gathers bf16 and accumulates fp32.
//      Calibrated rel_err ~2.5e-4.
// ---------------------------------------------------------------------------

#define NN 20000
#define N2 (2 * NN)           // fused node count
#define EE 640000
#define DH 512
#define GG 64
#define NB 296                // 2 CTAs per SM
#define TPB 256
#define MT 313                // ceil(40000/128)
#define NTILE (4 * MT)        // 1252 output tiles (128x128)

#define KSTR 72               // bf16 elements per smem row (64 data + 8 pad)
#define TILE_BYTES (128 * KSTR * 2)          // 18432
#define BUF_BYTES  (2 * TILE_BYTES)          // 36864 (A, B)
#define SM_RED     (3 * BUF_BYTES)           // 110592 (3-stage)
#define SMEM_BYTES (SM_RED + 1024)           // 111616 (x2 = 223232 <= 227KB)

// ---- scratch ---------------------------------------------------------------
__device__ __nv_bfloat16 g_h[N2 * DH];          // GEMM output h (bf16, L2-resident)
__device__ float g_x[N2 * DH];                  // last-layer agg output
__device__ __nv_bfloat16 g_a[N2 * DH];          // GEMM A operand (bf16)
__device__ __nv_bfloat16 g_whi[3 * DH * DH];    // W^T bf16, [l][n][k]
__device__ int   g_deg[2][NN];     // INVARIANT: zero at kernel entry
__device__ int   g_rowptr[2][NN + 1];
__device__ int   g_cursor[2][NN];
__device__ float g_dinv[2][NN];
__device__ int   g_csr_src[2][EE];
__device__ float g_csr_norm[2][EE];
__device__ float g_pooled[2][GG * DH];
__device__ unsigned g_count, g_gen;

// ---- grid barrier -----------------------------------------------------------
__device__ __forceinline__ void gsync(unsigned target) {
    __syncthreads();
    if (threadIdx.x == 0) {
        __threadfence();
        if (atomicAdd(&g_count, 1u) == NB - 1u) {
            atomicExch(&g_count, 0u);
            __threadfence();
            atomicAdd(&g_gen, 1u);
        } else {
            while (*((volatile unsigned*)&g_gen) < target) __nanosleep(64);
        }
        __threadfence();
    }
    __syncthreads();
}

// ---- tensor-core primitives ---------------------------------------------------
__device__ __forceinline__ void mma16816(float* d,
                                         uint32_t a0, uint32_t a1, uint32_t a2, uint32_t a3,
                                         uint32_t b0, uint32_t b1) {
    asm volatile(
        "mma.sync.aligned.m16n8k16.row.col.f32.bf16.bf16.f32 "
        "{%0,%1,%2,%3}, {%4,%5,%6,%7}, {%8,%9}, {%0,%1,%2,%3};"
        : "+f"(d[0]), "+f"(d[1]), "+f"(d[2]), "+f"(d[3])
        : "r"(a0), "r"(a1), "r"(a2), "r"(a3), "r"(b0), "r"(b1));
}
__device__ __forceinline__ void ldsm4(uint32_t& r0, uint32_t& r1, uint32_t& r2, uint32_t& r3,
                                      uint32_t addr) {
    asm volatile("ldmatrix.sync.aligned.m8n8.x4.shared.b16 {%0,%1,%2,%3}, [%4];"
                 : "=r"(r0), "=r"(r1), "=r"(r2), "=r"(r3) : "r"(addr));
}
#define CP_COMMIT() asm volatile("cp.async.commit_group;" ::: "memory")
#define CP_WAIT(n)  asm volatile("cp.async.wait_group %0;" :: "n"(n) : "memory")

// async fill: gmem bf16 [.,512] -> smem tile 128x64 (stride KSTR)
__device__ __forceinline__ void fill_tile_async(uint32_t smt,
                                                const __nv_bfloat16* __restrict__ g,
                                                int row0, int kc, int nrows) {
    const int tid = threadIdx.x;
#pragma unroll
    for (int i = 0; i < 4; i++) {
        int idx = i * 256 + tid;       // 0..1023
        int r   = idx >> 3;            // 0..127
        int c8  = (idx & 7) << 3;      // 0..56
        int gr  = row0 + r;
        bool valid = (gr < nrows);
        const void* src = g + (size_t)(valid ? gr : 0) * DH + kc + c8;
        uint32_t dst = smt + (uint32_t)(r * KSTR + c8) * 2;
        int sz = valid ? 16 : 0;
        asm volatile("cp.async.cg.shared.global [%0], [%1], 16, %2;"
                     :: "r"(dst), "l"(src), "r"(sz) : "memory");
    }
}

// fill both tiles for one k-chunk into the given stage buffer, commit once
__device__ __forceinline__ void fill_chunk(uint32_t buf, int bm, int bn, int kc8,
                                           const __nv_bfloat16* __restrict__ Whi) {
    fill_tile_async(buf + 0 * TILE_BYTES, g_a,  bm * 128, kc8 * 64, N2);
    fill_tile_async(buf + 1 * TILE_BYTES, Whi,  bn * 128, kc8 * 64, 1 << 30);
    CP_COMMIT();
}

// ---- GEMM phase: g_h[N2,512] = bf16( A @ W )  (A bf16, W bf16, fp32 accum) --
__device__ void gemm_phase(uint32_t smb, const __nv_bfloat16* __restrict__ Whi) {
    const int tid  = threadIdx.x;
    const int lane = tid & 31, warp = tid >> 5;
    const int wm = warp & 3;        // 32-row group
    const int wn = warp >> 2;       // 64-col group
    const int g  = lane >> 2;       // epilogue row-in-8
    const int tg = lane & 3;        // epilogue col pair
    const int seg = lane >> 3;      // ldmatrix segment 0..3
    const int lr  = lane & 7;

    const int aoff0 = (wm * 32 + 0  + (seg & 1) * 8 + lr) * KSTR + (seg >> 1) * 8;
    const int aoff1 = (wm * 32 + 16 + (seg & 1) * 8 + lr) * KSTR + (seg >> 1) * 8;
    const int boffb = (wn * 64 + (seg & 1) * 8 + lr) * KSTR + (seg >> 1) * 8;

    for (int t = blockIdx.x; t < NTILE; t += NB) {
        const int bm = t >> 2, bn = t & 3;

        float acc[2][8][4];
#pragma unroll
        for (int mt = 0; mt < 2; mt++)
#pragma unroll
            for (int nt = 0; nt < 8; nt++)
#pragma unroll
                for (int q = 0; q < 4; q++) acc[mt][nt][q] = 0.0f;

        // prologue: fill chunks 0,1 into stages 0,1
        fill_chunk(smb + 0 * BUF_BYTES, bm, bn, 0, Whi);
        fill_chunk(smb + 1 * BUF_BYTES, bm, bn, 1, Whi);

#pragma unroll 1
        for (int kc8 = 0; kc8 < 8; kc8++) {
            if (kc8 < 7) { CP_WAIT(1); } else { CP_WAIT(0); }
            __syncthreads();                 // chunk kc8 ready; all threads done with kc8-1
            if (kc8 + 2 < 8)
                fill_chunk(smb + (uint32_t)((kc8 + 2) % 3) * BUF_BYTES, bm, bn, kc8 + 2, Whi);

            const uint32_t cur = smb + (uint32_t)(kc8 % 3) * BUF_BYTES;
            const uint32_t Abuf = cur + 0 * TILE_BYTES;
            const uint32_t Bbuf = cur + 1 * TILE_BYTES;

#pragma unroll
            for (int ks4 = 0; ks4 < 4; ks4++) {
                const uint32_t kb = (uint32_t)(ks4 * 16) * 2;   // bytes

                uint32_t bh[8][2];
#pragma unroll
                for (int nq = 0; nq < 4; nq++) {
                    uint32_t r0, r1, r2, r3;
                    ldsm4(r0, r1, r2, r3, Bbuf + (uint32_t)(boffb + nq * 16 * KSTR) * 2 + kb);
                    bh[nq * 2][0] = r0; bh[nq * 2 + 1][0] = r1;
                    bh[nq * 2][1] = r2; bh[nq * 2 + 1][1] = r3;
                }
#pragma unroll
                for (int mt = 0; mt < 2; mt++) {
                    const int aoff = mt ? aoff1 : aoff0;
                    uint32_t ah0, ah1, ah2, ah3;
                    ldsm4(ah0, ah1, ah2, ah3, Abuf + (uint32_t)aoff * 2 + kb);
#pragma unroll
                    for (int nt = 0; nt < 8; nt++)
                        mma16816(acc[mt][nt], ah0, ah1, ah2, ah3, bh[nt][0], bh[nt][1]);
                }
            }
        }

        // epilogue: bf16 h. frag: c0,c1 at (g, 2tg); c2,c3 at (g+8, 2tg)
#pragma unroll
        for (int mt = 0; mt < 2; mt++) {
            int row0 = bm * 128 + wm * 32 + mt * 16 + g;
#pragma unroll
            for (int nt = 0; nt < 8; nt++) {
                int col = bn * 128 + wn * 64 + nt * 8 + 2 * tg;
                if (row0 < N2) {
                    __nv_bfloat162 p;
                    p.x = __float2bfloat16(acc[mt][nt][0]);
                    p.y = __float2bfloat16(acc[mt][nt][1]);
                    *(__nv_bfloat162*)&g_h[(size_t)row0 * DH + col] = p;
                }
                if (row0 + 8 < N2) {
                    __nv_bfloat162 p;
                    p.x = __float2bfloat16(acc[mt][nt][2]);
                    p.y = __float2bfloat16(acc[mt][nt][3]);
                    *(__nv_bfloat162*)&g_h[(size_t)(row0 + 8) * DH + col] = p;
                }
            }
        }
        __syncthreads();   // stages 0,1 consumed; next tile's prologue refills them
    }
}

// ---- aggregation over fused node range [0, 2NN); bf16 gathers, idx prefetch --
#define LOADI8(P, Q, csr, nrm, base)                                          \
    P##0 = csr[(base)];     P##1 = csr[(base) + 1];                           \
    P##2 = csr[(base) + 2]; P##3 = csr[(base) + 3];                           \
    P##4 = csr[(base) + 4]; P##5 = csr[(base) + 5];                           \
    P##6 = csr[(base) + 6]; P##7 = csr[(base) + 7];                           \
    Q##0 = nrm[(base)];     Q##1 = nrm[(base) + 1];                           \
    Q##2 = nrm[(base) + 2]; Q##3 = nrm[(base) + 3];                           \
    Q##4 = nrm[(base) + 4]; Q##5 = nrm[(base) + 5];                           \
    Q##6 = nrm[(base) + 6]; Q##7 = nrm[(base) + 7];

__device__ __forceinline__ float4 ld_bf4(const __nv_bfloat16* __restrict__ hb,
                                         size_t off) {
    const uint2 u = *(const uint2*)(hb + off);
    float2 f0 = __bfloat1622float2(*(const __nv_bfloat162*)&u.x);
    float2 f1 = __bfloat1622float2(*(const __nv_bfloat162*)&u.y);
    return make_float4(f0.x, f0.y, f1.x, f1.y);
}

#define GATHER8(P, Q)                                                         \
    {                                                                         \
        float4 v0 = ld_bf4(hb, (size_t)P##0 * DH + t4);                       \
        float4 v1 = ld_bf4(hb, (size_t)P##1 * DH + t4);                       \
        float4 v2 = ld_bf4(hb, (size_t)P##2 * DH + t4);                       \
        float4 v3 = ld_bf4(hb, (size_t)P##3 * DH + t4);                       \
        float4 v4 = ld_bf4(hb, (size_t)P##4 * DH + t4);                       \
        float4 v5 = ld_bf4(hb, (size_t)P##5 * DH + t4);                       \
        float4 v6 = ld_bf4(hb, (size_t)P##6 * DH + t4);                       \
        float4 v7 = ld_bf4(hb, (size_t)P##7 * DH + t4);                       \
        a0.x += Q##0 * v0.x; a0.y += Q##0 * v0.y; a0.z += Q##0 * v0.z; a0.w += Q##0 * v0.w; \
        a1.x += Q##1 * v1.x; a1.y += Q##1 * v1.y; a1.z += Q##1 * v1.z; a1.w += Q##1 * v1.w; \
        a2.x += Q##2 * v2.x; a2.y += Q##2 * v2.y; a2.z += Q##2 * v2.z; a2.w += Q##2 * v2.w; \
        a3.x += Q##3 * v3.x; a3.y += Q##3 * v3.y; a3.z += Q##3 * v3.z; a3.w += Q##3 * v3.w; \
        a0.x += Q##4 * v4.x; a0.y += Q##4 * v4.y; a0.z += Q##4 * v4.z; a0.w += Q##4 * v4.w; \
        a1.x += Q##5 * v5.x; a1.y += Q##5 * v5.y; a1.z += Q##5 * v5.z; a1.w += Q##5 * v5.w; \
        a2.x += Q##6 * v6.x; a2.y += Q##6 * v6.y; a2.z += Q##6 * v6.z; a2.w += Q##6 * v6.w; \
        a3.x += Q##7 * v7.x; a3.y += Q##7 * v7.y; a3.z += Q##7 * v7.z; a3.w += Q##7 * v7.w; \
    }

__device__ void agg_phase(const float* __restrict__ bias, int l) {
    const int sub = threadIdx.x >> 7;   // 0 or 1
    const int t   = threadIdx.x & 127;  // float4 lane
    const int t4  = t * 4;
    const float4 b4 = *(const float4*)&bias[t4];

    for (int j = blockIdx.x * 2 + sub; j < N2; j += NB * 2) {
        const int enc = (j >= NN);
        const int i   = j - enc * NN;
        const int* __restrict__ csr = g_csr_src[enc];
        const float* __restrict__ nrm = g_csr_norm[enc];
        const __nv_bfloat16* __restrict__ hb = g_h + (size_t)enc * NN * DH;

        int r0 = g_rowptr[enc][i];
        int r1 = g_rowptr[enc][i + 1];

        float4 a0 = make_float4(0.f, 0.f, 0.f, 0.f);
        float4 a1 = a0, a2 = a0, a3 = a0;

        int e = r0;
        const int last8 = r1 - 8;
        if (e <= last8) {
            int   p0, p1, p2, p3, p4, p5, p6, p7;
            float q0, q1, q2, q3, q4, q5, q6, q7;
            LOADI8(p, q, csr, nrm, e)
            e += 8;
            while (e <= last8) {
                int   c0, c1, c2, c3, c4, c5, c6, c7;
                float d0, d1, d2, d3, d4, d5, d6, d7;
                LOADI8(c, d, csr, nrm, e)      // prefetch next batch's indices
                GATHER8(p, q)                   // gathers + FMAs for current batch
                p0 = c0; p1 = c1; p2 = c2; p3 = c3;
                p4 = c4; p5 = c5; p6 = c6; p7 = c7;
                q0 = d0; q1 = d1; q2 = d2; q3 = d3;
                q4 = d4; q5 = d5; q6 = d6; q7 = d7;
                e += 8;
            }
            GATHER8(p, q)
        }
        for (; e < r1; e++) {
            int   s = csr[e];
            float w = nrm[e];
            float4 v = ld_bf4(hb, (size_t)s * DH + t4);
            a0.x += w * v.x; a0.y += w * v.y; a0.z += w * v.z; a0.w += w * v.w;
        }

        float4 acc;
        acc.x = (a0.x + a1.x) + (a2.x + a3.x);
        acc.y = (a0.y + a1.y) + (a2.y + a3.y);
        acc.z = (a0.z + a1.z) + (a2.z + a3.z);
        acc.w = (a0.w + a1.w) + (a2.w + a3.w);

        float d = g_dinv[enc][i];
        float wd = d * d;
        float4 vs = ld_bf4(hb, (size_t)i * DH + t4);
        acc.x += wd * vs.x + b4.x;
        acc.y += wd * vs.y + b4.y;
        acc.z += wd * vs.z + b4.z;
        acc.w += wd * vs.w + b4.w;

        if (l < 2) {   // relu + round to bf16 for next GEMM
            acc.x = fmaxf(acc.x, 0.f); acc.y = fmaxf(acc.y, 0.f);
            acc.z = fmaxf(acc.z, 0.f); acc.w = fmaxf(acc.w, 0.f);
            __nv_bfloat162 h01, h23;
            h01.x = __float2bfloat16(acc.x); h01.y = __float2bfloat16(acc.y);
            h23.x = __float2bfloat16(acc.z); h23.y = __float2bfloat16(acc.w);
            __nv_bfloat162* hp = (__nv_bfloat162*)(g_a + (size_t)j * DH + t4);
            hp[0] = h01; hp[1] = h23;
        } else {
            *(float4*)&g_x[(size_t)j * DH + t4] = acc;
        }
    }
}

// ---- pool (128 blocks: enc = bid>>6, graph = bid&63) -------------------------
__device__ void pool_phase(const int* __restrict__ batch_a,
                           const int* __restrict__ batch_b) {
    int bid = blockIdx.x;
    if (bid >= 2 * GG) return;
    int enc = bid >> 6;
    int g = bid & 63;
    int t = threadIdx.x;   // float2 lane

    const int* batch = enc ? batch_b : batch_a;
    const float* h = g_x + (size_t)enc * NN * DH;

    int lo = 0, hi = NN;
    while (lo < hi) { int m = (lo + hi) >> 1; if (batch[m] < g) lo = m + 1; else hi = m; }
    int start = lo;
    lo = start; hi = NN;
    while (lo < hi) { int m = (lo + hi) >> 1; if (batch[m] < g + 1) lo = m + 1; else hi = m; }
    int end = lo;

    float2 a0 = make_float2(0.f, 0.f), a1 = a0;
    int r = start;
    for (; r + 1 < end; r += 2) {
        float2 v0 = *(const float2*)&h[(size_t)r * DH + t * 2];
        float2 v1 = *(const float2*)&h[(size_t)(r + 1) * DH + t * 2];
        a0.x += v0.x; a0.y += v0.y;
        a1.x += v1.x; a1.y += v1.y;
    }
    if (r < end) {
        float2 v = *(const float2*)&h[(size_t)r * DH + t * 2];
        a0.x += v.x; a0.y += v.y;
    }
    float inv = 1.0f / fmaxf((float)(end - start), 1.0f);
    *(float2*)&g_pooled[enc][g * DH + t * 2] =
        make_float2((a0.x + a1.x) * inv, (a0.y + a1.y) * inv);
}

__device__ void dist_phase(float* __restrict__ out, float* sred) {
    int g = blockIdx.x;
    if (g >= GG) return;
    int t = threadIdx.x;

    float2 a = *(const float2*)&g_pooled[0][g * DH + t * 2];
    float2 b = *(const float2*)&g_pooled[1][g * DH + t * 2];
    float dx = a.x - b.x + 1e-6f;
    float dy = a.y - b.y + 1e-6f;
    float s = dx * dx + dy * dy;

    sred[t] = s;
    __syncthreads();
    for (int off = 128; off > 0; off >>= 1) {
        if (t < off) sred[t] += sred[t + off];
        __syncthreads();
    }
    if (t == 0) out[g] = sqrtf(sred[0]);
}

// ---- mega kernel --------------------------------------------------------------
extern __shared__ __align__(16) unsigned char smem_dyn[];

__global__ __launch_bounds__(TPB, 2) void mega_kernel(
    const float* __restrict__ x_a, const int* __restrict__ ei_a,
    const int* __restrict__ batch_a,
    const float* __restrict__ x_b, const int* __restrict__ ei_b,
    const int* __restrict__ batch_b,
    const float* __restrict__ W1, const float* __restrict__ b1,
    const float* __restrict__ W2, const float* __restrict__ b2,
    const float* __restrict__ W3, const float* __restrict__ b3,
    float* __restrict__ out)
{
    unsigned char* sm = smem_dyn;
    const uint32_t smb = (uint32_t)__cvta_generic_to_shared(sm);
    const int tid = threadIdx.x, bid = blockIdx.x;
    unsigned target = *((volatile unsigned*)&g_gen);

    // ---- Phase A (combined): W transpose+round, x rounds (both), deg counts
    {
        const float* Ws[3] = {W1, W2, W3};
        const int total = 3 * DH * DH;
        for (int idx = bid * TPB + tid; idx < total; idx += NB * TPB) {
            int l = idx >> 18;
            int rem = idx & (DH * DH - 1);
            int k = rem >> 9;
            int n = rem & 511;
            g_whi[l * DH * DH + n * DH + k] = __float2bfloat16(Ws[l][k * DH + n]);
        }
    }
    {
        const int total4 = NN * DH / 4;
        for (int idx = bid * TPB + tid; idx < 2 * total4; idx += NB * TPB) {
            int enc = (idx >= total4);
            int i4  = idx - enc * total4;
            const float* xs = enc ? x_b : x_a;
            float4 v = *(const float4*)(xs + (size_t)i4 * 4);
            __nv_bfloat162 h01, h23;
            h01.x = __float2bfloat16(v.x); h01.y = __float2bfloat16(v.y);
            h23.x = __float2bfloat16(v.z); h23.y = __float2bfloat16(v.w);
            size_t o4 = (size_t)enc * total4 + i4;
            __nv_bfloat162* hp = (__nv_bfloat162*)(g_a + o4 * 4);
            hp[0] = h01; hp[1] = h23;
        }
    }
    for (int e = bid * TPB + tid; e < 2 * EE; e += NB * TPB) {
        int enc = (e >= EE);
        int el  = e - enc * EE;
        const int* dstv = (enc ? ei_b : ei_a) + EE;
        atomicAdd(&g_deg[enc][dstv[el]], 1);
    }
    gsync(++target);

    // ---- Phase B: scans (block 0 -> enc 0, block 1 -> enc 1) ----
    if (bid < 2) {
        const int enc = bid;
        int* sh = (int*)(sm + SM_RED);
        const int chunk = (NN + TPB - 1) / TPB;   // 79
        int base = tid * chunk;
        int local = 0;
        for (int j = 0; j < chunk; j++) {
            int idx = base + j;
            if (idx < NN) local += g_deg[enc][idx];
        }
        sh[tid] = local;
        __syncthreads();
        for (int off = 1; off < TPB; off <<= 1) {
            int v = (tid >= off) ? sh[tid - off] : 0;
            __syncthreads();
            sh[tid] += v;
            __syncthreads();
        }
        int run = tid ? sh[tid - 1] : 0;
        for (int j = 0; j < chunk; j++) {
            int idx = base + j;
            if (idx < NN) {
                int d = g_deg[enc][idx];
                g_deg[enc][idx]    = 0;               // restore invariant
                g_rowptr[enc][idx] = run;
                g_cursor[enc][idx] = run;
                g_dinv[enc][idx]   = rsqrtf((float)d + 1.0f);
                run += d;
            }
        }
        if (tid == TPB - 1) g_rowptr[enc][NN] = sh[TPB - 1];
    }
    gsync(++target);

    // ---- Phase C: fill CSR (both encoders) ----
    for (int e = bid * TPB + tid; e < 2 * EE; e += NB * TPB) {
        int enc = (e >= EE);
        int el  = e - enc * EE;
        const int* srcv = enc ? ei_b : ei_a;
        const int* dstv = srcv + EE;
        int s = srcv[el], d = dstv[el];
        int pos = atomicAdd(&g_cursor[enc][d], 1);
        g_csr_src[enc][pos]  = s;
        g_csr_norm[enc][pos] = g_dinv[enc][s] * g_dinv[enc][d];
    }
    gsync(++target);

    // ---- 3 GCN layers over fused M=40000 ----
    for (int l = 0; l < 3; l++) {
        const float* bb = (l == 0) ? b1 : (l == 1) ? b2 : b3;
        gemm_phase(smb, g_whi + l * DH * DH);
        gsync(++target);
        agg_phase(bb, l);
        gsync(++target);
    }

    // ---- mean pool (both encoders, 128 blocks) ----
    pool_phase(batch_a, batch_b);
    gsync(++target);

    // ---- pairwise distance ----
    dist_phase(out, (float*)(sm + SM_RED));
}

// ---------------------------------------------------------------------------
// launch: ONE kernel (dynamic smem ~109KB, 2 CTAs/SM)
// ---------------------------------------------------------------------------
extern "C" void kernel_launch(void* const* d_in, const int* in_sizes, int n_in,
                              void* d_out, int out_size) {
    const float* x_a     = (const float*)d_in[0];
    const int*   ei_a    = (const int*)  d_in[1];
    const int*   batch_a = (const int*)  d_in[2];
    const float* x_b     = (const float*)d_in[3];
    const int*   ei_b    = (const int*)  d_in[4];
    const int*   batch_b = (const int*)  d_in[5];
    const float* W1 = (const float*)d_in[6];
    const float* b1 = (const float*)d_in[7];
    const float* W2 = (const float*)d_in[8];
    const float* b2 = (const float*)d_in[9];
    const float* W3 = (const float*)d_in[10];
    const float* b3 = (const float*)d_in[11];
    float* out = (float*)d_out;

    cudaFuncSetAttribute(mega_kernel, cudaFuncAttributeMaxDynamicSharedMemorySize,
                         SMEM_BYTES);
    mega_kernel<<<NB, TPB, SMEM_BYTES>>>(x_a, ei_a, batch_a, x_b, ei_b, batch_b,
                                         W1, b1, W2, b2, W3, b3, out);
}

// round 16
// speedup vs baseline: 2.3743x; 1.0274x over previous
#include <cuda_runtime.h>
#include <cuda_bf16.h>
#include <cstdint>

// ---------------------------------------------------------------------------
// SiameseBrainNet: persistent mega-kernel + mma.sync bf16 GEMM
// R16: normalization folded into data (h' = dinv*h; x pre-scaled for layer 1,
//      epilogue-scaled for layers 2-3) -> csr_norm eliminated, agg is pure
//      adds; scan hidden behind W-round; pool fused into agg-3 via atomics
//      (g_x eliminated). Same rounding-source count as R15 (~2.6e-4).
// ---------------------------------------------------------------------------

#define NN 20000
#define N2 (2 * NN)           // fused node count
#define EE 640000
#define DH 512
#define GG 64
#define NB 296                // 2 CTAs per SM
#define TPB 256
#define MT 313                // ceil(40000/128)
#define NTILE (4 * MT)        // 1252 output tiles (128x128)

#define KSTR 72               // bf16 elements per smem row (64 data + 8 pad)
#define TILE_BYTES (128 * KSTR * 2)          // 18432
#define BUF_BYTES  (2 * TILE_BYTES)          // 36864 (A, B)
#define SM_RED     (3 * BUF_BYTES)           // 110592 (3-stage)
#define SMEM_BYTES (SM_RED + 1024)           // 111616 (x2 = 223232 <= 227KB)

// ---- scratch ---------------------------------------------------------------
__device__ __nv_bfloat16 g_h[N2 * DH];          // h' = dinv*h (bf16, L2-resident)
__device__ __nv_bfloat16 g_a[N2 * DH];          // GEMM A operand (bf16)
__device__ __nv_bfloat16 g_whi[3 * DH * DH];    // W^T bf16, [l][n][k]
__device__ int   g_deg[2][NN];     // INVARIANT: zero at kernel entry
__device__ int   g_rowptr[2][NN + 1];
__device__ int   g_cursor[2][NN];
__device__ float g_dinv[2][NN];
__device__ int   g_csr_src[2][EE];
__device__ float g_invcnt[2][GG];
__device__ float g_pooled[2][GG * DH];          // zeroed in phase A1 each call
__device__ unsigned g_count, g_gen;

// ---- grid barrier -----------------------------------------------------------
__device__ __forceinline__ void gsync(unsigned target) {
    __syncthreads();
    if (threadIdx.x == 0) {
        __threadfence();
        if (atomicAdd(&g_count, 1u) == NB - 1u) {
            atomicExch(&g_count, 0u);
            __threadfence();
            atomicAdd(&g_gen, 1u);
        } else {
            while (*((volatile unsigned*)&g_gen) < target) __nanosleep(64);
        }
        __threadfence();
    }
    __syncthreads();
}

// ---- tensor-core primitives ---------------------------------------------------
__device__ __forceinline__ void mma16816(float* d,
                                         uint32_t a0, uint32_t a1, uint32_t a2, uint32_t a3,
                                         uint32_t b0, uint32_t b1) {
    asm volatile(
        "mma.sync.aligned.m16n8k16.row.col.f32.bf16.bf16.f32 "
        "{%0,%1,%2,%3}, {%4,%5,%6,%7}, {%8,%9}, {%0,%1,%2,%3};"
        : "+f"(d[0]), "+f"(d[1]), "+f"(d[2]), "+f"(d[3])
        : "r"(a0), "r"(a1), "r"(a2), "r"(a3), "r"(b0), "r"(b1));
}
__device__ __forceinline__ void ldsm4(uint32_t& r0, uint32_t& r1, uint32_t& r2, uint32_t& r3,
                                      uint32_t addr) {
    asm volatile("ldmatrix.sync.aligned.m8n8.x4.shared.b16 {%0,%1,%2,%3}, [%4];"
                 : "=r"(r0), "=r"(r1), "=r"(r2), "=r"(r3) : "r"(addr));
}
#define CP_COMMIT() asm volatile("cp.async.commit_group;" ::: "memory")
#define CP_WAIT(n)  asm volatile("cp.async.wait_group %0;" :: "n"(n) : "memory")

__device__ __forceinline__ float dinv_fused(int j) {
    int enc = j >= NN;
    return g_dinv[enc][j - enc * NN];
}

// async fill: gmem bf16 [.,512] -> smem tile 128x64 (stride KSTR)
__device__ __forceinline__ void fill_tile_async(uint32_t smt,
                                                const __nv_bfloat16* __restrict__ g,
                                                int row0, int kc, int nrows) {
    const int tid = threadIdx.x;
#pragma unroll
    for (int i = 0; i < 4; i++) {
        int idx = i * 256 + tid;       // 0..1023
        int r   = idx >> 3;            // 0..127
        int c8  = (idx & 7) << 3;      // 0..56
        int gr  = row0 + r;
        bool valid = (gr < nrows);
        const void* src = g + (size_t)(valid ? gr : 0) * DH + kc + c8;
        uint32_t dst = smt + (uint32_t)(r * KSTR + c8) * 2;
        int sz = valid ? 16 : 0;
        asm volatile("cp.async.cg.shared.global [%0], [%1], 16, %2;"
                     :: "r"(dst), "l"(src), "r"(sz) : "memory");
    }
}

// fill both tiles for one k-chunk into the given stage buffer, commit once
__device__ __forceinline__ void fill_chunk(uint32_t buf, int bm, int bn, int kc8,
                                           const __nv_bfloat16* __restrict__ Whi) {
    fill_tile_async(buf + 0 * TILE_BYTES, g_a,  bm * 128, kc8 * 64, N2);
    fill_tile_async(buf + 1 * TILE_BYTES, Whi,  bn * 128, kc8 * 64, 1 << 30);
    CP_COMMIT();
}

// ---- GEMM phase: g_h[N2,512] = bf16( (A @ W) * (scale_out ? dinv : 1) ) -----
__device__ void gemm_phase(uint32_t smb, const __nv_bfloat16* __restrict__ Whi,
                           int bid0, int nb0, int scale_out) {
    const int tid  = threadIdx.x;
    const int lane = tid & 31, warp = tid >> 5;
    const int wm = warp & 3;        // 32-row group
    const int wn = warp >> 2;       // 64-col group
    const int g  = lane >> 2;       // epilogue row-in-8
    const int tg = lane & 3;        // epilogue col pair
    const int seg = lane >> 3;      // ldmatrix segment 0..3
    const int lr  = lane & 7;

    if (bid0 < 0) return;

    const int aoff0 = (wm * 32 + 0  + (seg & 1) * 8 + lr) * KSTR + (seg >> 1) * 8;
    const int aoff1 = (wm * 32 + 16 + (seg & 1) * 8 + lr) * KSTR + (seg >> 1) * 8;
    const int boffb = (wn * 64 + (seg & 1) * 8 + lr) * KSTR + (seg >> 1) * 8;

    for (int t = bid0; t < NTILE; t += nb0) {
        const int bm = t >> 2, bn = t & 3;

        float acc[2][8][4];
#pragma unroll
        for (int mt = 0; mt < 2; mt++)
#pragma unroll
            for (int nt = 0; nt < 8; nt++)
#pragma unroll
                for (int q = 0; q < 4; q++) acc[mt][nt][q] = 0.0f;

        // prologue: fill chunks 0,1 into stages 0,1
        fill_chunk(smb + 0 * BUF_BYTES, bm, bn, 0, Whi);
        fill_chunk(smb + 1 * BUF_BYTES, bm, bn, 1, Whi);

#pragma unroll 1
        for (int kc8 = 0; kc8 < 8; kc8++) {
            if (kc8 < 7) { CP_WAIT(1); } else { CP_WAIT(0); }
            __syncthreads();                 // chunk kc8 ready; all threads done with kc8-1
            if (kc8 + 2 < 8)
                fill_chunk(smb + (uint32_t)((kc8 + 2) % 3) * BUF_BYTES, bm, bn, kc8 + 2, Whi);

            const uint32_t cur = smb + (uint32_t)(kc8 % 3) * BUF_BYTES;
            const uint32_t Abuf = cur + 0 * TILE_BYTES;
            const uint32_t Bbuf = cur + 1 * TILE_BYTES;

#pragma unroll
            for (int ks4 = 0; ks4 < 4; ks4++) {
                const uint32_t kb = (uint32_t)(ks4 * 16) * 2;   // bytes

                uint32_t bh[8][2];
#pragma unroll
                for (int nq = 0; nq < 4; nq++) {
                    uint32_t r0, r1, r2, r3;
                    ldsm4(r0, r1, r2, r3, Bbuf + (uint32_t)(boffb + nq * 16 * KSTR) * 2 + kb);
                    bh[nq * 2][0] = r0; bh[nq * 2 + 1][0] = r1;
                    bh[nq * 2][1] = r2; bh[nq * 2 + 1][1] = r3;
                }
#pragma unroll
                for (int mt = 0; mt < 2; mt++) {
                    const int aoff = mt ? aoff1 : aoff0;
                    uint32_t ah0, ah1, ah2, ah3;
                    ldsm4(ah0, ah1, ah2, ah3, Abuf + (uint32_t)aoff * 2 + kb);
#pragma unroll
                    for (int nt = 0; nt < 8; nt++)
                        mma16816(acc[mt][nt], ah0, ah1, ah2, ah3, bh[nt][0], bh[nt][1]);
                }
            }
        }

        // epilogue: bf16 h' (optionally scaled by dinv).
#pragma unroll
        for (int mt = 0; mt < 2; mt++) {
            int row0 = bm * 128 + wm * 32 + mt * 16 + g;
            float dva = 1.0f, dvb = 1.0f;
            if (scale_out) {
                if (row0 < N2)     dva = dinv_fused(row0);
                if (row0 + 8 < N2) dvb = dinv_fused(row0 + 8);
            }
#pragma unroll
            for (int nt = 0; nt < 8; nt++) {
                int col = bn * 128 + wn * 64 + nt * 8 + 2 * tg;
                if (row0 < N2) {
                    __nv_bfloat162 p;
                    p.x = __float2bfloat16(acc[mt][nt][0] * dva);
                    p.y = __float2bfloat16(acc[mt][nt][1] * dva);
                    *(__nv_bfloat162*)&g_h[(size_t)row0 * DH + col] = p;
                }
                if (row0 + 8 < N2) {
                    __nv_bfloat162 p;
                    p.x = __float2bfloat16(acc[mt][nt][2] * dvb);
                    p.y = __float2bfloat16(acc[mt][nt][3] * dvb);
                    *(__nv_bfloat162*)&g_h[(size_t)(row0 + 8) * DH + col] = p;
                }
            }
        }
        __syncthreads();   // stages 0,1 consumed; next tile's prologue refills them
    }
}

// ---- aggregation: sum of pre-scaled h' rows; idx prefetch; pure adds ---------
#define LDIDX8(P, csr, base)                                                  \
    P##0 = csr[(base)];     P##1 = csr[(base) + 1];                           \
    P##2 = csr[(base) + 2]; P##3 = csr[(base) + 3];                           \
    P##4 = csr[(base) + 4]; P##5 = csr[(base) + 5];                           \
    P##6 = csr[(base) + 6]; P##7 = csr[(base) + 7];

__device__ __forceinline__ float4 ld_bf4(const __nv_bfloat16* __restrict__ hb,
                                         size_t off) {
    const uint2 u = *(const uint2*)(hb + off);
    float2 f0 = __bfloat1622float2(*(const __nv_bfloat162*)&u.x);
    float2 f1 = __bfloat1622float2(*(const __nv_bfloat162*)&u.y);
    return make_float4(f0.x, f0.y, f1.x, f1.y);
}

#define GATHER8(P)                                                            \
    {                                                                         \
        float4 v0 = ld_bf4(hb, (size_t)P##0 * DH + t4);                       \
        float4 v1 = ld_bf4(hb, (size_t)P##1 * DH + t4);                       \
        float4 v2 = ld_bf4(hb, (size_t)P##2 * DH + t4);                       \
        float4 v3 = ld_bf4(hb, (size_t)P##3 * DH + t4);                       \
        float4 v4 = ld_bf4(hb, (size_t)P##4 * DH + t4);                       \
        float4 v5 = ld_bf4(hb, (size_t)P##5 * DH + t4);                       \
        float4 v6 = ld_bf4(hb, (size_t)P##6 * DH + t4);                       \
        float4 v7 = ld_bf4(hb, (size_t)P##7 * DH + t4);                       \
        a0.x += v0.x; a0.y += v0.y; a0.z += v0.z; a0.w += v0.w;               \
        a1.x += v1.x; a1.y += v1.y; a1.z += v1.z; a1.w += v1.w;               \
        a2.x += v2.x; a2.y += v2.y; a2.z += v2.z; a2.w += v2.w;               \
        a3.x += v3.x; a3.y += v3.y; a3.z += v3.z; a3.w += v3.w;               \
        a0.x += v4.x; a0.y += v4.y; a0.z += v4.z; a0.w += v4.w;               \
        a1.x += v5.x; a1.y += v5.y; a1.z += v5.z; a1.w += v5.w;               \
        a2.x += v6.x; a2.y += v6.y; a2.z += v6.z; a2.w += v6.w;               \
        a3.x += v7.x; a3.y += v7.y; a3.z += v7.z; a3.w += v7.w;               \
    }

__device__ void agg_phase(const float* __restrict__ bias, int l,
                          const int* __restrict__ batch_a,
                          const int* __restrict__ batch_b) {
    const int sub = threadIdx.x >> 7;   // 0 or 1
    const int t   = threadIdx.x & 127;  // float4 lane
    const int t4  = t * 4;
    const float4 b4 = *(const float4*)&bias[t4];

    for (int j = blockIdx.x * 2 + sub; j < N2; j += NB * 2) {
        const int enc = (j >= NN);
        const int i   = j - enc * NN;
        const int* __restrict__ csr = g_csr_src[enc];
        const __nv_bfloat16* __restrict__ hb = g_h + (size_t)enc * NN * DH;

        int r0 = g_rowptr[enc][i];
        int r1 = g_rowptr[enc][i + 1];

        float4 a0 = make_float4(0.f, 0.f, 0.f, 0.f);
        float4 a1 = a0, a2 = a0, a3 = a0;

        int e = r0;
        const int last8 = r1 - 8;
        if (e <= last8) {
            int p0, p1, p2, p3, p4, p5, p6, p7;
            LDIDX8(p, csr, e)
            e += 8;
            while (e <= last8) {
                int c0, c1, c2, c3, c4, c5, c6, c7;
                LDIDX8(c, csr, e)              // prefetch next batch's indices
                GATHER8(p)                      // gathers + adds for current batch
                p0 = c0; p1 = c1; p2 = c2; p3 = c3;
                p4 = c4; p5 = c5; p6 = c6; p7 = c7;
                e += 8;
            }
            GATHER8(p)
        }
        for (; e < r1; e++) {
            int s = csr[e];
            float4 v = ld_bf4(hb, (size_t)s * DH + t4);
            a0.x += v.x; a0.y += v.y; a0.z += v.z; a0.w += v.w;
        }

        // self term (h' already carries dinv_i)
        {
            float4 v = ld_bf4(hb, (size_t)i * DH + t4);
            a0.x += v.x; a0.y += v.y; a0.z += v.z; a0.w += v.w;
        }

        float dv = g_dinv[enc][i];
        float4 acc;
        acc.x = dv * ((a0.x + a1.x) + (a2.x + a3.x)) + b4.x;
        acc.y = dv * ((a0.y + a1.y) + (a2.y + a3.y)) + b4.y;
        acc.z = dv * ((a0.z + a1.z) + (a2.z + a3.z)) + b4.z;
        acc.w = dv * ((a0.w + a1.w) + (a2.w + a3.w)) + b4.w;

        if (l < 2) {   // relu + round to bf16 for next GEMM (unscaled)
            acc.x = fmaxf(acc.x, 0.f); acc.y = fmaxf(acc.y, 0.f);
            acc.z = fmaxf(acc.z, 0.f); acc.w = fmaxf(acc.w, 0.f);
            __nv_bfloat162 h01, h23;
            h01.x = __float2bfloat16(acc.x); h01.y = __float2bfloat16(acc.y);
            h23.x = __float2bfloat16(acc.z); h23.y = __float2bfloat16(acc.w);
            __nv_bfloat162* hp = (__nv_bfloat162*)(g_a + (size_t)j * DH + t4);
            hp[0] = h01; hp[1] = h23;
        } else {       // fused mean-pool: atomic accumulate acc/cnt into pooled
            const int* batch = enc ? batch_b : batch_a;
            int gid = batch[i];
            float w = g_invcnt[enc][gid];
            float* pp = &g_pooled[enc][gid * DH + t4];
            atomicAdd(pp + 0, acc.x * w);
            atomicAdd(pp + 1, acc.y * w);
            atomicAdd(pp + 2, acc.z * w);
            atomicAdd(pp + 3, acc.w * w);
        }
    }
}

__device__ void dist_phase(float* __restrict__ out, float* sred) {
    int g = blockIdx.x;
    if (g >= GG) return;
    int t = threadIdx.x;

    float2 a = *(const float2*)&g_pooled[0][g * DH + t * 2];
    float2 b = *(const float2*)&g_pooled[1][g * DH + t * 2];
    float dx = a.x - b.x + 1e-6f;
    float dy = a.y - b.y + 1e-6f;
    float s = dx * dx + dy * dy;

    sred[t] = s;
    __syncthreads();
    for (int off = 128; off > 0; off >>= 1) {
        if (t < off) sred[t] += sred[t + off];
        __syncthreads();
    }
    if (t == 0) out[g] = sqrtf(sred[0]);
}

// ---- mega kernel --------------------------------------------------------------
extern __shared__ __align__(16) unsigned char smem_dyn[];

__global__ __launch_bounds__(TPB, 2) void mega_kernel(
    const float* __restrict__ x_a, const int* __restrict__ ei_a,
    const int* __restrict__ batch_a,
    const float* __restrict__ x_b, const int* __restrict__ ei_b,
    const int* __restrict__ batch_b,
    const float* __restrict__ W1, const float* __restrict__ b1,
    const float* __restrict__ W2, const float* __restrict__ b2,
    const float* __restrict__ W3, const float* __restrict__ b3,
    float* __restrict__ out)
{
    unsigned char* sm = smem_dyn;
    const uint32_t smb = (uint32_t)__cvta_generic_to_shared(sm);
    const int tid = threadIdx.x, bid = blockIdx.x;
    unsigned target = *((volatile unsigned*)&g_gen);

    // ---- Phase A1: deg counts (both enc) + zero pooled ----
    for (int idx = bid * TPB + tid; idx < 2 * GG * DH; idx += NB * TPB)
        ((float*)g_pooled)[idx] = 0.0f;
    for (int e = bid * TPB + tid; e < 2 * EE; e += NB * TPB) {
        int enc = (e >= EE);
        int el  = e - enc * EE;
        const int* dstv = (enc ? ei_b : ei_a) + EE;
        atomicAdd(&g_deg[enc][dstv[el]], 1);
    }
    gsync(++target);

    // ---- Phase A2: blocks 0,1 scan + invcnt; others W transpose+round ----
    if (bid < 2) {
        const int enc = bid;
        int* sh = (int*)(sm + SM_RED);
        const int chunk = (NN + TPB - 1) / TPB;   // 79
        int base = tid * chunk;
        int local = 0;
        for (int j = 0; j < chunk; j++) {
            int idx = base + j;
            if (idx < NN) local += g_deg[enc][idx];
        }
        sh[tid] = local;
        __syncthreads();
        for (int off = 1; off < TPB; off <<= 1) {
            int v = (tid >= off) ? sh[tid - off] : 0;
            __syncthreads();
            sh[tid] += v;
            __syncthreads();
        }
        int run = tid ? sh[tid - 1] : 0;
        for (int j = 0; j < chunk; j++) {
            int idx = base + j;
            if (idx < NN) {
                int d = g_deg[enc][idx];
                g_deg[enc][idx]    = 0;               // restore invariant
                g_rowptr[enc][idx] = run;
                g_cursor[enc][idx] = run;
                g_dinv[enc][idx]   = rsqrtf((float)d + 1.0f);
                run += d;
            }
        }
        if (tid == TPB - 1) g_rowptr[enc][NN] = sh[TPB - 1];

        // per-graph inverse counts via binary search (batch is sorted)
        if (tid < GG) {
            const int* batch = enc ? batch_b : batch_a;
            int g = tid;
            int lo = 0, hi = NN;
            while (lo < hi) { int m = (lo + hi) >> 1; if (batch[m] < g) lo = m + 1; else hi = m; }
            int start = lo;
            lo = start; hi = NN;
            while (lo < hi) { int m = (lo + hi) >> 1; if (batch[m] < g + 1) lo = m + 1; else hi = m; }
            g_invcnt[enc][g] = 1.0f / fmaxf((float)(lo - start), 1.0f);
        }
    } else {
        const float* Ws[3] = {W1, W2, W3};
        const int total = 3 * DH * DH;
        for (int idx = (bid - 2) * TPB + tid; idx < total; idx += (NB - 2) * TPB) {
            int l = idx >> 18;
            int rem = idx & (DH * DH - 1);
            int k = rem >> 9;
            int n = rem & 511;
            g_whi[l * DH * DH + n * DH + k] = __float2bfloat16(Ws[l][k * DH + n]);
        }
    }
    gsync(++target);

    // ---- Phase A3: x round pre-scaled by dinv -> g_a; fill CSR (src only) ----
    {
        const int total4 = NN * DH / 4;
        for (int idx = bid * TPB + tid; idx < 2 * total4; idx += NB * TPB) {
            int j   = idx >> 7;            // fused node (DH/4 = 128)
            int enc = (j >= NN);
            int i   = j - enc * NN;
            const float* xs = enc ? x_b : x_a;
            float4 v = *(const float4*)(xs + (size_t)(idx - enc * total4) * 4);
            float dv = g_dinv[enc][i];
            __nv_bfloat162 h01, h23;
            h01.x = __float2bfloat16(v.x * dv); h01.y = __float2bfloat16(v.y * dv);
            h23.x = __float2bfloat16(v.z * dv); h23.y = __float2bfloat16(v.w * dv);
            __nv_bfloat162* hp = (__nv_bfloat162*)(g_a + (size_t)idx * 4);
            hp[0] = h01; hp[1] = h23;
        }
    }
    for (int e = bid * TPB + tid; e < 2 * EE; e += NB * TPB) {
        int enc = (e >= EE);
        int el  = e - enc * EE;
        const int* srcv = enc ? ei_b : ei_a;
        const int* dstv = srcv + EE;
        int s = srcv[el], d = dstv[el];
        int pos = atomicAdd(&g_cursor[enc][d], 1);
        g_csr_src[enc][pos] = s;
    }
    gsync(++target);

    // ---- layer 1: A is pre-scaled, epilogue unscaled ----
    gemm_phase(smb, g_whi + 0 * DH * DH, bid, NB, 0);
    gsync(++target);
    agg_phase(b1, 0, batch_a, batch_b);
    gsync(++target);

    // ---- layer 2 ----
    gemm_phase(smb, g_whi + 1 * DH * DH, bid, NB, 1);
    gsync(++target);
    agg_phase(b2, 1, batch_a, batch_b);
    gsync(++target);

    // ---- layer 3 (agg fuses mean-pool via atomics) ----
    gemm_phase(smb, g_whi + 2 * DH * DH, bid, NB, 1);
    gsync(++target);
    agg_phase(b3, 2, batch_a, batch_b);
    gsync(++target);

    // ---- pairwise distance ----
    dist_phase(out, (float*)(sm + SM_RED));
}

// ---------------------------------------------------------------------------
// launch: ONE kernel (dynamic smem ~109KB, 2 CTAs/SM)
// ---------------------------------------------------------------------------
extern "C" void kernel_launch(void* const* d_in, const int* in_sizes, int n_in,
                              void* d_out, int out_size) {
    const float* x_a     = (const float*)d_in[0];
    const int*   ei_a    = (const int*)  d_in[1];
    const int*   batch_a = (const int*)  d_in[2];
    const float* x_b     = (const float*)d_in[3];
    const int*   ei_b    = (const int*)  d_in[4];
    const int*   batch_b = (const int*)  d_in[5];
    const float* W1 = (const float*)d_in[6];
    const float* b1 = (const float*)d_in[7];
    const float* W2 = (const float*)d_in[8];
    const float* b2 = (const float*)d_in[9];
    const float* W3 = (const float*)d_in[10];
    const float* b3 = (const float*)d_in[11];
    float* out = (float*)d_out;

    cudaFuncSetAttribute(mega_kernel, cudaFuncAttributeMaxDynamicSharedMemorySize,
                         SMEM_BYTES);
    mega_kernel<<<NB, TPB, SMEM_BYTES>>>(x_a, ei_a, batch_a, x_b, ei_b, batch_b,
                                         W1, b1, W2, b2, W3, b3, out);
}

// round 17
// speedup vs baseline: 2.4779x; 1.0436x over previous
#include <cuda_runtime.h>
#include <cuda_bf16.h>
#include <cstdint>

// ---------------------------------------------------------------------------
// SiameseBrainNet: persistent mega-kernel + mma.sync bf16 GEMM
// R17: (a) agg uses contiguous per-block node ranges; fused pool accumulates
//          in registers, flushing atomics only on graph change (20.5M -> 0.6M)
//      (b) CSR fill moved into the GEMM-1 phase (overlaps tensor work).
//      Arithmetic identical to R16 (rel_err ~3.3e-4).
// ---------------------------------------------------------------------------

#define NN 20000
#define N2 (2 * NN)           // fused node count
#define EE 640000
#define DH 512
#define GG 64
#define NB 296                // 2 CTAs per SM
#define TPB 256
#define MT 313                // ceil(40000/128)
#define NTILE (4 * MT)        // 1252 output tiles (128x128)
#define CHUNK ((N2 + NB - 1) / NB)   // 136 nodes per block (contiguous)

#define KSTR 72               // bf16 elements per smem row (64 data + 8 pad)
#define TILE_BYTES (128 * KSTR * 2)          // 18432
#define BUF_BYTES  (2 * TILE_BYTES)          // 36864 (A, B)
#define SM_RED     (3 * BUF_BYTES)           // 110592 (3-stage)
#define SMEM_BYTES (SM_RED + 1024)           // 111616 (x2 = 223232 <= 227KB)

// ---- scratch ---------------------------------------------------------------
__device__ __nv_bfloat16 g_h[N2 * DH];          // h' = dinv*h (bf16, L2-resident)
__device__ __nv_bfloat16 g_a[N2 * DH];          // GEMM A operand (bf16)
__device__ __nv_bfloat16 g_whi[3 * DH * DH];    // W^T bf16, [l][n][k]
__device__ int   g_deg[2][NN];     // INVARIANT: zero at kernel entry
__device__ int   g_rowptr[2][NN + 1];
__device__ int   g_cursor[2][NN];
__device__ float g_dinv[2][NN];
__device__ int   g_csr_src[2][EE];
__device__ float g_invcnt[2][GG];
__device__ float g_pooled[2][GG * DH];          // zeroed in phase A1 each call
__device__ unsigned g_count, g_gen;

// ---- grid barrier -----------------------------------------------------------
__device__ __forceinline__ void gsync(unsigned target) {
    __syncthreads();
    if (threadIdx.x == 0) {
        __threadfence();
        if (atomicAdd(&g_count, 1u) == NB - 1u) {
            atomicExch(&g_count, 0u);
            __threadfence();
            atomicAdd(&g_gen, 1u);
        } else {
            while (*((volatile unsigned*)&g_gen) < target) __nanosleep(64);
        }
        __threadfence();
    }
    __syncthreads();
}

// ---- tensor-core primitives ---------------------------------------------------
__device__ __forceinline__ void mma16816(float* d,
                                         uint32_t a0, uint32_t a1, uint32_t a2, uint32_t a3,
                                         uint32_t b0, uint32_t b1) {
    asm volatile(
        "mma.sync.aligned.m16n8k16.row.col.f32.bf16.bf16.f32 "
        "{%0,%1,%2,%3}, {%4,%5,%6,%7}, {%8,%9}, {%0,%1,%2,%3};"
        : "+f"(d[0]), "+f"(d[1]), "+f"(d[2]), "+f"(d[3])
        : "r"(a0), "r"(a1), "r"(a2), "r"(a3), "r"(b0), "r"(b1));
}
__device__ __forceinline__ void ldsm4(uint32_t& r0, uint32_t& r1, uint32_t& r2, uint32_t& r3,
                                      uint32_t addr) {
    asm volatile("ldmatrix.sync.aligned.m8n8.x4.shared.b16 {%0,%1,%2,%3}, [%4];"
                 : "=r"(r0), "=r"(r1), "=r"(r2), "=r"(r3) : "r"(addr));
}
#define CP_COMMIT() asm volatile("cp.async.commit_group;" ::: "memory")
#define CP_WAIT(n)  asm volatile("cp.async.wait_group %0;" :: "n"(n) : "memory")

__device__ __forceinline__ float dinv_fused(int j) {
    int enc = j >= NN;
    return g_dinv[enc][j - enc * NN];
}

// async fill: gmem bf16 [.,512] -> smem tile 128x64 (stride KSTR)
__device__ __forceinline__ void fill_tile_async(uint32_t smt,
                                                const __nv_bfloat16* __restrict__ g,
                                                int row0, int kc, int nrows) {
    const int tid = threadIdx.x;
#pragma unroll
    for (int i = 0; i < 4; i++) {
        int idx = i * 256 + tid;       // 0..1023
        int r   = idx >> 3;            // 0..127
        int c8  = (idx & 7) << 3;      // 0..56
        int gr  = row0 + r;
        bool valid = (gr < nrows);
        const void* src = g + (size_t)(valid ? gr : 0) * DH + kc + c8;
        uint32_t dst = smt + (uint32_t)(r * KSTR + c8) * 2;
        int sz = valid ? 16 : 0;
        asm volatile("cp.async.cg.shared.global [%0], [%1], 16, %2;"
                     :: "r"(dst), "l"(src), "r"(sz) : "memory");
    }
}

// fill both tiles for one k-chunk into the given stage buffer, commit once
__device__ __forceinline__ void fill_chunk(uint32_t buf, int bm, int bn, int kc8,
                                           const __nv_bfloat16* __restrict__ Whi) {
    fill_tile_async(buf + 0 * TILE_BYTES, g_a,  bm * 128, kc8 * 64, N2);
    fill_tile_async(buf + 1 * TILE_BYTES, Whi,  bn * 128, kc8 * 64, 1 << 30);
    CP_COMMIT();
}

// ---- GEMM phase: g_h[N2,512] = bf16( (A @ W) * (scale_out ? dinv : 1) ) -----
__device__ void gemm_phase(uint32_t smb, const __nv_bfloat16* __restrict__ Whi,
                           int scale_out) {
    const int tid  = threadIdx.x;
    const int lane = tid & 31, warp = tid >> 5;
    const int wm = warp & 3;        // 32-row group
    const int wn = warp >> 2;       // 64-col group
    const int g  = lane >> 2;       // epilogue row-in-8
    const int tg = lane & 3;        // epilogue col pair
    const int seg = lane >> 3;      // ldmatrix segment 0..3
    const int lr  = lane & 7;

    const int aoff0 = (wm * 32 + 0  + (seg & 1) * 8 + lr) * KSTR + (seg >> 1) * 8;
    const int aoff1 = (wm * 32 + 16 + (seg & 1) * 8 + lr) * KSTR + (seg >> 1) * 8;
    const int boffb = (wn * 64 + (seg & 1) * 8 + lr) * KSTR + (seg >> 1) * 8;

    for (int t = blockIdx.x; t < NTILE; t += NB) {
        const int bm = t >> 2, bn = t & 3;

        float acc[2][8][4];
#pragma unroll
        for (int mt = 0; mt < 2; mt++)
#pragma unroll
            for (int nt = 0; nt < 8; nt++)
#pragma unroll
                for (int q = 0; q < 4; q++) acc[mt][nt][q] = 0.0f;

        // prologue: fill chunks 0,1 into stages 0,1
        fill_chunk(smb + 0 * BUF_BYTES, bm, bn, 0, Whi);
        fill_chunk(smb + 1 * BUF_BYTES, bm, bn, 1, Whi);

#pragma unroll 1
        for (int kc8 = 0; kc8 < 8; kc8++) {
            if (kc8 < 7) { CP_WAIT(1); } else { CP_WAIT(0); }
            __syncthreads();                 // chunk kc8 ready; all threads done with kc8-1
            if (kc8 + 2 < 8)
                fill_chunk(smb + (uint32_t)((kc8 + 2) % 3) * BUF_BYTES, bm, bn, kc8 + 2, Whi);

            const uint32_t cur = smb + (uint32_t)(kc8 % 3) * BUF_BYTES;
            const uint32_t Abuf = cur + 0 * TILE_BYTES;
            const uint32_t Bbuf = cur + 1 * TILE_BYTES;

#pragma unroll
            for (int ks4 = 0; ks4 < 4; ks4++) {
                const uint32_t kb = (uint32_t)(ks4 * 16) * 2;   // bytes

                uint32_t bh[8][2];
#pragma unroll
                for (int nq = 0; nq < 4; nq++) {
                    uint32_t r0, r1, r2, r3;
                    ldsm4(r0, r1, r2, r3, Bbuf + (uint32_t)(boffb + nq * 16 * KSTR) * 2 + kb);
                    bh[nq * 2][0] = r0; bh[nq * 2 + 1][0] = r1;
                    bh[nq * 2][1] = r2; bh[nq * 2 + 1][1] = r3;
                }
#pragma unroll
                for (int mt = 0; mt < 2; mt++) {
                    const int aoff = mt ? aoff1 : aoff0;
                    uint32_t ah0, ah1, ah2, ah3;
                    ldsm4(ah0, ah1, ah2, ah3, Abuf + (uint32_t)aoff * 2 + kb);
#pragma unroll
                    for (int nt = 0; nt < 8; nt++)
                        mma16816(acc[mt][nt], ah0, ah1, ah2, ah3, bh[nt][0], bh[nt][1]);
                }
            }
        }

        // epilogue: bf16 h' (optionally scaled by dinv).
#pragma unroll
        for (int mt = 0; mt < 2; mt++) {
            int row0 = bm * 128 + wm * 32 + mt * 16 + g;
            float dva = 1.0f, dvb = 1.0f;
            if (scale_out) {
                if (row0 < N2)     dva = dinv_fused(row0);
                if (row0 + 8 < N2) dvb = dinv_fused(row0 + 8);
            }
#pragma unroll
            for (int nt = 0; nt < 8; nt++) {
                int col = bn * 128 + wn * 64 + nt * 8 + 2 * tg;
                if (row0 < N2) {
                    __nv_bfloat162 p;
                    p.x = __float2bfloat16(acc[mt][nt][0] * dva);
                    p.y = __float2bfloat16(acc[mt][nt][1] * dva);
                    *(__nv_bfloat162*)&g_h[(size_t)row0 * DH + col] = p;
                }
                if (row0 + 8 < N2) {
                    __nv_bfloat162 p;
                    p.x = __float2bfloat16(acc[mt][nt][2] * dvb);
                    p.y = __float2bfloat16(acc[mt][nt][3] * dvb);
                    *(__nv_bfloat162*)&g_h[(size_t)(row0 + 8) * DH + col] = p;
                }
            }
        }
        __syncthreads();   // stages 0,1 consumed; next tile's prologue refills them
    }
}

// ---- aggregation: contiguous node ranges; register-accumulated pooling ------
#define LDIDX8(P, csr, base)                                                  \
    P##0 = csr[(base)];     P##1 = csr[(base) + 1];                           \
    P##2 = csr[(base) + 2]; P##3 = csr[(base) + 3];                           \
    P##4 = csr[(base) + 4]; P##5 = csr[(base) + 5];                           \
    P##6 = csr[(base) + 6]; P##7 = csr[(base) + 7];

__device__ __forceinline__ float4 ld_bf4(const __nv_bfloat16* __restrict__ hb,
                                         size_t off) {
    const uint2 u = *(const uint2*)(hb + off);
    float2 f0 = __bfloat1622float2(*(const __nv_bfloat162*)&u.x);
    float2 f1 = __bfloat1622float2(*(const __nv_bfloat162*)&u.y);
    return make_float4(f0.x, f0.y, f1.x, f1.y);
}

#define GATHER8(P)                                                            \
    {                                                                         \
        float4 v0 = ld_bf4(hb, (size_t)P##0 * DH + t4);                       \
        float4 v1 = ld_bf4(hb, (size_t)P##1 * DH + t4);                       \
        float4 v2 = ld_bf4(hb, (size_t)P##2 * DH + t4);                       \
        float4 v3 = ld_bf4(hb, (size_t)P##3 * DH + t4);                       \
        float4 v4 = ld_bf4(hb, (size_t)P##4 * DH + t4);                       \
        float4 v5 = ld_bf4(hb, (size_t)P##5 * DH + t4);                       \
        float4 v6 = ld_bf4(hb, (size_t)P##6 * DH + t4);                       \
        float4 v7 = ld_bf4(hb, (size_t)P##7 * DH + t4);                       \
        a0.x += v0.x; a0.y += v0.y; a0.z += v0.z; a0.w += v0.w;               \
        a1.x += v1.x; a1.y += v1.y; a1.z += v1.z; a1.w += v1.w;               \
        a2.x += v2.x; a2.y += v2.y; a2.z += v2.z; a2.w += v2.w;               \
        a3.x += v3.x; a3.y += v3.y; a3.z += v3.z; a3.w += v3.w;               \
        a0.x += v4.x; a0.y += v4.y; a0.z += v4.z; a0.w += v4.w;               \
        a1.x += v5.x; a1.y += v5.y; a1.z += v5.z; a1.w += v5.w;               \
        a2.x += v6.x; a2.y += v6.y; a2.z += v6.z; a2.w += v6.w;               \
        a3.x += v7.x; a3.y += v7.y; a3.z += v7.z; a3.w += v7.w;               \
    }

__device__ void agg_phase(const float* __restrict__ bias, int l,
                          const int* __restrict__ batch_a,
                          const int* __restrict__ batch_b) {
    const int sub = threadIdx.x >> 7;   // 0 or 1
    const int t   = threadIdx.x & 127;  // float4 lane
    const int t4  = t * 4;
    const float4 b4 = *(const float4*)&bias[t4];

    const int j0 = blockIdx.x * CHUNK;
    const int j1 = min(j0 + CHUNK, N2);

    // register pooled accumulator (layer 2 only)
    float4 pacc = make_float4(0.f, 0.f, 0.f, 0.f);
    int cur_key = -1;   // enc*GG + gid

    for (int j = j0 + sub; j < j1; j += 2) {
        const int enc = (j >= NN);
        const int i   = j - enc * NN;
        const int* __restrict__ csr = g_csr_src[enc];
        const __nv_bfloat16* __restrict__ hb = g_h + (size_t)enc * NN * DH;

        int r0 = g_rowptr[enc][i];
        int r1 = g_rowptr[enc][i + 1];

        float4 a0 = make_float4(0.f, 0.f, 0.f, 0.f);
        float4 a1 = a0, a2 = a0, a3 = a0;

        int e = r0;
        const int last8 = r1 - 8;
        if (e <= last8) {
            int p0, p1, p2, p3, p4, p5, p6, p7;
            LDIDX8(p, csr, e)
            e += 8;
            while (e <= last8) {
                int c0, c1, c2, c3, c4, c5, c6, c7;
                LDIDX8(c, csr, e)              // prefetch next batch's indices
                GATHER8(p)                      // gathers + adds for current batch
                p0 = c0; p1 = c1; p2 = c2; p3 = c3;
                p4 = c4; p5 = c5; p6 = c6; p7 = c7;
                e += 8;
            }
            GATHER8(p)
        }
        for (; e < r1; e++) {
            int s = csr[e];
            float4 v = ld_bf4(hb, (size_t)s * DH + t4);
            a0.x += v.x; a0.y += v.y; a0.z += v.z; a0.w += v.w;
        }

        // self term (h' already carries dinv_i)
        {
            float4 v = ld_bf4(hb, (size_t)i * DH + t4);
            a0.x += v.x; a0.y += v.y; a0.z += v.z; a0.w += v.w;
        }

        float dv = g_dinv[enc][i];
        float4 acc;
        acc.x = dv * ((a0.x + a1.x) + (a2.x + a3.x)) + b4.x;
        acc.y = dv * ((a0.y + a1.y) + (a2.y + a3.y)) + b4.y;
        acc.z = dv * ((a0.z + a1.z) + (a2.z + a3.z)) + b4.z;
        acc.w = dv * ((a0.w + a1.w) + (a2.w + a3.w)) + b4.w;

        if (l < 2) {   // relu + round to bf16 for next GEMM (unscaled)
            acc.x = fmaxf(acc.x, 0.f); acc.y = fmaxf(acc.y, 0.f);
            acc.z = fmaxf(acc.z, 0.f); acc.w = fmaxf(acc.w, 0.f);
            __nv_bfloat162 h01, h23;
            h01.x = __float2bfloat16(acc.x); h01.y = __float2bfloat16(acc.y);
            h23.x = __float2bfloat16(acc.z); h23.y = __float2bfloat16(acc.w);
            __nv_bfloat162* hp = (__nv_bfloat162*)(g_a + (size_t)j * DH + t4);
            hp[0] = h01; hp[1] = h23;
        } else {       // pooled accumulation in registers; flush on graph change
            const int* batch = enc ? batch_b : batch_a;
            int gid = batch[i];
            int key = enc * GG + gid;
            if (key != cur_key) {
                if (cur_key >= 0) {
                    float* pp = &((float*)g_pooled)[cur_key * DH + t4];
                    atomicAdd(pp + 0, pacc.x);
                    atomicAdd(pp + 1, pacc.y);
                    atomicAdd(pp + 2, pacc.z);
                    atomicAdd(pp + 3, pacc.w);
                }
                cur_key = key;
                pacc = make_float4(0.f, 0.f, 0.f, 0.f);
            }
            float w = g_invcnt[enc][gid];
            pacc.x += acc.x * w;
            pacc.y += acc.y * w;
            pacc.z += acc.z * w;
            pacc.w += acc.w * w;
        }
    }
    // final flush
    if (l == 2 && cur_key >= 0) {
        float* pp = &((float*)g_pooled)[cur_key * DH + t4];
        atomicAdd(pp + 0, pacc.x);
        atomicAdd(pp + 1, pacc.y);
        atomicAdd(pp + 2, pacc.z);
        atomicAdd(pp + 3, pacc.w);
    }
}

__device__ void dist_phase(float* __restrict__ out, float* sred) {
    int g = blockIdx.x;
    if (g >= GG) return;
    int t = threadIdx.x;

    float2 a = *(const float2*)&g_pooled[0][g * DH + t * 2];
    float2 b = *(const float2*)&g_pooled[1][g * DH + t * 2];
    float dx = a.x - b.x + 1e-6f;
    float dy = a.y - b.y + 1e-6f;
    float s = dx * dx + dy * dy;

    sred[t] = s;
    __syncthreads();
    for (int off = 128; off > 0; off >>= 1) {
        if (t < off) sred[t] += sred[t + off];
        __syncthreads();
    }
    if (t == 0) out[g] = sqrtf(sred[0]);
}

// ---- mega kernel --------------------------------------------------------------
extern __shared__ __align__(16) unsigned char smem_dyn[];

__global__ __launch_bounds__(TPB, 2) void mega_kernel(
    const float* __restrict__ x_a, const int* __restrict__ ei_a,
    const int* __restrict__ batch_a,
    const float* __restrict__ x_b, const int* __restrict__ ei_b,
    const int* __restrict__ batch_b,
    const float* __restrict__ W1, const float* __restrict__ b1,
    const float* __restrict__ W2, const float* __restrict__ b2,
    const float* __restrict__ W3, const float* __restrict__ b3,
    float* __restrict__ out)
{
    unsigned char* sm = smem_dyn;
    const uint32_t smb = (uint32_t)__cvta_generic_to_shared(sm);
    const int tid = threadIdx.x, bid = blockIdx.x;
    unsigned target = *((volatile unsigned*)&g_gen);

    // ---- Phase A1: deg counts (both enc) + zero pooled ----
    for (int idx = bid * TPB + tid; idx < 2 * GG * DH; idx += NB * TPB)
        ((float*)g_pooled)[idx] = 0.0f;
    for (int e = bid * TPB + tid; e < 2 * EE; e += NB * TPB) {
        int enc = (e >= EE);
        int el  = e - enc * EE;
        const int* dstv = (enc ? ei_b : ei_a) + EE;
        atomicAdd(&g_deg[enc][dstv[el]], 1);
    }
    gsync(++target);

    // ---- Phase A2: blocks 0,1 scan + invcnt; others W transpose+round ----
    if (bid < 2) {
        const int enc = bid;
        int* sh = (int*)(sm + SM_RED);
        const int chunk = (NN + TPB - 1) / TPB;   // 79
        int base = tid * chunk;
        int local = 0;
        for (int j = 0; j < chunk; j++) {
            int idx = base + j;
            if (idx < NN) local += g_deg[enc][idx];
        }
        sh[tid] = local;
        __syncthreads();
        for (int off = 1; off < TPB; off <<= 1) {
            int v = (tid >= off) ? sh[tid - off] : 0;
            __syncthreads();
            sh[tid] += v;
            __syncthreads();
        }
        int run = tid ? sh[tid - 1] : 0;
        for (int j = 0; j < chunk; j++) {
            int idx = base + j;
            if (idx < NN) {
                int d = g_deg[enc][idx];
                g_deg[enc][idx]    = 0;               // restore invariant
                g_rowptr[enc][idx] = run;
                g_cursor[enc][idx] = run;
                g_dinv[enc][idx]   = rsqrtf((float)d + 1.0f);
                run += d;
            }
        }
        if (tid == TPB - 1) g_rowptr[enc][NN] = sh[TPB - 1];

        // per-graph inverse counts via binary search (batch is sorted)
        if (tid < GG) {
            const int* batch = enc ? batch_b : batch_a;
            int g = tid;
            int lo = 0, hi = NN;
            while (lo < hi) { int m = (lo + hi) >> 1; if (batch[m] < g) lo = m + 1; else hi = m; }
            int start = lo;
            lo = start; hi = NN;
            while (lo < hi) { int m = (lo + hi) >> 1; if (batch[m] < g + 1) lo = m + 1; else hi = m; }
            g_invcnt[enc][g] = 1.0f / fmaxf((float)(lo - start), 1.0f);
        }
    } else {
        const float* Ws[3] = {W1, W2, W3};
        const int total = 3 * DH * DH;
        for (int idx = (bid - 2) * TPB + tid; idx < total; idx += (NB - 2) * TPB) {
            int l = idx >> 18;
            int rem = idx & (DH * DH - 1);
            int k = rem >> 9;
            int n = rem & 511;
            g_whi[l * DH * DH + n * DH + k] = __float2bfloat16(Ws[l][k * DH + n]);
        }
    }
    gsync(++target);

    // ---- Phase A3: x round pre-scaled by dinv -> g_a ----
    {
        const int total4 = NN * DH / 4;
        for (int idx = bid * TPB + tid; idx < 2 * total4; idx += NB * TPB) {
            int j   = idx >> 7;            // fused node (DH/4 = 128)
            int enc = (j >= NN);
            int i   = j - enc * NN;
            const float* xs = enc ? x_b : x_a;
            float4 v = *(const float4*)(xs + (size_t)(idx - enc * total4) * 4);
            float dv = g_dinv[enc][i];
            __nv_bfloat162 h01, h23;
            h01.x = __float2bfloat16(v.x * dv); h01.y = __float2bfloat16(v.y * dv);
            h23.x = __float2bfloat16(v.z * dv); h23.y = __float2bfloat16(v.w * dv);
            __nv_bfloat162* hp = (__nv_bfloat162*)(g_a + (size_t)idx * 4);
            hp[0] = h01; hp[1] = h23;
        }
    }
    gsync(++target);

    // ---- layer 1 GEMM + CSR fill fused in one phase (CSR consumed post-barrier)
    gemm_phase(smb, g_whi + 0 * DH * DH, 0);
    for (int e = bid * TPB + tid; e < 2 * EE; e += NB * TPB) {
        int enc = (e >= EE);
        int el  = e - enc * EE;
        const int* srcv = enc ? ei_b : ei_a;
        const int* dstv = srcv + EE;
        int s = srcv[el], d = dstv[el];
        int pos = atomicAdd(&g_cursor[enc][d], 1);
        g_csr_src[enc][pos] = s;
    }
    gsync(++target);
    agg_phase(b1, 0, batch_a, batch_b);
    gsync(++target);

    // ---- layer 2 ----
    gemm_phase(smb, g_whi + 1 * DH * DH, 1);
    gsync(++target);
    agg_phase(b2, 1, batch_a, batch_b);
    gsync(++target);

    // ---- layer 3 (agg fuses mean-pool, register-accumulated) ----
    gemm_phase(smb, g_whi + 2 * DH * DH, 1);
    gsync(++target);
    agg_phase(b3, 2, batch_a, batch_b);
    gsync(++target);

    // ---- pairwise distance ----
    dist_phase(out, (float*)(sm + SM_RED));
}

// ---------------------------------------------------------------------------
// launch: ONE kernel (dynamic smem ~109KB, 2 CTAs/SM)
// ---------------------------------------------------------------------------
extern "C" void kernel_launch(void* const* d_in, const int* in_sizes, int n_in,
                              void* d_out, int out_size) {
    const float* x_a     = (const float*)d_in[0];
    const int*   ei_a    = (const int*)  d_in[1];
    const int*   batch_a = (const int*)  d_in[2];
    const float* x_b     = (const float*)d_in[3];
    const int*   ei_b    = (const int*)  d_in[4];
    const int*   batch_b = (const int*)  d_in[5];
    const float* W1 = (const float*)d_in[6];
    const float* b1 = (const float*)d_in[7];
    const float* W2 = (const float*)d_in[8];
    const float* b2 = (const float*)d_in[9];
    const float* W3 = (const float*)d_in[10];
    const float* b3 = (const float*)d_in[11];
    float* out = (float*)d_out;

    cudaFuncSetAttribute(mega_kernel, cudaFuncAttributeMaxDynamicSharedMemorySize,
                         SMEM_BYTES);
    mega_kernel<<<NB, TPB, SMEM_BYTES>>>(x_a, ei_a, batch_a, x_b, ei_b, batch_b,
                                         W1, b1, W2, b2, W3, b3, out);
}